// round 1
// baseline (speedup 1.0000x reference)
#include <cuda_runtime.h>
#include <cuda_bf16.h>

#define BB 8
#define NN 32768
#define CC 32
#define KK 22

constexpr int P  = 32;   // points per block
constexpr int PPITCH = 33;   // padded pitch (bank-conflict free transposed access)
constexpr int THREADS = 256;

// ---------------- device scratch (no allocations allowed) ----------------
__device__ float g_f2[BB * NN * 128];            // 128 MB activation tensor (h2 per point)
__device__ int   g_cf[2 * BB * CC * 128];        // seg-max of f2 (float bits, >=0)
__device__ int   g_cc[2 * BB * CC * 32];         // seg-max of corr
__device__ float g_cf2[2 * BB * CC * 128];       // cf @ corr_matrix
__device__ int   g_net[BB * 128];                // global max-pool (float bits, >=0)

// transposed weights: layout dst[i*O + w*(O/8) + j] = W[(w+8j)][i]
__device__ float g_wtin[KK * 256];
__device__ float g_wt1 [2][256 * 64];
__device__ float g_wt2 [2][64 * 128];
__device__ float g_wt3 [2][128 * 128];
__device__ float g_wtc1[2][128 * 128];
__device__ float g_wtc2[2][128 * 256];
__device__ float g_wtc3[2][256 * 32];
__device__ float g_wto1[256 * 128];
__device__ float g_wto2[128 * 128];

// ---------------- prep kernels ----------------
__global__ void transpose_k(const float* __restrict__ src, float* __restrict__ dst, int I, int O) {
    int t = blockIdx.x * blockDim.x + threadIdx.x;
    if (t >= I * O) return;
    int o = t / I, i = t % I;
    int w = o & 7, j = o >> 3;
    dst[i * O + w * (O >> 3) + j] = src[o * I + i];
}

__global__ void zero_k() {
    int t = blockIdx.x * blockDim.x + threadIdx.x;
    if (t < 2 * BB * CC * 128) g_cf[t] = 0;
    if (t < 2 * BB * CC * 32)  g_cc[t] = 0;
    if (t < BB * 128)          g_net[t] = 0;
}

// ---------------- fused layer: O x I matvec over 32 points ----------------
// warp w owns outputs o = w + 8j; lane = point. WT layout gives float4 weight loads.
template <int I, int O, bool RELU>
__device__ __forceinline__ void layerT(const float* __restrict__ WT,
                                       const float* __restrict__ bias,
                                       const float* __restrict__ Hin,
                                       float* __restrict__ Hout,
                                       int w, int lane) {
    constexpr int J = O / 8;
    float acc[J];
#pragma unroll
    for (int j = 0; j < J; j++) acc[j] = __ldg(bias + w + 8 * j);
#pragma unroll 2
    for (int i = 0; i < I; i++) {
        float hv = Hin[i * PPITCH + lane];
        const float4* wp = reinterpret_cast<const float4*>(WT + i * O + w * J);
#pragma unroll
        for (int j4 = 0; j4 < J / 4; j4++) {
            float4 wv = __ldg(wp + j4);
            acc[4 * j4 + 0] = fmaf(wv.x, hv, acc[4 * j4 + 0]);
            acc[4 * j4 + 1] = fmaf(wv.y, hv, acc[4 * j4 + 1]);
            acc[4 * j4 + 2] = fmaf(wv.z, hv, acc[4 * j4 + 2]);
            acc[4 * j4 + 3] = fmaf(wv.w, hv, acc[4 * j4 + 3]);
        }
    }
#pragma unroll
    for (int j = 0; j < J; j++) {
        float v = acc[j];
        if (RELU) v = fmaxf(v, 0.0f);
        Hout[(w + 8 * j) * PPITCH + lane] = v;
    }
}

// shared layout (floats): X[256*33] Y[256*33] Z[128*33] cfl[32*128] ccl[32*32] cl0[64] cl1[64]
constexpr int SM_FLOATS = 256 * PPITCH + 256 * PPITCH + 128 * PPITCH + CC * 128 + CC * 32 + 64 + 64;
constexpr int SMEM_BYTES = SM_FLOATS * 4;

// ---------------- kernel A: input -> conv1 -> conv2 -> (store f2) -> corr chain -> segmax ----
__global__ __launch_bounds__(THREADS, 2) void kA(const float* __restrict__ feat,
                                                 const int* __restrict__ clus,
                                                 const float* b_in, const float* b1,
                                                 const float* b2, const float* bc1,
                                                 const float* bc2, const float* bc3) {
    extern __shared__ float sm[];
    float* X = sm;
    float* Y = X + 256 * PPITCH;
    float* Z = Y + 256 * PPITCH;
    int* cfl = (int*)(Z + 128 * PPITCH);
    int* ccl = cfl + CC * 128;
    int* cl  = ccl + CC * 32;
    int t = threadIdx.x, w = t >> 5, lane = t & 31;
    int b = blockIdx.x >> 10, n0 = (blockIdx.x & 1023) * P;

    for (int r = t; r < CC * 128; r += THREADS) cfl[r] = 0;
    for (int r = t; r < CC * 32; r += THREADS)  ccl[r] = 0;
    if (t < P) cl[t] = clus[b * NN + n0 + t];   // iteration 0 clusters
    for (int r = t; r < P * KK; r += THREADS) {
        int p = r / KK, k = r % KK;
        Y[k * PPITCH + p] = feat[(b * NN + n0 + p) * KK + k];
    }
    __syncthreads();
    layerT<KK, 256, true>(g_wtin, b_in, Y, X, w, lane);       // h0
    __syncthreads();
    layerT<256, 64, true>(g_wt1[0], b1, X, Y, w, lane);       // h1
    __syncthreads();
    layerT<64, 128, true>(g_wt2[0], b2, Y, Z, w, lane);       // h2 = f2
    __syncthreads();
    for (int r = t; r < P * 128; r += THREADS) {              // store f2 (coalesced)
        int p = r >> 7, c = r & 127;
        g_f2[(b * NN + n0 + p) * 128 + c] = Z[c * PPITCH + p];
    }
    layerT<128, 128, true>(g_wtc1[0], bc1, Z, Y, w, lane);    // c1
    __syncthreads();
    layerT<128, 256, true>(g_wtc2[0], bc2, Y, X, w, lane);    // c2
    __syncthreads();
    layerT<256, 32, true>(g_wtc3[0], bc3, X, Y, w, lane);     // c3 (rows 0..31)
    __syncthreads();
    // segment-max pre-reduce in shared (values >= 0 so int-max == float-max)
    for (int r = t; r < P * 128; r += THREADS) {
        int p = r >> 7, c = r & 127;
        atomicMax(&cfl[cl[p] * 128 + c], __float_as_int(Z[c * PPITCH + p]));
    }
    for (int r = t; r < P * 32; r += THREADS) {
        int p = r >> 5, c = r & 31;
        atomicMax(&ccl[cl[p] * 32 + c], __float_as_int(Y[c * PPITCH + p]));
    }
    __syncthreads();
    for (int r = t; r < CC * 128; r += THREADS) { int v = cfl[r]; if (v) atomicMax(&g_cf[b * CC * 128 + r], v); }
    for (int r = t; r < CC * 32; r += THREADS)  { int v = ccl[r]; if (v) atomicMax(&g_cc[b * CC * 32 + r], v); }
}

// ---------------- kernel B: per-batch correlation matrix + cf @ corr -------------
__global__ void kB(int it) {
    __shared__ float cm[CC * 32], corr[CC * CC], invn[CC], cfs[CC * 128];
    int b = blockIdx.x, t = threadIdx.x;
    for (int r = t; r < CC * 32; r += THREADS)  cm[r]  = __int_as_float(g_cc[(it * BB + b) * CC * 32 + r]);
    for (int r = t; r < CC * 128; r += THREADS) cfs[r] = __int_as_float(g_cf[(it * BB + b) * CC * 128 + r]);
    __syncthreads();
    if (t < CC) {
        float s = 0.f;
        for (int c = 0; c < 32; c++) { float v = cm[t * 32 + c]; s += v * v; }
        invn[t] = 1.0f / fmaxf(sqrtf(s), 1e-12f);
    }
    __syncthreads();
    for (int r = t; r < CC * 32; r += THREADS) cm[r] *= invn[r >> 5];
    __syncthreads();
    for (int r = t; r < CC * CC; r += THREADS) {
        int c1 = r >> 5, c2 = r & 31;
        float s = 0.f;
        for (int c = 0; c < 32; c++) s += cm[c1 * 32 + c] * cm[c2 * 32 + c];
        corr[r] = s;
    }
    __syncthreads();
    for (int r = t; r < CC * 128; r += THREADS) {
        int c2 = r >> 7, ch = r & 127;
        float s = 0.f;
        for (int c1 = 0; c1 < 32; c1++) s += cfs[c1 * 128 + ch] * corr[c1 * 32 + c2];
        g_cf2[(it * BB + b) * CC * 128 + r] = s;
    }
}

// ---------------- kernel C: conv3 + pool gather + concat -> next iter chain -----
__global__ __launch_bounds__(THREADS, 2) void kC(const int* __restrict__ clus,
                                                 const float* b3, const float* b1,
                                                 const float* b2, const float* bc1,
                                                 const float* bc2, const float* bc3) {
    extern __shared__ float sm[];
    float* X = sm;
    float* Y = X + 256 * PPITCH;
    float* Z = Y + 256 * PPITCH;
    int* cfl = (int*)(Z + 128 * PPITCH);
    int* ccl = cfl + CC * 128;
    int* cl0 = ccl + CC * 32;
    int* cl1 = cl0 + 64;
    int t = threadIdx.x, w = t >> 5, lane = t & 31;
    int b = blockIdx.x >> 10, n0 = (blockIdx.x & 1023) * P;

    for (int r = t; r < CC * 128; r += THREADS) cfl[r] = 0;
    for (int r = t; r < CC * 32; r += THREADS)  ccl[r] = 0;
    if (t < P) {
        cl0[t] = clus[b * NN + n0 + t];
        cl1[t] = clus[(BB + b) * NN + n0 + t];
    }
    for (int r = t; r < P * 128; r += THREADS) {       // load f2 (it0)
        int p = r >> 7, c = r & 127;
        Z[c * PPITCH + p] = g_f2[(b * NN + n0 + p) * 128 + c];
    }
    __syncthreads();
    layerT<128, 128, true>(g_wt3[0], b3, Z, X, w, lane);   // h3 -> X rows 0..127
    for (int r = t; r < P * 128; r += THREADS) {           // pool gather -> X rows 128..255
        int p = r >> 7, c = r & 127;
        X[(128 + c) * PPITCH + p] = g_cf2[(b * CC + cl0[p]) * 128 + c];
    }
    __syncthreads();
    layerT<256, 64, true>(g_wt1[1], b1, X, Y, w, lane);
    __syncthreads();
    layerT<64, 128, true>(g_wt2[1], b2, Y, Z, w, lane);    // h2' (it1)
    __syncthreads();
    for (int r = t; r < P * 128; r += THREADS) {
        int p = r >> 7, c = r & 127;
        g_f2[(b * NN + n0 + p) * 128 + c] = Z[c * PPITCH + p];
    }
    layerT<128, 128, true>(g_wtc1[1], bc1, Z, Y, w, lane);
    __syncthreads();
    layerT<128, 256, true>(g_wtc2[1], bc2, Y, X, w, lane);
    __syncthreads();
    layerT<256, 32, true>(g_wtc3[1], bc3, X, Y, w, lane);
    __syncthreads();
    for (int r = t; r < P * 128; r += THREADS) {
        int p = r >> 7, c = r & 127;
        atomicMax(&cfl[cl1[p] * 128 + c], __float_as_int(Z[c * PPITCH + p]));
    }
    for (int r = t; r < P * 32; r += THREADS) {
        int p = r >> 5, c = r & 31;
        atomicMax(&ccl[cl1[p] * 32 + c], __float_as_int(Y[c * PPITCH + p]));
    }
    __syncthreads();
    for (int r = t; r < CC * 128; r += THREADS) { int v = cfl[r]; if (v) atomicMax(&g_cf[(BB + b) * CC * 128 + r], v); }
    for (int r = t; r < CC * 32; r += THREADS)  { int v = ccl[r]; if (v) atomicMax(&g_cc[(BB + b) * CC * 32 + r], v); }
}

// ---------------- kernel D: conv3 + pool + out convs + global max ---------------
__global__ __launch_bounds__(THREADS, 2) void kD(const int* __restrict__ clus,
                                                 const float* b3, const float* bo1,
                                                 const float* bo2) {
    extern __shared__ float sm[];
    float* X = sm;
    float* Y = X + 256 * PPITCH;
    float* Z = Y + 256 * PPITCH;
    int* cl1 = (int*)(Z + 128 * PPITCH);
    int t = threadIdx.x, w = t >> 5, lane = t & 31;
    int b = blockIdx.x >> 10, n0 = (blockIdx.x & 1023) * P;

    if (t < P) cl1[t] = clus[(BB + b) * NN + n0 + t];
    for (int r = t; r < P * 128; r += THREADS) {
        int p = r >> 7, c = r & 127;
        Z[c * PPITCH + p] = g_f2[(b * NN + n0 + p) * 128 + c];
    }
    __syncthreads();
    layerT<128, 128, true>(g_wt3[1], b3, Z, X, w, lane);   // rows 0..127
    for (int r = t; r < P * 128; r += THREADS) {           // pool gather rows 128..255
        int p = r >> 7, c = r & 127;
        X[(128 + c) * PPITCH + p] = g_cf2[((BB + b) * CC + cl1[p]) * 128 + c];
    }
    __syncthreads();
    layerT<256, 128, true>(g_wto1, bo1, X, Y, w, lane);
    __syncthreads();
    layerT<128, 128, true>(g_wto2, bo2, Y, Z, w, lane);
    __syncthreads();
    if (t < 128) {
        float m = 0.0f;
        for (int p = 0; p < P; p++) m = fmaxf(m, Z[t * PPITCH + p]);
        atomicMax(&g_net[b * 128 + t], __float_as_int(m));
    }
}

// ---------------- kernel E: dense head ----------------
__global__ void kE(const float* __restrict__ dw1, const float* __restrict__ db1,
                   const float* __restrict__ dw2, const float* __restrict__ db2,
                   const float* __restrict__ dw3, const float* __restrict__ db3,
                   float* __restrict__ out) {
    __shared__ float net[BB * 128], l1[BB * 256], l2[BB * 256];
    int t = threadIdx.x;
    for (int r = t; r < BB * 128; r += THREADS) net[r] = __int_as_float(g_net[r]);
    __syncthreads();
    for (int r = t; r < BB * 256; r += THREADS) {
        int b = r >> 8, o = r & 255;
        float s = db1[o];
        for (int i = 0; i < 128; i++) s = fmaf(net[b * 128 + i], dw1[i * 256 + o], s);
        l1[r] = s >= 0.f ? s : 0.2f * s;
    }
    __syncthreads();
    for (int r = t; r < BB * 256; r += THREADS) {
        int b = r >> 8, o = r & 255;
        float s = db2[o];
        for (int i = 0; i < 256; i++) s = fmaf(l1[b * 256 + i], dw2[i * 256 + o], s);
        l2[r] = s >= 0.f ? s : 0.2f * s;
    }
    __syncthreads();
    for (int r = t; r < BB * 40; r += THREADS) {
        int b = r / 40, o = r % 40;
        float s = db3[o];
        for (int i = 0; i < 256; i++) s = fmaf(l2[b * 256 + i], dw3[i * 40 + o], s);
        out[r] = s;
    }
}

// ---------------- host launcher ----------------
extern "C" void kernel_launch(void* const* d_in, const int* in_sizes, int n_in,
                              void* d_out, int out_size) {
    const float* feat = (const float*)d_in[0];
    const int*   clus = (const int*)d_in[1];
    const float* w_in = (const float*)d_in[2];
    const float* b_in = (const float*)d_in[3];
    const float* w1   = (const float*)d_in[4];
    const float* b1   = (const float*)d_in[5];
    const float* w2   = (const float*)d_in[6];
    const float* b2   = (const float*)d_in[7];
    const float* w3   = (const float*)d_in[8];
    const float* b3   = (const float*)d_in[9];
    const float* wc1  = (const float*)d_in[10];
    const float* bc1  = (const float*)d_in[11];
    const float* wc2  = (const float*)d_in[12];
    const float* bc2  = (const float*)d_in[13];
    const float* wc3  = (const float*)d_in[14];
    const float* bc3  = (const float*)d_in[15];
    const float* wo1  = (const float*)d_in[16];
    const float* bo1  = (const float*)d_in[17];
    const float* wo2  = (const float*)d_in[18];
    const float* bo2  = (const float*)d_in[19];
    const float* dw1  = (const float*)d_in[20];
    const float* db1  = (const float*)d_in[21];
    const float* dw2  = (const float*)d_in[22];
    const float* db2  = (const float*)d_in[23];
    const float* dw3  = (const float*)d_in[24];
    const float* db3  = (const float*)d_in[25];

    cudaFuncSetAttribute(kA, cudaFuncAttributeMaxDynamicSharedMemorySize, SMEM_BYTES);
    cudaFuncSetAttribute(kC, cudaFuncAttributeMaxDynamicSharedMemorySize, SMEM_BYTES);
    cudaFuncSetAttribute(kD, cudaFuncAttributeMaxDynamicSharedMemorySize, SMEM_BYTES);

    float *p_wtin, *p_wt1, *p_wt2, *p_wt3, *p_wtc1, *p_wtc2, *p_wtc3, *p_wto1, *p_wto2;
    cudaGetSymbolAddress((void**)&p_wtin, g_wtin);
    cudaGetSymbolAddress((void**)&p_wt1,  g_wt1);
    cudaGetSymbolAddress((void**)&p_wt2,  g_wt2);
    cudaGetSymbolAddress((void**)&p_wt3,  g_wt3);
    cudaGetSymbolAddress((void**)&p_wtc1, g_wtc1);
    cudaGetSymbolAddress((void**)&p_wtc2, g_wtc2);
    cudaGetSymbolAddress((void**)&p_wtc3, g_wtc3);
    cudaGetSymbolAddress((void**)&p_wto1, g_wto1);
    cudaGetSymbolAddress((void**)&p_wto2, g_wto2);

    auto tp = [](const float* s, float* d, int I, int O) {
        int n = I * O;
        transpose_k<<<(n + 255) / 256, 256>>>(s, d, I, O);
    };
    tp(w_in, p_wtin, KK, 256);
    for (int it = 0; it < 2; it++) {
        tp(w1  + it * 64 * 256,  p_wt1  + it * 256 * 64,  256, 64);
        tp(w2  + it * 128 * 64,  p_wt2  + it * 64 * 128,  64, 128);
        tp(w3  + it * 128 * 128, p_wt3  + it * 128 * 128, 128, 128);
        tp(wc1 + it * 128 * 128, p_wtc1 + it * 128 * 128, 128, 128);
        tp(wc2 + it * 256 * 128, p_wtc2 + it * 128 * 256, 128, 256);
        tp(wc3 + it * 32 * 256,  p_wtc3 + it * 256 * 32,  256, 32);
    }
    tp(wo1, p_wto1, 256, 128);
    tp(wo2, p_wto2, 128, 128);

    zero_k<<<256, 256>>>();

    int grid = BB * (NN / P);   // 8192
    kA<<<grid, THREADS, SMEM_BYTES>>>(feat, clus, b_in, b1, b2, bc1, bc2, bc3);
    kB<<<BB, THREADS>>>(0);
    kC<<<grid, THREADS, SMEM_BYTES>>>(clus, b3, b1 + 64, b2 + 128, bc1 + 128, bc2 + 256, bc3 + 32);
    kB<<<BB, THREADS>>>(1);
    kD<<<grid, THREADS, SMEM_BYTES>>>(clus, b3 + 128, bo1, bo2);
    kE<<<1, THREADS>>>(dw1, db1, dw2, db2, dw3, db3, (float*)d_out);
}

// round 2
// speedup vs baseline: 1.1679x; 1.1679x over previous
#include <cuda_runtime.h>
#include <cuda_bf16.h>

#define BB 8
#define NN 32768
#define CC 32
#define KK 22

constexpr int P  = 64;        // points per block (2 per thread-lane, pair-interleaved)
constexpr int PP = 66;        // padded row pitch in floats (64 + 2)
constexpr int THREADS = 256;

// ---------------- device scratch ----------------
__device__ float g_f2[BB * NN * 128];
__device__ int   g_cf[2 * BB * CC * 128];
__device__ int   g_cc[2 * BB * CC * 32];
__device__ float g_cf2[2 * BB * CC * 128];
__device__ int   g_net[BB * 128];

// transposed weights: dst[i*O + w*(O/8) + j] = W[(w+8j)][i]
__device__ float g_wtin[KK * 256];
__device__ float g_wt1 [2][256 * 64];
__device__ float g_wt2 [2][64 * 128];
__device__ float g_wt3 [2][128 * 128];
__device__ float g_wtc1[2][128 * 128];
__device__ float g_wtc2[2][128 * 256];
__device__ float g_wtc3[2][256 * 32];
__device__ float g_wto1[256 * 128];
__device__ float g_wto2[128 * 128];

// ---------------- prep: all weight transposes in ONE launch ----------------
struct TPJobs {
    const float* src[15];
    float*       dst[15];
    int          I[15];
    int          O[15];
    int          n[15];
};

__global__ void tp_all(TPJobs jobs, int total) {
    int t = blockIdx.x * blockDim.x + threadIdx.x;
    if (t >= total) return;
    int j = 0;
    int e = t;
    while (e >= jobs.n[j]) { e -= jobs.n[j]; j++; }
    int I = jobs.I[j], O = jobs.O[j];
    int o = e / I, i = e % I;
    int w = o & 7, jj = o >> 3;
    jobs.dst[j][i * O + w * (O >> 3) + jj] = jobs.src[j][o * I + i];
}

__global__ void zero1_k() {
    int t = blockIdx.x * blockDim.x + threadIdx.x;
    if (t < 2 * BB * CC * 128) g_cf[t] = 0;
    if (t < 2 * BB * CC * 32)  g_cc[t] = 0;
}
__global__ void zero2_k() {
    int t = blockIdx.x * blockDim.x + threadIdx.x;
    if (t < BB * 128) g_net[t] = 0;
}

// ---------------- fused layer: O x I matvec over 64 points (2/thread) -------
// warp w owns outputs o = w + 8*j ; lane owns point pair (lane, lane+32)
// activations pair-interleaved: point p lives at column (p&31)*2 + (p>>5)
template <int I, int O, bool RELU>
__device__ __forceinline__ void layerT2(const float* __restrict__ WT,
                                        const float* __restrict__ bias,
                                        const float* __restrict__ Hin,
                                        float* __restrict__ Hout,
                                        int w, int lane) {
    constexpr int J = O / 8;
    float a0[J], a1[J];
#pragma unroll
    for (int j = 0; j < J; j++) {
        float bv = __ldg(bias + w + 8 * j);
        a0[j] = bv; a1[j] = bv;
    }
    const float* hp = Hin + lane * 2;
    const float4* wrow = reinterpret_cast<const float4*>(WT + w * J);
#pragma unroll 2
    for (int i = 0; i < I; i++) {
        float2 hv = *reinterpret_cast<const float2*>(hp + i * PP);
        const float4* wr = reinterpret_cast<const float4*>(
            reinterpret_cast<const float*>(wrow) + i * O);
#pragma unroll
        for (int j4 = 0; j4 < J / 4; j4++) {
            float4 wv = __ldg(wr + j4);
            a0[4 * j4 + 0] = fmaf(wv.x, hv.x, a0[4 * j4 + 0]);
            a1[4 * j4 + 0] = fmaf(wv.x, hv.y, a1[4 * j4 + 0]);
            a0[4 * j4 + 1] = fmaf(wv.y, hv.x, a0[4 * j4 + 1]);
            a1[4 * j4 + 1] = fmaf(wv.y, hv.y, a1[4 * j4 + 1]);
            a0[4 * j4 + 2] = fmaf(wv.z, hv.x, a0[4 * j4 + 2]);
            a1[4 * j4 + 2] = fmaf(wv.z, hv.y, a1[4 * j4 + 2]);
            a0[4 * j4 + 3] = fmaf(wv.w, hv.x, a0[4 * j4 + 3]);
            a1[4 * j4 + 3] = fmaf(wv.w, hv.y, a1[4 * j4 + 3]);
        }
    }
#pragma unroll
    for (int j = 0; j < J; j++) {
        float v0 = a0[j], v1 = a1[j];
        if (RELU) { v0 = fmaxf(v0, 0.0f); v1 = fmaxf(v1, 0.0f); }
        *reinterpret_cast<float2*>(Hout + (w + 8 * j) * PP + lane * 2) =
            make_float2(v0, v1);
    }
}

__device__ __forceinline__ int pcol(int p) { return ((p & 31) << 1) | (p >> 5); }

// shared: X[256*66] Y[256*66] Z[128*66] cfl[32*128] ccl[32*32] cl0[64] cl1[64]
constexpr int SM_FLOATS = 256 * PP + 256 * PP + 128 * PP + CC * 128 + CC * 32 + 64 + 64;
constexpr int SMEM_BYTES = SM_FLOATS * 4;   // 189,952 B

// ---------------- kernel A ----------------
__global__ __launch_bounds__(THREADS, 1) void kA(const float* __restrict__ feat,
                                                 const int* __restrict__ clus,
                                                 const float* b_in, const float* b1,
                                                 const float* b2, const float* bc1,
                                                 const float* bc2, const float* bc3) {
    extern __shared__ float sm[];
    float* X = sm;
    float* Y = X + 256 * PP;
    float* Z = Y + 256 * PP;
    int* cfl = (int*)(Z + 128 * PP);
    int* ccl = cfl + CC * 128;
    int* cl  = ccl + CC * 32;
    int t = threadIdx.x, w = t >> 5, lane = t & 31;
    int b = blockIdx.x >> 9, n0 = (blockIdx.x & 511) * P;

    for (int r = t; r < CC * 128; r += THREADS) cfl[r] = 0;
    for (int r = t; r < CC * 32; r += THREADS)  ccl[r] = 0;
    if (t < P) cl[t] = clus[b * NN + n0 + t];
    for (int r = t; r < P * KK; r += THREADS) {
        int p = r / KK, k = r % KK;
        Y[k * PP + pcol(p)] = feat[(b * NN + n0 + p) * KK + k];
    }
    __syncthreads();
    layerT2<KK, 256, true>(g_wtin, b_in, Y, X, w, lane);
    __syncthreads();
    layerT2<256, 64, true>(g_wt1[0], b1, X, Y, w, lane);
    __syncthreads();
    layerT2<64, 128, true>(g_wt2[0], b2, Y, Z, w, lane);
    __syncthreads();
    for (int r = t; r < P * 128; r += THREADS) {
        int p = r >> 7, c = r & 127;
        g_f2[(b * NN + n0 + p) * 128 + c] = Z[c * PP + pcol(p)];
    }
    layerT2<128, 128, true>(g_wtc1[0], bc1, Z, Y, w, lane);
    __syncthreads();
    layerT2<128, 256, true>(g_wtc2[0], bc2, Y, X, w, lane);
    __syncthreads();
    layerT2<256, 32, true>(g_wtc3[0], bc3, X, Y, w, lane);
    __syncthreads();
    for (int r = t; r < P * 128; r += THREADS) {
        int p = r >> 7, c = r & 127;
        atomicMax(&cfl[cl[p] * 128 + c], __float_as_int(Z[c * PP + pcol(p)]));
    }
    for (int r = t; r < P * 32; r += THREADS) {
        int p = r >> 5, c = r & 31;
        atomicMax(&ccl[cl[p] * 32 + c], __float_as_int(Y[c * PP + pcol(p)]));
    }
    __syncthreads();
    for (int r = t; r < CC * 128; r += THREADS) { int v = cfl[r]; if (v) atomicMax(&g_cf[b * CC * 128 + r], v); }
    for (int r = t; r < CC * 32; r += THREADS)  { int v = ccl[r]; if (v) atomicMax(&g_cc[b * CC * 32 + r], v); }
}

// ---------------- kernel B: per-batch corr matrix + cf @ corr ----------------
__global__ void kB(int it) {
    __shared__ float cm[CC * 32], corr[CC * CC], invn[CC], cfs[CC * 128];
    int b = blockIdx.x, t = threadIdx.x;
    for (int r = t; r < CC * 32; r += THREADS)  cm[r]  = __int_as_float(g_cc[(it * BB + b) * CC * 32 + r]);
    for (int r = t; r < CC * 128; r += THREADS) cfs[r] = __int_as_float(g_cf[(it * BB + b) * CC * 128 + r]);
    __syncthreads();
    if (t < CC) {
        float s = 0.f;
        for (int c = 0; c < 32; c++) { float v = cm[t * 32 + c]; s += v * v; }
        invn[t] = 1.0f / fmaxf(sqrtf(s), 1e-12f);
    }
    __syncthreads();
    for (int r = t; r < CC * 32; r += THREADS) cm[r] *= invn[r >> 5];
    __syncthreads();
    for (int r = t; r < CC * CC; r += THREADS) {
        int c1 = r >> 5, c2 = r & 31;
        float s = 0.f;
        for (int c = 0; c < 32; c++) s += cm[c1 * 32 + c] * cm[c2 * 32 + c];
        corr[r] = s;
    }
    __syncthreads();
    for (int r = t; r < CC * 128; r += THREADS) {
        int c2 = r >> 7, ch = r & 127;
        float s = 0.f;
        for (int c1 = 0; c1 < 32; c1++) s += cfs[c1 * 128 + ch] * corr[c1 * 32 + c2];
        g_cf2[(it * BB + b) * CC * 128 + r] = s;
    }
}

// ---------------- kernel C ----------------
__global__ __launch_bounds__(THREADS, 1) void kC(const int* __restrict__ clus,
                                                 const float* b3, const float* b1,
                                                 const float* b2, const float* bc1,
                                                 const float* bc2, const float* bc3) {
    extern __shared__ float sm[];
    float* X = sm;
    float* Y = X + 256 * PP;
    float* Z = Y + 256 * PP;
    int* cfl = (int*)(Z + 128 * PP);
    int* ccl = cfl + CC * 128;
    int* cl0 = ccl + CC * 32;
    int* cl1 = cl0 + 64;
    int t = threadIdx.x, w = t >> 5, lane = t & 31;
    int b = blockIdx.x >> 9, n0 = (blockIdx.x & 511) * P;

    for (int r = t; r < CC * 128; r += THREADS) cfl[r] = 0;
    for (int r = t; r < CC * 32; r += THREADS)  ccl[r] = 0;
    if (t < P) {
        cl0[t] = clus[b * NN + n0 + t];
        cl1[t] = clus[(BB + b) * NN + n0 + t];
    }
    for (int r = t; r < P * 128; r += THREADS) {
        int p = r >> 7, c = r & 127;
        Z[c * PP + pcol(p)] = g_f2[(b * NN + n0 + p) * 128 + c];
    }
    __syncthreads();
    layerT2<128, 128, true>(g_wt3[0], b3, Z, X, w, lane);       // rows 0..127
    for (int r = t; r < P * 128; r += THREADS) {                // rows 128..255
        int p = r >> 7, c = r & 127;
        X[(128 + c) * PP + pcol(p)] = g_cf2[(b * CC + cl0[p]) * 128 + c];
    }
    __syncthreads();
    layerT2<256, 64, true>(g_wt1[1], b1, X, Y, w, lane);
    __syncthreads();
    layerT2<64, 128, true>(g_wt2[1], b2, Y, Z, w, lane);
    __syncthreads();
    for (int r = t; r < P * 128; r += THREADS) {
        int p = r >> 7, c = r & 127;
        g_f2[(b * NN + n0 + p) * 128 + c] = Z[c * PP + pcol(p)];
    }
    layerT2<128, 128, true>(g_wtc1[1], bc1, Z, Y, w, lane);
    __syncthreads();
    layerT2<128, 256, true>(g_wtc2[1], bc2, Y, X, w, lane);
    __syncthreads();
    layerT2<256, 32, true>(g_wtc3[1], bc3, X, Y, w, lane);
    __syncthreads();
    for (int r = t; r < P * 128; r += THREADS) {
        int p = r >> 7, c = r & 127;
        atomicMax(&cfl[cl1[p] * 128 + c], __float_as_int(Z[c * PP + pcol(p)]));
    }
    for (int r = t; r < P * 32; r += THREADS) {
        int p = r >> 5, c = r & 31;
        atomicMax(&ccl[cl1[p] * 32 + c], __float_as_int(Y[c * PP + pcol(p)]));
    }
    __syncthreads();
    for (int r = t; r < CC * 128; r += THREADS) { int v = cfl[r]; if (v) atomicMax(&g_cf[(BB + b) * CC * 128 + r], v); }
    for (int r = t; r < CC * 32; r += THREADS)  { int v = ccl[r]; if (v) atomicMax(&g_cc[(BB + b) * CC * 32 + r], v); }
}

// ---------------- kernel D ----------------
__global__ __launch_bounds__(THREADS, 1) void kD(const int* __restrict__ clus,
                                                 const float* b3, const float* bo1,
                                                 const float* bo2) {
    extern __shared__ float sm[];
    float* X = sm;
    float* Y = X + 256 * PP;
    float* Z = Y + 256 * PP;
    int* cl1 = (int*)(Z + 128 * PP);
    int t = threadIdx.x, w = t >> 5, lane = t & 31;
    int b = blockIdx.x >> 9, n0 = (blockIdx.x & 511) * P;

    if (t < P) cl1[t] = clus[(BB + b) * NN + n0 + t];
    for (int r = t; r < P * 128; r += THREADS) {
        int p = r >> 7, c = r & 127;
        Z[c * PP + pcol(p)] = g_f2[(b * NN + n0 + p) * 128 + c];
    }
    __syncthreads();
    layerT2<128, 128, true>(g_wt3[1], b3, Z, X, w, lane);       // rows 0..127
    for (int r = t; r < P * 128; r += THREADS) {                // rows 128..255
        int p = r >> 7, c = r & 127;
        X[(128 + c) * PP + pcol(p)] = g_cf2[((BB + b) * CC + cl1[p]) * 128 + c];
    }
    __syncthreads();
    layerT2<256, 128, true>(g_wto1, bo1, X, Y, w, lane);
    __syncthreads();
    layerT2<128, 128, true>(g_wto2, bo2, Y, Z, w, lane);
    __syncthreads();
    if (t < 128) {
        float m = 0.0f;
        for (int c = 0; c < P; c++) m = fmaxf(m, Z[t * PP + c]);
        atomicMax(&g_net[b * 128 + t], __float_as_int(m));
    }
}

// ---------------- kernel E: dense head ----------------
__global__ void kE(const float* __restrict__ dw1, const float* __restrict__ db1,
                   const float* __restrict__ dw2, const float* __restrict__ db2,
                   const float* __restrict__ dw3, const float* __restrict__ db3,
                   float* __restrict__ out) {
    __shared__ float net[BB * 128], l1[BB * 256], l2[BB * 256];
    int t = threadIdx.x;
    for (int r = t; r < BB * 128; r += THREADS) net[r] = __int_as_float(g_net[r]);
    __syncthreads();
    for (int r = t; r < BB * 256; r += THREADS) {
        int b = r >> 8, o = r & 255;
        float s = db1[o];
        for (int i = 0; i < 128; i++) s = fmaf(net[b * 128 + i], dw1[i * 256 + o], s);
        l1[r] = s >= 0.f ? s : 0.2f * s;
    }
    __syncthreads();
    for (int r = t; r < BB * 256; r += THREADS) {
        int b = r >> 8, o = r & 255;
        float s = db2[o];
        for (int i = 0; i < 256; i++) s = fmaf(l1[b * 256 + i], dw2[i * 256 + o], s);
        l2[r] = s >= 0.f ? s : 0.2f * s;
    }
    __syncthreads();
    for (int r = t; r < BB * 40; r += THREADS) {
        int b = r / 40, o = r % 40;
        float s = db3[o];
        for (int i = 0; i < 256; i++) s = fmaf(l2[b * 256 + i], dw3[i * 40 + o], s);
        out[r] = s;
    }
}

// ---------------- host launcher ----------------
extern "C" void kernel_launch(void* const* d_in, const int* in_sizes, int n_in,
                              void* d_out, int out_size) {
    const float* feat = (const float*)d_in[0];
    const int*   clus = (const int*)d_in[1];
    const float* w_in = (const float*)d_in[2];
    const float* b_in = (const float*)d_in[3];
    const float* w1   = (const float*)d_in[4];
    const float* b1   = (const float*)d_in[5];
    const float* w2   = (const float*)d_in[6];
    const float* b2   = (const float*)d_in[7];
    const float* w3   = (const float*)d_in[8];
    const float* b3   = (const float*)d_in[9];
    const float* wc1  = (const float*)d_in[10];
    const float* bc1  = (const float*)d_in[11];
    const float* wc2  = (const float*)d_in[12];
    const float* bc2  = (const float*)d_in[13];
    const float* wc3  = (const float*)d_in[14];
    const float* bc3  = (const float*)d_in[15];
    const float* wo1  = (const float*)d_in[16];
    const float* bo1  = (const float*)d_in[17];
    const float* wo2  = (const float*)d_in[18];
    const float* bo2  = (const float*)d_in[19];
    const float* dw1  = (const float*)d_in[20];
    const float* db1  = (const float*)d_in[21];
    const float* dw2  = (const float*)d_in[22];
    const float* db2  = (const float*)d_in[23];
    const float* dw3  = (const float*)d_in[24];
    const float* db3  = (const float*)d_in[25];

    cudaFuncSetAttribute(kA, cudaFuncAttributeMaxDynamicSharedMemorySize, SMEM_BYTES);
    cudaFuncSetAttribute(kC, cudaFuncAttributeMaxDynamicSharedMemorySize, SMEM_BYTES);
    cudaFuncSetAttribute(kD, cudaFuncAttributeMaxDynamicSharedMemorySize, SMEM_BYTES);

    float *p_wtin, *p_wt1, *p_wt2, *p_wt3, *p_wtc1, *p_wtc2, *p_wtc3, *p_wto1, *p_wto2;
    cudaGetSymbolAddress((void**)&p_wtin, g_wtin);
    cudaGetSymbolAddress((void**)&p_wt1,  g_wt1);
    cudaGetSymbolAddress((void**)&p_wt2,  g_wt2);
    cudaGetSymbolAddress((void**)&p_wt3,  g_wt3);
    cudaGetSymbolAddress((void**)&p_wtc1, g_wtc1);
    cudaGetSymbolAddress((void**)&p_wtc2, g_wtc2);
    cudaGetSymbolAddress((void**)&p_wtc3, g_wtc3);
    cudaGetSymbolAddress((void**)&p_wto1, g_wto1);
    cudaGetSymbolAddress((void**)&p_wto2, g_wto2);

    TPJobs jobs;
    int idx = 0, total = 0;
    auto add = [&](const float* s, float* d, int I, int O) {
        jobs.src[idx] = s; jobs.dst[idx] = d;
        jobs.I[idx] = I; jobs.O[idx] = O; jobs.n[idx] = I * O;
        total += I * O; idx++;
    };
    add(w_in, p_wtin, KK, 256);
    for (int it = 0; it < 2; it++) {
        add(w1  + it * 64 * 256,  p_wt1  + it * 256 * 64,  256, 64);
        add(w2  + it * 128 * 64,  p_wt2  + it * 64 * 128,  64, 128);
        add(w3  + it * 128 * 128, p_wt3  + it * 128 * 128, 128, 128);
        add(wc1 + it * 128 * 128, p_wtc1 + it * 128 * 128, 128, 128);
        add(wc2 + it * 256 * 128, p_wtc2 + it * 128 * 256, 128, 256);
        add(wc3 + it * 32 * 256,  p_wtc3 + it * 256 * 32,  256, 32);
    }
    add(wo1, p_wto1, 256, 128);
    add(wo2, p_wto2, 128, 128);

    // launch order chosen so ncu (-s 5 -c 1) captures kC (6th launch)
    tp_all<<<(total + 255) / 256, 256>>>(jobs, total);   // 1
    zero1_k<<<256, 256>>>();                             // 2
    zero2_k<<<4, 256>>>();                               // 3

    int grid = BB * (NN / P);   // 4096
    kA<<<grid, THREADS, SMEM_BYTES>>>(feat, clus, b_in, b1, b2, bc1, bc2, bc3);   // 4
    kB<<<BB, THREADS>>>(0);                                                       // 5
    kC<<<grid, THREADS, SMEM_BYTES>>>(clus, b3, b1 + 64, b2 + 128, bc1 + 128, bc2 + 256, bc3 + 32); // 6 <- ncu
    kB<<<BB, THREADS>>>(1);
    kD<<<grid, THREADS, SMEM_BYTES>>>(clus, b3 + 128, bo1, bo2);
    kE<<<1, THREADS>>>(dw1, db1, dw2, db2, dw3, db3, (float*)d_out);
}

// round 3
// speedup vs baseline: 1.2726x; 1.0897x over previous
#include <cuda_runtime.h>
#include <cuda_bf16.h>

#define BB 8
#define NN 32768
#define CC 32
#define KK 22

constexpr int P  = 64;        // points per block (2 per thread-lane, pair-interleaved)
constexpr int PP = 66;        // padded row pitch in floats
constexpr int THREADS = 512;  // 16 warps
constexpr int TE = 256;       // threads for small kernels

// ---------------- device scratch ----------------
__device__ float g_f2[BB * NN * 128];
__device__ int   g_cf[2 * BB * CC * 128];
__device__ int   g_cc[2 * BB * CC * 32];
__device__ float g_cf2[2 * BB * CC * 128];
__device__ int   g_net[BB * 128];

// transposed weights: dst[i*O + w*(O/16) + j] = W[(w+16j)][i]
__device__ float g_wtin[KK * 256];
__device__ float g_wt1 [2][256 * 64];
__device__ float g_wt2 [2][64 * 128];
__device__ float g_wt3 [2][128 * 128];
__device__ float g_wtc1[2][128 * 128];
__device__ float g_wtc2[2][128 * 256];
__device__ float g_wtc3[2][256 * 32];
__device__ float g_wto1[256 * 128];
__device__ float g_wto2[128 * 128];

// ---------------- prep: all weight transposes in ONE launch ----------------
struct TPJobs {
    const float* src[15];
    float*       dst[15];
    int          I[15];
    int          O[15];
    int          n[15];
};

__global__ void tp_all(TPJobs jobs, int total) {
    int t = blockIdx.x * blockDim.x + threadIdx.x;
    if (t >= total) return;
    int j = 0;
    int e = t;
    while (e >= jobs.n[j]) { e -= jobs.n[j]; j++; }
    int I = jobs.I[j], O = jobs.O[j];
    int o = e / I, i = e % I;
    int w = o & 15, jj = o >> 4;
    jobs.dst[j][i * O + w * (O >> 4) + jj] = jobs.src[j][o * I + i];
}

__global__ void zero1_k() {
    int t = blockIdx.x * blockDim.x + threadIdx.x;
    if (t < 2 * BB * CC * 128) g_cf[t] = 0;
    if (t < 2 * BB * CC * 32)  g_cc[t] = 0;
}
__global__ void zero2_k() {
    int t = blockIdx.x * blockDim.x + threadIdx.x;
    if (t < BB * 128) g_net[t] = 0;
}

// ---------------- fused layer: O x I matvec over 64 points (2/thread) -------
// 16 warps: warp w owns outputs o = w + 16*j ; lane owns point pair (lane, lane+32)
template <int I, int O, bool RELU>
__device__ __forceinline__ void layerT16(const float* __restrict__ WT,
                                         const float* __restrict__ bias,
                                         const float* __restrict__ Hin,
                                         float* __restrict__ Hout,
                                         int w, int lane) {
    constexpr int J = O / 16;
    constexpr int J4 = J / 4;
    constexpr int JR = J & 3;   // 0 or 2
    float a0[J], a1[J];
#pragma unroll
    for (int j = 0; j < J; j++) {
        float bv = __ldg(bias + w + 16 * j);
        a0[j] = bv; a1[j] = bv;
    }
    const float* hp = Hin + lane * 2;
#pragma unroll 2
    for (int i = 0; i < I; i++) {
        float2 hv = *reinterpret_cast<const float2*>(hp + i * PP);
        const float* wr = WT + i * O + w * J;
#pragma unroll
        for (int j4 = 0; j4 < J4; j4++) {
            float4 wv = __ldg(reinterpret_cast<const float4*>(wr) + j4);
            a0[4 * j4 + 0] = fmaf(wv.x, hv.x, a0[4 * j4 + 0]);
            a1[4 * j4 + 0] = fmaf(wv.x, hv.y, a1[4 * j4 + 0]);
            a0[4 * j4 + 1] = fmaf(wv.y, hv.x, a0[4 * j4 + 1]);
            a1[4 * j4 + 1] = fmaf(wv.y, hv.y, a1[4 * j4 + 1]);
            a0[4 * j4 + 2] = fmaf(wv.z, hv.x, a0[4 * j4 + 2]);
            a1[4 * j4 + 2] = fmaf(wv.z, hv.y, a1[4 * j4 + 2]);
            a0[4 * j4 + 3] = fmaf(wv.w, hv.x, a0[4 * j4 + 3]);
            a1[4 * j4 + 3] = fmaf(wv.w, hv.y, a1[4 * j4 + 3]);
        }
        if (JR == 2) {
            float2 wv = __ldg(reinterpret_cast<const float2*>(wr + 4 * J4));
            a0[4 * J4 + 0] = fmaf(wv.x, hv.x, a0[4 * J4 + 0]);
            a1[4 * J4 + 0] = fmaf(wv.x, hv.y, a1[4 * J4 + 0]);
            a0[4 * J4 + 1] = fmaf(wv.y, hv.x, a0[4 * J4 + 1]);
            a1[4 * J4 + 1] = fmaf(wv.y, hv.y, a1[4 * J4 + 1]);
        }
    }
#pragma unroll
    for (int j = 0; j < J; j++) {
        float v0 = a0[j], v1 = a1[j];
        if (RELU) { v0 = fmaxf(v0, 0.0f); v1 = fmaxf(v1, 0.0f); }
        *reinterpret_cast<float2*>(Hout + (w + 16 * j) * PP + lane * 2) =
            make_float2(v0, v1);
    }
}

__device__ __forceinline__ int pcol(int p) { return ((p & 31) << 1) | (p >> 5); }

// shared: X[256*66] Y[256*66] Z[128*66] cfl[32*128] ccl[32*32] cl0[64] cl1[64]
constexpr int SM_FLOATS = 256 * PP + 256 * PP + 128 * PP + CC * 128 + CC * 32 + 64 + 64;
constexpr int SMEM_BYTES = SM_FLOATS * 4;   // 189,952 B

// ---------------- kernel A ----------------
__global__ __launch_bounds__(THREADS, 1) void kA(const float* __restrict__ feat,
                                                 const int* __restrict__ clus,
                                                 const float* b_in, const float* b1,
                                                 const float* b2, const float* bc1,
                                                 const float* bc2, const float* bc3) {
    extern __shared__ float sm[];
    float* X = sm;
    float* Y = X + 256 * PP;
    float* Z = Y + 256 * PP;
    int* cfl = (int*)(Z + 128 * PP);
    int* ccl = cfl + CC * 128;
    int* cl  = ccl + CC * 32;
    int t = threadIdx.x, w = t >> 5, lane = t & 31;
    int b = blockIdx.x >> 9, n0 = (blockIdx.x & 511) * P;

    for (int r = t; r < CC * 128; r += THREADS) cfl[r] = 0;
    for (int r = t; r < CC * 32; r += THREADS)  ccl[r] = 0;
    if (t < P) cl[t] = clus[b * NN + n0 + t];
    for (int r = t; r < P * KK; r += THREADS) {
        int p = r / KK, k = r % KK;
        Y[k * PP + pcol(p)] = feat[(b * NN + n0 + p) * KK + k];
    }
    __syncthreads();
    layerT16<KK, 256, true>(g_wtin, b_in, Y, X, w, lane);
    __syncthreads();
    layerT16<256, 64, true>(g_wt1[0], b1, X, Y, w, lane);
    __syncthreads();
    layerT16<64, 128, true>(g_wt2[0], b2, Y, Z, w, lane);
    __syncthreads();
    for (int r = t; r < P * 128; r += THREADS) {
        int p = r >> 7, c = r & 127;
        g_f2[(b * NN + n0 + p) * 128 + c] = Z[c * PP + pcol(p)];
    }
    layerT16<128, 128, true>(g_wtc1[0], bc1, Z, Y, w, lane);
    __syncthreads();
    layerT16<128, 256, true>(g_wtc2[0], bc2, Y, X, w, lane);
    __syncthreads();
    layerT16<256, 32, true>(g_wtc3[0], bc3, X, Y, w, lane);
    __syncthreads();
    for (int r = t; r < P * 128; r += THREADS) {
        int p = r >> 7, c = r & 127;
        atomicMax(&cfl[cl[p] * 128 + c], __float_as_int(Z[c * PP + pcol(p)]));
    }
    for (int r = t; r < P * 32; r += THREADS) {
        int p = r >> 5, c = r & 31;
        atomicMax(&ccl[cl[p] * 32 + c], __float_as_int(Y[c * PP + pcol(p)]));
    }
    __syncthreads();
    for (int r = t; r < CC * 128; r += THREADS) { int v = cfl[r]; if (v) atomicMax(&g_cf[b * CC * 128 + r], v); }
    for (int r = t; r < CC * 32; r += THREADS)  { int v = ccl[r]; if (v) atomicMax(&g_cc[b * CC * 32 + r], v); }
}

// ---------------- kernel B: per-batch corr matrix + cf @ corr ----------------
__global__ void kB(int it) {
    __shared__ float cm[CC * 32], corr[CC * CC], invn[CC], cfs[CC * 128];
    int b = blockIdx.x, t = threadIdx.x;
    for (int r = t; r < CC * 32; r += TE)  cm[r]  = __int_as_float(g_cc[(it * BB + b) * CC * 32 + r]);
    for (int r = t; r < CC * 128; r += TE) cfs[r] = __int_as_float(g_cf[(it * BB + b) * CC * 128 + r]);
    __syncthreads();
    if (t < CC) {
        float s = 0.f;
        for (int c = 0; c < 32; c++) { float v = cm[t * 32 + c]; s += v * v; }
        invn[t] = 1.0f / fmaxf(sqrtf(s), 1e-12f);
    }
    __syncthreads();
    for (int r = t; r < CC * 32; r += TE) cm[r] *= invn[r >> 5];
    __syncthreads();
    for (int r = t; r < CC * CC; r += TE) {
        int c1 = r >> 5, c2 = r & 31;
        float s = 0.f;
        for (int c = 0; c < 32; c++) s += cm[c1 * 32 + c] * cm[c2 * 32 + c];
        corr[r] = s;
    }
    __syncthreads();
    for (int r = t; r < CC * 128; r += TE) {
        int c2 = r >> 7, ch = r & 127;
        float s = 0.f;
        for (int c1 = 0; c1 < 32; c1++) s += cfs[c1 * 128 + ch] * corr[c1 * 32 + c2];
        g_cf2[(it * BB + b) * CC * 128 + r] = s;
    }
}

// ---------------- kernel C ----------------
__global__ __launch_bounds__(THREADS, 1) void kC(const int* __restrict__ clus,
                                                 const float* b3, const float* b1,
                                                 const float* b2, const float* bc1,
                                                 const float* bc2, const float* bc3) {
    extern __shared__ float sm[];
    float* X = sm;
    float* Y = X + 256 * PP;
    float* Z = Y + 256 * PP;
    int* cfl = (int*)(Z + 128 * PP);
    int* ccl = cfl + CC * 128;
    int* cl0 = ccl + CC * 32;
    int* cl1 = cl0 + 64;
    int t = threadIdx.x, w = t >> 5, lane = t & 31;
    int b = blockIdx.x >> 9, n0 = (blockIdx.x & 511) * P;

    for (int r = t; r < CC * 128; r += THREADS) cfl[r] = 0;
    for (int r = t; r < CC * 32; r += THREADS)  ccl[r] = 0;
    if (t < P) {
        cl0[t] = clus[b * NN + n0 + t];
        cl1[t] = clus[(BB + b) * NN + n0 + t];
    }
    for (int r = t; r < P * 128; r += THREADS) {
        int p = r >> 7, c = r & 127;
        Z[c * PP + pcol(p)] = g_f2[(b * NN + n0 + p) * 128 + c];
    }
    __syncthreads();
    layerT16<128, 128, true>(g_wt3[0], b3, Z, X, w, lane);      // rows 0..127
    for (int r = t; r < P * 128; r += THREADS) {                // rows 128..255
        int p = r >> 7, c = r & 127;
        X[(128 + c) * PP + pcol(p)] = g_cf2[(b * CC + cl0[p]) * 128 + c];
    }
    __syncthreads();
    layerT16<256, 64, true>(g_wt1[1], b1, X, Y, w, lane);
    __syncthreads();
    layerT16<64, 128, true>(g_wt2[1], b2, Y, Z, w, lane);
    __syncthreads();
    for (int r = t; r < P * 128; r += THREADS) {
        int p = r >> 7, c = r & 127;
        g_f2[(b * NN + n0 + p) * 128 + c] = Z[c * PP + pcol(p)];
    }
    layerT16<128, 128, true>(g_wtc1[1], bc1, Z, Y, w, lane);
    __syncthreads();
    layerT16<128, 256, true>(g_wtc2[1], bc2, Y, X, w, lane);
    __syncthreads();
    layerT16<256, 32, true>(g_wtc3[1], bc3, X, Y, w, lane);
    __syncthreads();
    for (int r = t; r < P * 128; r += THREADS) {
        int p = r >> 7, c = r & 127;
        atomicMax(&cfl[cl1[p] * 128 + c], __float_as_int(Z[c * PP + pcol(p)]));
    }
    for (int r = t; r < P * 32; r += THREADS) {
        int p = r >> 5, c = r & 31;
        atomicMax(&ccl[cl1[p] * 32 + c], __float_as_int(Y[c * PP + pcol(p)]));
    }
    __syncthreads();
    for (int r = t; r < CC * 128; r += THREADS) { int v = cfl[r]; if (v) atomicMax(&g_cf[(BB + b) * CC * 128 + r], v); }
    for (int r = t; r < CC * 32; r += THREADS)  { int v = ccl[r]; if (v) atomicMax(&g_cc[(BB + b) * CC * 32 + r], v); }
}

// ---------------- kernel D ----------------
__global__ __launch_bounds__(THREADS, 1) void kD(const int* __restrict__ clus,
                                                 const float* b3, const float* bo1,
                                                 const float* bo2) {
    extern __shared__ float sm[];
    float* X = sm;
    float* Y = X + 256 * PP;
    float* Z = Y + 256 * PP;
    int* cl1 = (int*)(Z + 128 * PP);
    int t = threadIdx.x, w = t >> 5, lane = t & 31;
    int b = blockIdx.x >> 9, n0 = (blockIdx.x & 511) * P;

    if (t < P) cl1[t] = clus[(BB + b) * NN + n0 + t];
    for (int r = t; r < P * 128; r += THREADS) {
        int p = r >> 7, c = r & 127;
        Z[c * PP + pcol(p)] = g_f2[(b * NN + n0 + p) * 128 + c];
    }
    __syncthreads();
    layerT16<128, 128, true>(g_wt3[1], b3, Z, X, w, lane);      // rows 0..127
    for (int r = t; r < P * 128; r += THREADS) {                // rows 128..255
        int p = r >> 7, c = r & 127;
        X[(128 + c) * PP + pcol(p)] = g_cf2[((BB + b) * CC + cl1[p]) * 128 + c];
    }
    __syncthreads();
    layerT16<256, 128, true>(g_wto1, bo1, X, Y, w, lane);
    __syncthreads();
    layerT16<128, 128, true>(g_wto2, bo2, Y, Z, w, lane);
    __syncthreads();
    if (t < 128) {
        float m = 0.0f;
        for (int c = 0; c < P; c++) m = fmaxf(m, Z[t * PP + c]);
        atomicMax(&g_net[b * 128 + t], __float_as_int(m));
    }
}

// ---------------- kernel E: dense head ----------------
__global__ void kE(const float* __restrict__ dw1, const float* __restrict__ db1,
                   const float* __restrict__ dw2, const float* __restrict__ db2,
                   const float* __restrict__ dw3, const float* __restrict__ db3,
                   float* __restrict__ out) {
    __shared__ float net[BB * 128], l1[BB * 256], l2[BB * 256];
    int t = threadIdx.x;
    for (int r = t; r < BB * 128; r += TE) net[r] = __int_as_float(g_net[r]);
    __syncthreads();
    for (int r = t; r < BB * 256; r += TE) {
        int b = r >> 8, o = r & 255;
        float s = db1[o];
        for (int i = 0; i < 128; i++) s = fmaf(net[b * 128 + i], dw1[i * 256 + o], s);
        l1[r] = s >= 0.f ? s : 0.2f * s;
    }
    __syncthreads();
    for (int r = t; r < BB * 256; r += TE) {
        int b = r >> 8, o = r & 255;
        float s = db2[o];
        for (int i = 0; i < 256; i++) s = fmaf(l1[b * 256 + i], dw2[i * 256 + o], s);
        l2[r] = s >= 0.f ? s : 0.2f * s;
    }
    __syncthreads();
    for (int r = t; r < BB * 40; r += TE) {
        int b = r / 40, o = r % 40;
        float s = db3[o];
        for (int i = 0; i < 256; i++) s = fmaf(l2[b * 256 + i], dw3[i * 40 + o], s);
        out[r] = s;
    }
}

// ---------------- host launcher ----------------
extern "C" void kernel_launch(void* const* d_in, const int* in_sizes, int n_in,
                              void* d_out, int out_size) {
    const float* feat = (const float*)d_in[0];
    const int*   clus = (const int*)d_in[1];
    const float* w_in = (const float*)d_in[2];
    const float* b_in = (const float*)d_in[3];
    const float* w1   = (const float*)d_in[4];
    const float* b1   = (const float*)d_in[5];
    const float* w2   = (const float*)d_in[6];
    const float* b2   = (const float*)d_in[7];
    const float* w3   = (const float*)d_in[8];
    const float* b3   = (const float*)d_in[9];
    const float* wc1  = (const float*)d_in[10];
    const float* bc1  = (const float*)d_in[11];
    const float* wc2  = (const float*)d_in[12];
    const float* bc2  = (const float*)d_in[13];
    const float* wc3  = (const float*)d_in[14];
    const float* bc3  = (const float*)d_in[15];
    const float* wo1  = (const float*)d_in[16];
    const float* bo1  = (const float*)d_in[17];
    const float* wo2  = (const float*)d_in[18];
    const float* bo2  = (const float*)d_in[19];
    const float* dw1  = (const float*)d_in[20];
    const float* db1  = (const float*)d_in[21];
    const float* dw2  = (const float*)d_in[22];
    const float* db2  = (const float*)d_in[23];
    const float* dw3  = (const float*)d_in[24];
    const float* db3  = (const float*)d_in[25];

    cudaFuncSetAttribute(kA, cudaFuncAttributeMaxDynamicSharedMemorySize, SMEM_BYTES);
    cudaFuncSetAttribute(kC, cudaFuncAttributeMaxDynamicSharedMemorySize, SMEM_BYTES);
    cudaFuncSetAttribute(kD, cudaFuncAttributeMaxDynamicSharedMemorySize, SMEM_BYTES);

    float *p_wtin, *p_wt1, *p_wt2, *p_wt3, *p_wtc1, *p_wtc2, *p_wtc3, *p_wto1, *p_wto2;
    cudaGetSymbolAddress((void**)&p_wtin, g_wtin);
    cudaGetSymbolAddress((void**)&p_wt1,  g_wt1);
    cudaGetSymbolAddress((void**)&p_wt2,  g_wt2);
    cudaGetSymbolAddress((void**)&p_wt3,  g_wt3);
    cudaGetSymbolAddress((void**)&p_wtc1, g_wtc1);
    cudaGetSymbolAddress((void**)&p_wtc2, g_wtc2);
    cudaGetSymbolAddress((void**)&p_wtc3, g_wtc3);
    cudaGetSymbolAddress((void**)&p_wto1, g_wto1);
    cudaGetSymbolAddress((void**)&p_wto2, g_wto2);

    TPJobs jobs;
    int idx = 0, total = 0;
    auto add = [&](const float* s, float* d, int I, int O) {
        jobs.src[idx] = s; jobs.dst[idx] = d;
        jobs.I[idx] = I; jobs.O[idx] = O; jobs.n[idx] = I * O;
        total += I * O; idx++;
    };
    add(w_in, p_wtin, KK, 256);
    for (int it = 0; it < 2; it++) {
        add(w1  + it * 64 * 256,  p_wt1  + it * 256 * 64,  256, 64);
        add(w2  + it * 128 * 64,  p_wt2  + it * 64 * 128,  64, 128);
        add(w3  + it * 128 * 128, p_wt3  + it * 128 * 128, 128, 128);
        add(wc1 + it * 128 * 128, p_wtc1 + it * 128 * 128, 128, 128);
        add(wc2 + it * 256 * 128, p_wtc2 + it * 128 * 256, 128, 256);
        add(wc3 + it * 32 * 256,  p_wtc3 + it * 256 * 32,  256, 32);
    }
    add(wo1, p_wto1, 256, 128);
    add(wo2, p_wto2, 128, 128);

    // launch order chosen so ncu (-s 5 -c 1) captures kC (6th launch)
    tp_all<<<(total + 255) / 256, 256>>>(jobs, total);   // 1
    zero1_k<<<256, 256>>>();                             // 2
    zero2_k<<<4, 256>>>();                               // 3

    int grid = BB * (NN / P);   // 4096
    kA<<<grid, THREADS, SMEM_BYTES>>>(feat, clus, b_in, b1, b2, bc1, bc2, bc3);   // 4
    kB<<<BB, TE>>>(0);                                                            // 5
    kC<<<grid, THREADS, SMEM_BYTES>>>(clus, b3, b1 + 64, b2 + 128, bc1 + 128, bc2 + 256, bc3 + 32); // 6 <- ncu
    kB<<<BB, TE>>>(1);
    kD<<<grid, THREADS, SMEM_BYTES>>>(clus, b3 + 128, bo1, bo2);
    kE<<<1, TE>>>(dw1, db1, dw2, db2, dw3, db3, (float*)d_out);
}

// round 4
// speedup vs baseline: 1.5907x; 1.2500x over previous
#include <cuda_runtime.h>
#include <cuda_bf16.h>

#define BB 8
#define NN 32768
#define CC 32
#define KK 22

constexpr int P  = 64;        // points per block (2 per thread-lane, pair-interleaved)
constexpr int PP = 66;        // padded row pitch in floats
constexpr int THREADS = 512;  // 16 warps
constexpr int TE = 256;       // threads for small kernels

// ---------------- device scratch ----------------
__device__ float g_f2[BB * NN * 128];
__device__ int   g_cf[2 * BB * CC * 128];
__device__ int   g_cc[2 * BB * CC * 32];
__device__ float g_cf2[2 * BB * CC * 128];
__device__ int   g_net[BB * 128];

// transposed weights: dst[i*O + w*(O/16) + j] = W[(w+16j)][i]
__device__ float g_wtin[KK * 256];
__device__ float g_wt1 [2][256 * 64];
__device__ float g_wt2 [2][64 * 128];
__device__ float g_wt3 [2][128 * 128];
__device__ float g_wtc1[2][128 * 128];
__device__ float g_wtc2[2][128 * 256];
__device__ float g_wtc3[2][256 * 32];
__device__ float g_wto1[256 * 128];
__device__ float g_wto2[128 * 128];

// ---------------- prep: all weight transposes in ONE launch ----------------
struct TPJobs {
    const float* src[15];
    float*       dst[15];
    int          I[15];
    int          O[15];
    int          n[15];
};

__global__ void tp_all(TPJobs jobs, int total) {
    int t = blockIdx.x * blockDim.x + threadIdx.x;
    if (t >= total) return;
    int j = 0;
    int e = t;
    while (e >= jobs.n[j]) { e -= jobs.n[j]; j++; }
    int I = jobs.I[j], O = jobs.O[j];
    int o = e / I, i = e % I;
    int w = o & 15, jj = o >> 4;
    jobs.dst[j][i * O + w * (O >> 4) + jj] = jobs.src[j][o * I + i];
}

__global__ void zero1_k() {
    int t = blockIdx.x * blockDim.x + threadIdx.x;
    if (t < 2 * BB * CC * 128) g_cf[t] = 0;
    if (t < 2 * BB * CC * 32)  g_cc[t] = 0;
}
__global__ void zero2_k() {
    int t = blockIdx.x * blockDim.x + threadIdx.x;
    if (t < BB * 128) g_net[t] = 0;
}

// ---------------- fused layer: O x I matvec over 64 points (2/thread) -------
// 16 warps: warp w owns outputs o = w + 16*j ; lane owns point pair (lane, lane+32)
// Inner loop chunked so U*J == 32: all weight/activation loads for a chunk are
// batched up front (MLP ~8-16) before the 64 FMAs, hiding L2 latency.
template <int I, int O, bool RELU>
__device__ __forceinline__ void layerT16(const float* __restrict__ WT,
                                         const float* __restrict__ bias,
                                         const float* __restrict__ Hin,
                                         float* __restrict__ Hout,
                                         int w, int lane) {
    constexpr int J = O / 16;
    constexpr int U = 32 / J;           // chunk depth: U*J = 32 weight floats
    static_assert(I % U == 0, "I must be divisible by U");
    float a0[J], a1[J];
#pragma unroll
    for (int j = 0; j < J; j++) {
        float bv = __ldg(bias + w + 16 * j);
        a0[j] = bv; a1[j] = bv;
    }
    const float* hp = Hin + lane * 2;
    for (int i0 = 0; i0 < I; i0 += U) {
        float2 hv[U];
#pragma unroll
        for (int u = 0; u < U; u++)
            hv[u] = *reinterpret_cast<const float2*>(hp + (i0 + u) * PP);
        if constexpr (J == 2) {
            float2 wv[U];
#pragma unroll
            for (int u = 0; u < U; u++)
                wv[u] = __ldg(reinterpret_cast<const float2*>(WT + (i0 + u) * O + w * J));
#pragma unroll
            for (int u = 0; u < U; u++) {
                a0[0] = fmaf(wv[u].x, hv[u].x, a0[0]);
                a1[0] = fmaf(wv[u].x, hv[u].y, a1[0]);
                a0[1] = fmaf(wv[u].y, hv[u].x, a0[1]);
                a1[1] = fmaf(wv[u].y, hv[u].y, a1[1]);
            }
        } else {
            constexpr int NF4 = (J >= 4) ? J / 4 : 1;
            float4 wv[U][NF4];
#pragma unroll
            for (int u = 0; u < U; u++)
#pragma unroll
                for (int f = 0; f < NF4; f++)
                    wv[u][f] = __ldg(reinterpret_cast<const float4*>(WT + (i0 + u) * O + w * J) + f);
#pragma unroll
            for (int u = 0; u < U; u++) {
#pragma unroll
                for (int f = 0; f < NF4; f++) {
                    a0[4 * f + 0] = fmaf(wv[u][f].x, hv[u].x, a0[4 * f + 0]);
                    a1[4 * f + 0] = fmaf(wv[u][f].x, hv[u].y, a1[4 * f + 0]);
                    a0[4 * f + 1] = fmaf(wv[u][f].y, hv[u].x, a0[4 * f + 1]);
                    a1[4 * f + 1] = fmaf(wv[u][f].y, hv[u].y, a1[4 * f + 1]);
                    a0[4 * f + 2] = fmaf(wv[u][f].z, hv[u].x, a0[4 * f + 2]);
                    a1[4 * f + 2] = fmaf(wv[u][f].z, hv[u].y, a1[4 * f + 2]);
                    a0[4 * f + 3] = fmaf(wv[u][f].w, hv[u].x, a0[4 * f + 3]);
                    a1[4 * f + 3] = fmaf(wv[u][f].w, hv[u].y, a1[4 * f + 3]);
                }
            }
        }
    }
#pragma unroll
    for (int j = 0; j < J; j++) {
        float v0 = a0[j], v1 = a1[j];
        if (RELU) { v0 = fmaxf(v0, 0.0f); v1 = fmaxf(v1, 0.0f); }
        *reinterpret_cast<float2*>(Hout + (w + 16 * j) * PP + lane * 2) =
            make_float2(v0, v1);
    }
}

__device__ __forceinline__ int pcol(int p) { return ((p & 31) << 1) | (p >> 5); }

// shared: X[256*66] Y[256*66] Z[128*66] cfl[32*128] ccl[32*32] cl0[64] cl1[64]
constexpr int SM_FLOATS = 256 * PP + 256 * PP + 128 * PP + CC * 128 + CC * 32 + 64 + 64;
constexpr int SMEM_BYTES = SM_FLOATS * 4;   // 189,952 B

// ---------------- kernel A ----------------
__global__ __launch_bounds__(THREADS, 1) void kA(const float* __restrict__ feat,
                                                 const int* __restrict__ clus,
                                                 const float* b_in, const float* b1,
                                                 const float* b2, const float* bc1,
                                                 const float* bc2, const float* bc3) {
    extern __shared__ float sm[];
    float* X = sm;
    float* Y = X + 256 * PP;
    float* Z = Y + 256 * PP;
    int* cfl = (int*)(Z + 128 * PP);
    int* ccl = cfl + CC * 128;
    int* cl  = ccl + CC * 32;
    int t = threadIdx.x, w = t >> 5, lane = t & 31;
    int b = blockIdx.x >> 9, n0 = (blockIdx.x & 511) * P;

    for (int r = t; r < CC * 128; r += THREADS) cfl[r] = 0;
    for (int r = t; r < CC * 32; r += THREADS)  ccl[r] = 0;
    if (t < P) cl[t] = clus[b * NN + n0 + t];
    for (int r = t; r < P * KK; r += THREADS) {
        int p = r / KK, k = r % KK;
        Y[k * PP + pcol(p)] = feat[(b * NN + n0 + p) * KK + k];
    }
    __syncthreads();
    layerT16<KK, 256, true>(g_wtin, b_in, Y, X, w, lane);
    __syncthreads();
    layerT16<256, 64, true>(g_wt1[0], b1, X, Y, w, lane);
    __syncthreads();
    layerT16<64, 128, true>(g_wt2[0], b2, Y, Z, w, lane);
    __syncthreads();
    for (int r = t; r < P * 128; r += THREADS) {
        int p = r >> 7, c = r & 127;
        g_f2[(b * NN + n0 + p) * 128 + c] = Z[c * PP + pcol(p)];
    }
    layerT16<128, 128, true>(g_wtc1[0], bc1, Z, Y, w, lane);
    __syncthreads();
    layerT16<128, 256, true>(g_wtc2[0], bc2, Y, X, w, lane);
    __syncthreads();
    layerT16<256, 32, true>(g_wtc3[0], bc3, X, Y, w, lane);
    __syncthreads();
    for (int r = t; r < P * 128; r += THREADS) {
        int p = r >> 7, c = r & 127;
        atomicMax(&cfl[cl[p] * 128 + c], __float_as_int(Z[c * PP + pcol(p)]));
    }
    for (int r = t; r < P * 32; r += THREADS) {
        int p = r >> 5, c = r & 31;
        atomicMax(&ccl[cl[p] * 32 + c], __float_as_int(Y[c * PP + pcol(p)]));
    }
    __syncthreads();
    for (int r = t; r < CC * 128; r += THREADS) { int v = cfl[r]; if (v) atomicMax(&g_cf[b * CC * 128 + r], v); }
    for (int r = t; r < CC * 32; r += THREADS)  { int v = ccl[r]; if (v) atomicMax(&g_cc[b * CC * 32 + r], v); }
}

// ---------------- kernel B: per-batch corr matrix + cf @ corr ----------------
__global__ void kB(int it) {
    __shared__ float cm[CC * 32], corr[CC * CC], invn[CC], cfs[CC * 128];
    int b = blockIdx.x, t = threadIdx.x;
    for (int r = t; r < CC * 32; r += TE)  cm[r]  = __int_as_float(g_cc[(it * BB + b) * CC * 32 + r]);
    for (int r = t; r < CC * 128; r += TE) cfs[r] = __int_as_float(g_cf[(it * BB + b) * CC * 128 + r]);
    __syncthreads();
    if (t < CC) {
        float s = 0.f;
        for (int c = 0; c < 32; c++) { float v = cm[t * 32 + c]; s += v * v; }
        invn[t] = 1.0f / fmaxf(sqrtf(s), 1e-12f);
    }
    __syncthreads();
    for (int r = t; r < CC * 32; r += TE) cm[r] *= invn[r >> 5];
    __syncthreads();
    for (int r = t; r < CC * CC; r += TE) {
        int c1 = r >> 5, c2 = r & 31;
        float s = 0.f;
        for (int c = 0; c < 32; c++) s += cm[c1 * 32 + c] * cm[c2 * 32 + c];
        corr[r] = s;
    }
    __syncthreads();
    for (int r = t; r < CC * 128; r += TE) {
        int c2 = r >> 7, ch = r & 127;
        float s = 0.f;
        for (int c1 = 0; c1 < 32; c1++) s += cfs[c1 * 128 + ch] * corr[c1 * 32 + c2];
        g_cf2[(it * BB + b) * CC * 128 + r] = s;
    }
}

// ---------------- kernel C ----------------
__global__ __launch_bounds__(THREADS, 1) void kC(const int* __restrict__ clus,
                                                 const float* b3, const float* b1,
                                                 const float* b2, const float* bc1,
                                                 const float* bc2, const float* bc3) {
    extern __shared__ float sm[];
    float* X = sm;
    float* Y = X + 256 * PP;
    float* Z = Y + 256 * PP;
    int* cfl = (int*)(Z + 128 * PP);
    int* ccl = cfl + CC * 128;
    int* cl0 = ccl + CC * 32;
    int* cl1 = cl0 + 64;
    int t = threadIdx.x, w = t >> 5, lane = t & 31;
    int b = blockIdx.x >> 9, n0 = (blockIdx.x & 511) * P;

    for (int r = t; r < CC * 128; r += THREADS) cfl[r] = 0;
    for (int r = t; r < CC * 32; r += THREADS)  ccl[r] = 0;
    if (t < P) {
        cl0[t] = clus[b * NN + n0 + t];
        cl1[t] = clus[(BB + b) * NN + n0 + t];
    }
    for (int r = t; r < P * 128; r += THREADS) {
        int p = r >> 7, c = r & 127;
        Z[c * PP + pcol(p)] = g_f2[(b * NN + n0 + p) * 128 + c];
    }
    __syncthreads();
    layerT16<128, 128, true>(g_wt3[0], b3, Z, X, w, lane);      // rows 0..127
    for (int r = t; r < P * 128; r += THREADS) {                // rows 128..255
        int p = r >> 7, c = r & 127;
        X[(128 + c) * PP + pcol(p)] = g_cf2[(b * CC + cl0[p]) * 128 + c];
    }
    __syncthreads();
    layerT16<256, 64, true>(g_wt1[1], b1, X, Y, w, lane);
    __syncthreads();
    layerT16<64, 128, true>(g_wt2[1], b2, Y, Z, w, lane);
    __syncthreads();
    for (int r = t; r < P * 128; r += THREADS) {
        int p = r >> 7, c = r & 127;
        g_f2[(b * NN + n0 + p) * 128 + c] = Z[c * PP + pcol(p)];
    }
    layerT16<128, 128, true>(g_wtc1[1], bc1, Z, Y, w, lane);
    __syncthreads();
    layerT16<128, 256, true>(g_wtc2[1], bc2, Y, X, w, lane);
    __syncthreads();
    layerT16<256, 32, true>(g_wtc3[1], bc3, X, Y, w, lane);
    __syncthreads();
    for (int r = t; r < P * 128; r += THREADS) {
        int p = r >> 7, c = r & 127;
        atomicMax(&cfl[cl1[p] * 128 + c], __float_as_int(Z[c * PP + pcol(p)]));
    }
    for (int r = t; r < P * 32; r += THREADS) {
        int p = r >> 5, c = r & 31;
        atomicMax(&ccl[cl1[p] * 32 + c], __float_as_int(Y[c * PP + pcol(p)]));
    }
    __syncthreads();
    for (int r = t; r < CC * 128; r += THREADS) { int v = cfl[r]; if (v) atomicMax(&g_cf[(BB + b) * CC * 128 + r], v); }
    for (int r = t; r < CC * 32; r += THREADS)  { int v = ccl[r]; if (v) atomicMax(&g_cc[(BB + b) * CC * 32 + r], v); }
}

// ---------------- kernel D ----------------
__global__ __launch_bounds__(THREADS, 1) void kD(const int* __restrict__ clus,
                                                 const float* b3, const float* bo1,
                                                 const float* bo2) {
    extern __shared__ float sm[];
    float* X = sm;
    float* Y = X + 256 * PP;
    float* Z = Y + 256 * PP;
    int* cl1 = (int*)(Z + 128 * PP);
    int t = threadIdx.x, w = t >> 5, lane = t & 31;
    int b = blockIdx.x >> 9, n0 = (blockIdx.x & 511) * P;

    if (t < P) cl1[t] = clus[(BB + b) * NN + n0 + t];
    for (int r = t; r < P * 128; r += THREADS) {
        int p = r >> 7, c = r & 127;
        Z[c * PP + pcol(p)] = g_f2[(b * NN + n0 + p) * 128 + c];
    }
    __syncthreads();
    layerT16<128, 128, true>(g_wt3[1], b3, Z, X, w, lane);      // rows 0..127
    for (int r = t; r < P * 128; r += THREADS) {                // rows 128..255
        int p = r >> 7, c = r & 127;
        X[(128 + c) * PP + pcol(p)] = g_cf2[((BB + b) * CC + cl1[p]) * 128 + c];
    }
    __syncthreads();
    layerT16<256, 128, true>(g_wto1, bo1, X, Y, w, lane);
    __syncthreads();
    layerT16<128, 128, true>(g_wto2, bo2, Y, Z, w, lane);
    __syncthreads();
    if (t < 128) {
        float m = 0.0f;
        for (int c = 0; c < P; c++) m = fmaxf(m, Z[t * PP + c]);
        atomicMax(&g_net[b * 128 + t], __float_as_int(m));
    }
}

// ---------------- kernel E: dense head ----------------
__global__ void kE(const float* __restrict__ dw1, const float* __restrict__ db1,
                   const float* __restrict__ dw2, const float* __restrict__ db2,
                   const float* __restrict__ dw3, const float* __restrict__ db3,
                   float* __restrict__ out) {
    __shared__ float net[BB * 128], l1[BB * 256], l2[BB * 256];
    int t = threadIdx.x;
    for (int r = t; r < BB * 128; r += TE) net[r] = __int_as_float(g_net[r]);
    __syncthreads();
    for (int r = t; r < BB * 256; r += TE) {
        int b = r >> 8, o = r & 255;
        float s = db1[o];
        for (int i = 0; i < 128; i++) s = fmaf(net[b * 128 + i], dw1[i * 256 + o], s);
        l1[r] = s >= 0.f ? s : 0.2f * s;
    }
    __syncthreads();
    for (int r = t; r < BB * 256; r += TE) {
        int b = r >> 8, o = r & 255;
        float s = db2[o];
        for (int i = 0; i < 256; i++) s = fmaf(l1[b * 256 + i], dw2[i * 256 + o], s);
        l2[r] = s >= 0.f ? s : 0.2f * s;
    }
    __syncthreads();
    for (int r = t; r < BB * 40; r += TE) {
        int b = r / 40, o = r % 40;
        float s = db3[o];
        for (int i = 0; i < 256; i++) s = fmaf(l2[b * 256 + i], dw3[i * 40 + o], s);
        out[r] = s;
    }
}

// ---------------- host launcher ----------------
extern "C" void kernel_launch(void* const* d_in, const int* in_sizes, int n_in,
                              void* d_out, int out_size) {
    const float* feat = (const float*)d_in[0];
    const int*   clus = (const int*)d_in[1];
    const float* w_in = (const float*)d_in[2];
    const float* b_in = (const float*)d_in[3];
    const float* w1   = (const float*)d_in[4];
    const float* b1   = (const float*)d_in[5];
    const float* w2   = (const float*)d_in[6];
    const float* b2   = (const float*)d_in[7];
    const float* w3   = (const float*)d_in[8];
    const float* b3   = (const float*)d_in[9];
    const float* wc1  = (const float*)d_in[10];
    const float* bc1  = (const float*)d_in[11];
    const float* wc2  = (const float*)d_in[12];
    const float* bc2  = (const float*)d_in[13];
    const float* wc3  = (const float*)d_in[14];
    const float* bc3  = (const float*)d_in[15];
    const float* wo1  = (const float*)d_in[16];
    const float* bo1  = (const float*)d_in[17];
    const float* wo2  = (const float*)d_in[18];
    const float* bo2  = (const float*)d_in[19];
    const float* dw1  = (const float*)d_in[20];
    const float* db1  = (const float*)d_in[21];
    const float* dw2  = (const float*)d_in[22];
    const float* db2  = (const float*)d_in[23];
    const float* dw3  = (const float*)d_in[24];
    const float* db3  = (const float*)d_in[25];

    cudaFuncSetAttribute(kA, cudaFuncAttributeMaxDynamicSharedMemorySize, SMEM_BYTES);
    cudaFuncSetAttribute(kC, cudaFuncAttributeMaxDynamicSharedMemorySize, SMEM_BYTES);
    cudaFuncSetAttribute(kD, cudaFuncAttributeMaxDynamicSharedMemorySize, SMEM_BYTES);

    float *p_wtin, *p_wt1, *p_wt2, *p_wt3, *p_wtc1, *p_wtc2, *p_wtc3, *p_wto1, *p_wto2;
    cudaGetSymbolAddress((void**)&p_wtin, g_wtin);
    cudaGetSymbolAddress((void**)&p_wt1,  g_wt1);
    cudaGetSymbolAddress((void**)&p_wt2,  g_wt2);
    cudaGetSymbolAddress((void**)&p_wt3,  g_wt3);
    cudaGetSymbolAddress((void**)&p_wtc1, g_wtc1);
    cudaGetSymbolAddress((void**)&p_wtc2, g_wtc2);
    cudaGetSymbolAddress((void**)&p_wtc3, g_wtc3);
    cudaGetSymbolAddress((void**)&p_wto1, g_wto1);
    cudaGetSymbolAddress((void**)&p_wto2, g_wto2);

    TPJobs jobs;
    int idx = 0, total = 0;
    auto add = [&](const float* s, float* d, int I, int O) {
        jobs.src[idx] = s; jobs.dst[idx] = d;
        jobs.I[idx] = I; jobs.O[idx] = O; jobs.n[idx] = I * O;
        total += I * O; idx++;
    };
    add(w_in, p_wtin, KK, 256);
    for (int it = 0; it < 2; it++) {
        add(w1  + it * 64 * 256,  p_wt1  + it * 256 * 64,  256, 64);
        add(w2  + it * 128 * 64,  p_wt2  + it * 64 * 128,  64, 128);
        add(w3  + it * 128 * 128, p_wt3  + it * 128 * 128, 128, 128);
        add(wc1 + it * 128 * 128, p_wtc1 + it * 128 * 128, 128, 128);
        add(wc2 + it * 256 * 128, p_wtc2 + it * 128 * 256, 128, 256);
        add(wc3 + it * 32 * 256,  p_wtc3 + it * 256 * 32,  256, 32);
    }
    add(wo1, p_wto1, 256, 128);
    add(wo2, p_wto2, 128, 128);

    // launch order chosen so ncu (-s 5 -c 1) captures kC (6th launch)
    tp_all<<<(total + 255) / 256, 256>>>(jobs, total);   // 1
    zero1_k<<<256, 256>>>();                             // 2
    zero2_k<<<4, 256>>>();                               // 3

    int grid = BB * (NN / P);   // 4096
    kA<<<grid, THREADS, SMEM_BYTES>>>(feat, clus, b_in, b1, b2, bc1, bc2, bc3);   // 4
    kB<<<BB, TE>>>(0);                                                            // 5
    kC<<<grid, THREADS, SMEM_BYTES>>>(clus, b3, b1 + 64, b2 + 128, bc1 + 128, bc2 + 256, bc3 + 32); // 6 <- ncu
    kB<<<BB, TE>>>(1);
    kD<<<grid, THREADS, SMEM_BYTES>>>(clus, b3 + 128, bo1, bo2);
    kE<<<1, TE>>>(dw1, db1, dw2, db2, dw3, db3, (float*)d_out);
}

// round 5
// speedup vs baseline: 4.0149x; 2.5239x over previous
#include <cuda_runtime.h>
#include <cuda_bf16.h>

#define BB 8
#define NN 32768
#define CC 32
#define KIN 22

constexpr int P  = 64;        // points per block
constexpr int SPA = 272;      // A-buffer pitch (halves), 256ch, bank-friendly
constexpr int SPB = 144;      // B-buffer pitch (halves), 128ch
constexpr int THREADS = 512;  // 16 warps
constexpr int TE = 256;

// ---------------- device scratch ----------------
__device__ unsigned g_f2u[BB * NN * 128];        // f2 activations packed (hi|lo<<16)
__device__ int   g_cf[2 * BB * CC * 128];
__device__ int   g_cc[2 * BB * CC * 32];
__device__ float g_cf2[2 * BB * CC * 128];
__device__ int   g_net[BB * 128];

// weight fragments (u32 = 2 packed bf16), size = O * Ipad u32 per matrix
__device__ unsigned fr_in [256 * 32];
__device__ unsigned fr_w1 [2][64 * 256];
__device__ unsigned fr_w2 [2][128 * 64];
__device__ unsigned fr_w3 [2][128 * 128];
__device__ unsigned fr_c1 [2][128 * 128];
__device__ unsigned fr_c2 [2][256 * 128];
__device__ unsigned fr_c3 [2][32 * 256];
__device__ unsigned fr_o1 [128 * 256];
__device__ unsigned fr_o2 [128 * 128];

// ---------------- prep: pack all weights into MMA fragment layout ----------------
struct FJobs {
    const float* src[15];
    unsigned*    dst[15];
    int Ireal[15], Ipad[15], O[15], n[15];
};

__global__ void frag_all(FJobs jobs, int total) {
    int t = blockIdx.x * blockDim.x + threadIdx.x;
    if (t >= total) return;
    int j = 0, e = t;
    while (e >= jobs.n[j]) { e -= jobs.n[j]; j++; }
    int Ireal = jobs.Ireal[j], Ipad = jobs.Ipad[j];
    int KS = Ipad / 16;
    int f = e >> 7;                 // fragment index
    int idx = e & 127;              // u32 within fragment
    int lane = idx >> 2, r = idx & 3;
    int term = f & 1, q = f >> 1;
    int ks = q % KS, mt = q / KS;
    int g = lane >> 2, c = lane & 3;
    int row = mt * 16 + g + (r & 1) * 8;
    int k0  = ks * 16 + 2 * c + (r & 2) * 4;
    const float* W = jobs.src[j];
    float v0 = (k0     < Ireal) ? W[row * Ireal + k0]     : 0.0f;
    float v1 = (k0 + 1 < Ireal) ? W[row * Ireal + k0 + 1] : 0.0f;
    unsigned short h0, h1;
    if (term == 0) {
        h0 = __bfloat16_as_ushort(__float2bfloat16(v0));
        h1 = __bfloat16_as_ushort(__float2bfloat16(v1));
    } else {
        __nv_bfloat16 b0 = __float2bfloat16(v0);
        __nv_bfloat16 b1 = __float2bfloat16(v1);
        h0 = __bfloat16_as_ushort(__float2bfloat16(v0 - __bfloat162float(b0)));
        h1 = __bfloat16_as_ushort(__float2bfloat16(v1 - __bfloat162float(b1)));
    }
    jobs.dst[j][e] = (unsigned)h0 | ((unsigned)h1 << 16);
}

__global__ void zero1_k() {
    int t = blockIdx.x * blockDim.x + threadIdx.x;
    if (t < 2 * BB * CC * 128) g_cf[t] = 0;
    if (t < 2 * BB * CC * 32)  g_cc[t] = 0;
}
__global__ void zero2_k() {
    int t = blockIdx.x * blockDim.x + threadIdx.x;
    if (t < BB * 128) g_net[t] = 0;
}

// ---------------- mma + split helpers ----------------
__device__ __forceinline__ void mma16816(float* d, unsigned a0, unsigned a1,
                                         unsigned a2, unsigned a3,
                                         unsigned b0, unsigned b1) {
    asm volatile(
        "mma.sync.aligned.m16n8k16.row.col.f32.bf16.bf16.f32 "
        "{%0,%1,%2,%3}, {%4,%5,%6,%7}, {%8,%9}, {%0,%1,%2,%3};"
        : "+f"(d[0]), "+f"(d[1]), "+f"(d[2]), "+f"(d[3])
        : "r"(a0), "r"(a1), "r"(a2), "r"(a3), "r"(b0), "r"(b1));
}

__device__ __forceinline__ void split_store(float v, __nv_bfloat16* Dhi,
                                            __nv_bfloat16* Dlo, int off) {
    __nv_bfloat16 hb = __float2bfloat16(v);
    __nv_bfloat16 lb = __float2bfloat16(v - __bfloat162float(hb));
    Dhi[off] = hb; Dlo[off] = lb;
}

// ---------------- tensor-core layer: D[O x 64] = W[O x I] * H[I x 64] -------
// 16 warps; warp handles mt = w%MT, n-tiles [ntb, ntb+NTW)
template <int I, int O, bool RELU>
__device__ __forceinline__ void layerMMA(const unsigned* __restrict__ WF,
                                         const float* __restrict__ bias,
                                         const __nv_bfloat16* __restrict__ Shi,
                                         const __nv_bfloat16* __restrict__ Slo,
                                         int sp,
                                         __nv_bfloat16* __restrict__ Dhi,
                                         __nv_bfloat16* __restrict__ Dlo,
                                         int dp, int w, int lane) {
    constexpr int KS = I / 16;
    constexpr int MT = O / 16;
    constexpr int NTW = O / 32;     // n-tiles per warp
    int mt  = (MT == 16) ? w : (w % MT);
    int ntb = (MT == 16) ? 0 : (w / MT) * NTW;
    int g = lane >> 2, c = lane & 3;
    float acc[NTW][4];
    float bv0 = __ldg(bias + mt * 16 + g);
    float bv1 = __ldg(bias + mt * 16 + 8 + g);
#pragma unroll
    for (int n = 0; n < NTW; n++) {
        acc[n][0] = bv0; acc[n][1] = bv0;
        acc[n][2] = bv1; acc[n][3] = bv1;
    }
#pragma unroll 2
    for (int ks = 0; ks < KS; ks++) {
        const uint4* base = reinterpret_cast<const uint4*>(WF) + (mt * KS + ks) * 64 + lane;
        uint4 ah = __ldg(base);
        uint4 al = __ldg(base + 32);
#pragma unroll
        for (int n = 0; n < NTW; n++) {
            int p = (ntb + n) * 8 + g;
            const unsigned* sh = reinterpret_cast<const unsigned*>(Shi + p * sp + ks * 16 + 2 * c);
            const unsigned* sl = reinterpret_cast<const unsigned*>(Slo + p * sp + ks * 16 + 2 * c);
            unsigned bh0 = sh[0], bh1 = sh[4];
            unsigned bl0 = sl[0], bl1 = sl[4];
            mma16816(acc[n], ah.x, ah.y, ah.z, ah.w, bh0, bh1);
            mma16816(acc[n], ah.x, ah.y, ah.z, ah.w, bl0, bl1);
            mma16816(acc[n], al.x, al.y, al.z, al.w, bh0, bh1);
        }
    }
#pragma unroll
    for (int n = 0; n < NTW; n++) {
        int p0 = (ntb + n) * 8 + 2 * c, p1 = p0 + 1;
        int m0 = mt * 16 + g, m1 = m0 + 8;
        float v0 = acc[n][0], v1 = acc[n][1], v2 = acc[n][2], v3 = acc[n][3];
        if (RELU) {
            v0 = fmaxf(v0, 0.f); v1 = fmaxf(v1, 0.f);
            v2 = fmaxf(v2, 0.f); v3 = fmaxf(v3, 0.f);
        }
        split_store(v0, Dhi, Dlo, p0 * dp + m0);
        split_store(v1, Dhi, Dlo, p1 * dp + m0);
        split_store(v2, Dhi, Dlo, p0 * dp + m1);
        split_store(v3, Dhi, Dlo, p1 * dp + m1);
    }
}

// shared layout (bytes)
constexpr int AHI_OFF = 0;
constexpr int ALO_OFF = AHI_OFF + 64 * SPA * 2;        // 34816
constexpr int BHI_OFF = ALO_OFF + 64 * SPA * 2;        // 69632
constexpr int BLO_OFF = BHI_OFF + 64 * SPB * 2;        // 88064
constexpr int CFL_OFF = BLO_OFF + 64 * SPB * 2;        // 106496
constexpr int CCL_OFF = CFL_OFF + CC * 128 * 4;        // 122880
constexpr int CL_OFF  = CCL_OFF + CC * 32 * 4;         // 126976
constexpr int SMEM_BYTES = CL_OFF + 2 * 64 * 4;        // 127488

struct Smem {
    __nv_bfloat16 *Ahi, *Alo, *Bhi, *Blo;
    int *cfl, *ccl, *cl0, *cl1;
};
__device__ __forceinline__ Smem carve(char* sm) {
    Smem s;
    s.Ahi = (__nv_bfloat16*)(sm + AHI_OFF);
    s.Alo = (__nv_bfloat16*)(sm + ALO_OFF);
    s.Bhi = (__nv_bfloat16*)(sm + BHI_OFF);
    s.Blo = (__nv_bfloat16*)(sm + BLO_OFF);
    s.cfl = (int*)(sm + CFL_OFF);
    s.ccl = (int*)(sm + CCL_OFF);
    s.cl0 = (int*)(sm + CL_OFF);
    s.cl1 = s.cl0 + 64;
    return s;
}

// ---------------- kernel A ----------------
__global__ __launch_bounds__(THREADS, 1) void kA(const float* __restrict__ feat,
                                                 const int* __restrict__ clus,
                                                 const float* b_in, const float* b1,
                                                 const float* b2, const float* bc1,
                                                 const float* bc2, const float* bc3) {
    extern __shared__ char smraw[];
    Smem s = carve(smraw);
    int t = threadIdx.x, w = t >> 5, lane = t & 31;
    int b = blockIdx.x >> 9, n0 = (blockIdx.x & 511) * P;

    for (int r = t; r < CC * 128; r += THREADS) s.cfl[r] = 0;
    for (int r = t; r < CC * 32; r += THREADS)  s.ccl[r] = 0;
    if (t < P) s.cl0[t] = clus[b * NN + n0 + t];
    for (int r = t; r < P * 32; r += THREADS) {           // features -> B (pad 22->32)
        int p = r >> 5, k = r & 31;
        float v = (k < KIN) ? feat[(b * NN + n0 + p) * KIN + k] : 0.0f;
        split_store(v, s.Bhi, s.Blo, p * SPB + k);
    }
    __syncthreads();
    layerMMA<32, 256, true>(fr_in, b_in, s.Bhi, s.Blo, SPB, s.Ahi, s.Alo, SPA, w, lane);
    __syncthreads();
    layerMMA<256, 64, true>(fr_w1[0], b1, s.Ahi, s.Alo, SPA, s.Bhi, s.Blo, SPB, w, lane);
    __syncthreads();
    layerMMA<64, 128, true>(fr_w2[0], b2, s.Bhi, s.Blo, SPB, s.Ahi, s.Alo, SPA, w, lane);
    __syncthreads();
    for (int r = t; r < P * 128; r += THREADS) {          // f2 store + segmax cf
        int p = r >> 7, c = r & 127;
        __nv_bfloat16 hi = s.Ahi[p * SPA + c], lo = s.Alo[p * SPA + c];
        g_f2u[(b * NN + n0 + p) * 128 + c] =
            (unsigned)__bfloat16_as_ushort(hi) | ((unsigned)__bfloat16_as_ushort(lo) << 16);
        float v = __bfloat162float(hi) + __bfloat162float(lo);
        atomicMax(&s.cfl[s.cl0[p] * 128 + c], __float_as_int(v));
    }
    layerMMA<128, 128, true>(fr_c1[0], bc1, s.Ahi, s.Alo, SPA, s.Bhi, s.Blo, SPB, w, lane);
    __syncthreads();
    layerMMA<128, 256, true>(fr_c2[0], bc2, s.Bhi, s.Blo, SPB, s.Ahi, s.Alo, SPA, w, lane);
    __syncthreads();
    layerMMA<256, 32, true>(fr_c3[0], bc3, s.Ahi, s.Alo, SPA, s.Bhi, s.Blo, SPB, w, lane);
    __syncthreads();
    for (int r = t; r < P * 32; r += THREADS) {           // segmax cc
        int p = r >> 5, c = r & 31;
        float v = __bfloat162float(s.Bhi[p * SPB + c]) + __bfloat162float(s.Blo[p * SPB + c]);
        atomicMax(&s.ccl[s.cl0[p] * 32 + c], __float_as_int(v));
    }
    __syncthreads();
    for (int r = t; r < CC * 128; r += THREADS) { int v = s.cfl[r]; if (v) atomicMax(&g_cf[b * CC * 128 + r], v); }
    for (int r = t; r < CC * 32; r += THREADS)  { int v = s.ccl[r]; if (v) atomicMax(&g_cc[b * CC * 32 + r], v); }
}

// ---------------- kernel B: per-batch corr matrix + cf @ corr ----------------
__global__ void kB(int it) {
    __shared__ float cm[CC * 32], corr[CC * CC], invn[CC], cfs[CC * 128];
    int b = blockIdx.x, t = threadIdx.x;
    for (int r = t; r < CC * 32; r += TE)  cm[r]  = __int_as_float(g_cc[(it * BB + b) * CC * 32 + r]);
    for (int r = t; r < CC * 128; r += TE) cfs[r] = __int_as_float(g_cf[(it * BB + b) * CC * 128 + r]);
    __syncthreads();
    if (t < CC) {
        float ss = 0.f;
        for (int c = 0; c < 32; c++) { float v = cm[t * 32 + c]; ss += v * v; }
        invn[t] = 1.0f / fmaxf(sqrtf(ss), 1e-12f);
    }
    __syncthreads();
    for (int r = t; r < CC * 32; r += TE) cm[r] *= invn[r >> 5];
    __syncthreads();
    for (int r = t; r < CC * CC; r += TE) {
        int c1 = r >> 5, c2 = r & 31;
        float ss = 0.f;
        for (int c = 0; c < 32; c++) ss += cm[c1 * 32 + c] * cm[c2 * 32 + c];
        corr[r] = ss;
    }
    __syncthreads();
    for (int r = t; r < CC * 128; r += TE) {
        int c2 = r >> 7, ch = r & 127;
        float ss = 0.f;
        for (int c1 = 0; c1 < 32; c1++) ss += cfs[c1 * 128 + ch] * corr[c1 * 32 + c2];
        g_cf2[(it * BB + b) * CC * 128 + r] = ss;
    }
}

// ---------------- kernel C ----------------
__global__ __launch_bounds__(THREADS, 1) void kC(const int* __restrict__ clus,
                                                 const float* b3, const float* b1,
                                                 const float* b2, const float* bc1,
                                                 const float* bc2, const float* bc3) {
    extern __shared__ char smraw[];
    Smem s = carve(smraw);
    int t = threadIdx.x, w = t >> 5, lane = t & 31;
    int b = blockIdx.x >> 9, n0 = (blockIdx.x & 511) * P;

    for (int r = t; r < CC * 128; r += THREADS) s.cfl[r] = 0;
    for (int r = t; r < CC * 32; r += THREADS)  s.ccl[r] = 0;
    if (t < P) {
        s.cl0[t] = clus[b * NN + n0 + t];
        s.cl1[t] = clus[(BB + b) * NN + n0 + t];
    }
    for (int r = t; r < P * 128; r += THREADS) {          // load f2 -> B
        int p = r >> 7, c = r & 127;
        unsigned u = g_f2u[(b * NN + n0 + p) * 128 + c];
        s.Bhi[p * SPB + c] = __ushort_as_bfloat16((unsigned short)(u & 0xFFFF));
        s.Blo[p * SPB + c] = __ushort_as_bfloat16((unsigned short)(u >> 16));
    }
    __syncthreads();
    layerMMA<128, 128, true>(fr_w3[0], b3, s.Bhi, s.Blo, SPB, s.Ahi, s.Alo, SPA, w, lane);
    for (int r = t; r < P * 128; r += THREADS) {          // pool gather -> A ch 128..255
        int p = r >> 7, c = r & 127;
        float v = g_cf2[(b * CC + s.cl0[p]) * 128 + c];
        split_store(v, s.Ahi, s.Alo, p * SPA + 128 + c);
    }
    __syncthreads();
    layerMMA<256, 64, true>(fr_w1[1], b1, s.Ahi, s.Alo, SPA, s.Bhi, s.Blo, SPB, w, lane);
    __syncthreads();
    layerMMA<64, 128, true>(fr_w2[1], b2, s.Bhi, s.Blo, SPB, s.Ahi, s.Alo, SPA, w, lane);
    __syncthreads();
    for (int r = t; r < P * 128; r += THREADS) {          // f2' store + segmax cf
        int p = r >> 7, c = r & 127;
        __nv_bfloat16 hi = s.Ahi[p * SPA + c], lo = s.Alo[p * SPA + c];
        g_f2u[(b * NN + n0 + p) * 128 + c] =
            (unsigned)__bfloat16_as_ushort(hi) | ((unsigned)__bfloat16_as_ushort(lo) << 16);
        float v = __bfloat162float(hi) + __bfloat162float(lo);
        atomicMax(&s.cfl[s.cl1[p] * 128 + c], __float_as_int(v));
    }
    layerMMA<128, 128, true>(fr_c1[1], bc1, s.Ahi, s.Alo, SPA, s.Bhi, s.Blo, SPB, w, lane);
    __syncthreads();
    layerMMA<128, 256, true>(fr_c2[1], bc2, s.Bhi, s.Blo, SPB, s.Ahi, s.Alo, SPA, w, lane);
    __syncthreads();
    layerMMA<256, 32, true>(fr_c3[1], bc3, s.Ahi, s.Alo, SPA, s.Bhi, s.Blo, SPB, w, lane);
    __syncthreads();
    for (int r = t; r < P * 32; r += THREADS) {
        int p = r >> 5, c = r & 31;
        float v = __bfloat162float(s.Bhi[p * SPB + c]) + __bfloat162float(s.Blo[p * SPB + c]);
        atomicMax(&s.ccl[s.cl1[p] * 32 + c], __float_as_int(v));
    }
    __syncthreads();
    for (int r = t; r < CC * 128; r += THREADS) { int v = s.cfl[r]; if (v) atomicMax(&g_cf[(BB + b) * CC * 128 + r], v); }
    for (int r = t; r < CC * 32; r += THREADS)  { int v = s.ccl[r]; if (v) atomicMax(&g_cc[(BB + b) * CC * 32 + r], v); }
}

// ---------------- kernel D ----------------
__global__ __launch_bounds__(THREADS, 1) void kD(const int* __restrict__ clus,
                                                 const float* b3, const float* bo1,
                                                 const float* bo2) {
    extern __shared__ char smraw[];
    Smem s = carve(smraw);
    int t = threadIdx.x, w = t >> 5, lane = t & 31;
    int b = blockIdx.x >> 9, n0 = (blockIdx.x & 511) * P;

    if (t < P) s.cl1[t] = clus[(BB + b) * NN + n0 + t];
    for (int r = t; r < P * 128; r += THREADS) {          // load f2' -> B
        int p = r >> 7, c = r & 127;
        unsigned u = g_f2u[(b * NN + n0 + p) * 128 + c];
        s.Bhi[p * SPB + c] = __ushort_as_bfloat16((unsigned short)(u & 0xFFFF));
        s.Blo[p * SPB + c] = __ushort_as_bfloat16((unsigned short)(u >> 16));
    }
    __syncthreads();
    layerMMA<128, 128, true>(fr_w3[1], b3, s.Bhi, s.Blo, SPB, s.Ahi, s.Alo, SPA, w, lane);
    for (int r = t; r < P * 128; r += THREADS) {          // pool gather -> A ch 128..255
        int p = r >> 7, c = r & 127;
        float v = g_cf2[((BB + b) * CC + s.cl1[p]) * 128 + c];
        split_store(v, s.Ahi, s.Alo, p * SPA + 128 + c);
    }
    __syncthreads();
    layerMMA<256, 128, true>(fr_o1, bo1, s.Ahi, s.Alo, SPA, s.Bhi, s.Blo, SPB, w, lane);
    __syncthreads();
    layerMMA<128, 128, true>(fr_o2, bo2, s.Bhi, s.Blo, SPB, s.Ahi, s.Alo, SPA, w, lane);
    __syncthreads();
    if (t < 128) {
        float m = 0.0f;
        for (int p = 0; p < P; p++) {
            float v = __bfloat162float(s.Ahi[p * SPA + t]) + __bfloat162float(s.Alo[p * SPA + t]);
            m = fmaxf(m, v);
        }
        atomicMax(&g_net[b * 128 + t], __float_as_int(m));
    }
}

// ---------------- kernel E: dense head ----------------
__global__ void kE(const float* __restrict__ dw1, const float* __restrict__ db1,
                   const float* __restrict__ dw2, const float* __restrict__ db2,
                   const float* __restrict__ dw3, const float* __restrict__ db3,
                   float* __restrict__ out) {
    __shared__ float net[BB * 128], l1[BB * 256], l2[BB * 256];
    int t = threadIdx.x;
    for (int r = t; r < BB * 128; r += TE) net[r] = __int_as_float(g_net[r]);
    __syncthreads();
    for (int r = t; r < BB * 256; r += TE) {
        int b = r >> 8, o = r & 255;
        float ss = db1[o];
        for (int i = 0; i < 128; i++) ss = fmaf(net[b * 128 + i], dw1[i * 256 + o], ss);
        l1[r] = ss >= 0.f ? ss : 0.2f * ss;
    }
    __syncthreads();
    for (int r = t; r < BB * 256; r += TE) {
        int b = r >> 8, o = r & 255;
        float ss = db2[o];
        for (int i = 0; i < 256; i++) ss = fmaf(l1[b * 256 + i], dw2[i * 256 + o], ss);
        l2[r] = ss >= 0.f ? ss : 0.2f * ss;
    }
    __syncthreads();
    for (int r = t; r < BB * 40; r += TE) {
        int b = r / 40, o = r % 40;
        float ss = db3[o];
        for (int i = 0; i < 256; i++) ss = fmaf(l2[b * 256 + i], dw3[i * 40 + o], ss);
        out[r] = ss;
    }
}

// ---------------- host launcher ----------------
extern "C" void kernel_launch(void* const* d_in, const int* in_sizes, int n_in,
                              void* d_out, int out_size) {
    const float* feat = (const float*)d_in[0];
    const int*   clus = (const int*)d_in[1];
    const float* w_in = (const float*)d_in[2];
    const float* b_in = (const float*)d_in[3];
    const float* w1   = (const float*)d_in[4];
    const float* b1   = (const float*)d_in[5];
    const float* w2   = (const float*)d_in[6];
    const float* b2   = (const float*)d_in[7];
    const float* w3   = (const float*)d_in[8];
    const float* b3   = (const float*)d_in[9];
    const float* wc1  = (const float*)d_in[10];
    const float* bc1  = (const float*)d_in[11];
    const float* wc2  = (const float*)d_in[12];
    const float* bc2  = (const float*)d_in[13];
    const float* wc3  = (const float*)d_in[14];
    const float* bc3  = (const float*)d_in[15];
    const float* wo1  = (const float*)d_in[16];
    const float* bo1  = (const float*)d_in[17];
    const float* wo2  = (const float*)d_in[18];
    const float* bo2  = (const float*)d_in[19];
    const float* dw1  = (const float*)d_in[20];
    const float* db1  = (const float*)d_in[21];
    const float* dw2  = (const float*)d_in[22];
    const float* db2  = (const float*)d_in[23];
    const float* dw3  = (const float*)d_in[24];
    const float* db3  = (const float*)d_in[25];

    cudaFuncSetAttribute(kA, cudaFuncAttributeMaxDynamicSharedMemorySize, SMEM_BYTES);
    cudaFuncSetAttribute(kC, cudaFuncAttributeMaxDynamicSharedMemorySize, SMEM_BYTES);
    cudaFuncSetAttribute(kD, cudaFuncAttributeMaxDynamicSharedMemorySize, SMEM_BYTES);

    unsigned *p_in, *p_w1, *p_w2, *p_w3, *p_c1, *p_c2, *p_c3, *p_o1, *p_o2;
    cudaGetSymbolAddress((void**)&p_in, fr_in);
    cudaGetSymbolAddress((void**)&p_w1, fr_w1);
    cudaGetSymbolAddress((void**)&p_w2, fr_w2);
    cudaGetSymbolAddress((void**)&p_w3, fr_w3);
    cudaGetSymbolAddress((void**)&p_c1, fr_c1);
    cudaGetSymbolAddress((void**)&p_c2, fr_c2);
    cudaGetSymbolAddress((void**)&p_c3, fr_c3);
    cudaGetSymbolAddress((void**)&p_o1, fr_o1);
    cudaGetSymbolAddress((void**)&p_o2, fr_o2);

    FJobs jobs;
    int idx = 0, total = 0;
    auto add = [&](const float* s, unsigned* d, int Ireal, int Ipad, int O) {
        jobs.src[idx] = s; jobs.dst[idx] = d;
        jobs.Ireal[idx] = Ireal; jobs.Ipad[idx] = Ipad; jobs.O[idx] = O;
        jobs.n[idx] = O * Ipad;
        total += O * Ipad; idx++;
    };
    add(w_in, p_in, KIN, 32, 256);
    for (int it = 0; it < 2; it++) {
        add(w1  + it * 64 * 256,  p_w1 + it * 64 * 256,  256, 256, 64);
        add(w2  + it * 128 * 64,  p_w2 + it * 128 * 64,  64, 64, 128);
        add(w3  + it * 128 * 128, p_w3 + it * 128 * 128, 128, 128, 128);
        add(wc1 + it * 128 * 128, p_c1 + it * 128 * 128, 128, 128, 128);
        add(wc2 + it * 256 * 128, p_c2 + it * 256 * 128, 128, 128, 256);
        add(wc3 + it * 32 * 256,  p_c3 + it * 32 * 256,  256, 256, 32);
    }
    add(wo1, p_o1, 256, 256, 128);
    add(wo2, p_o2, 128, 128, 128);

    // launch order chosen so ncu (-s 5 -c 1) captures kC (6th launch)
    frag_all<<<(total + 255) / 256, 256>>>(jobs, total);  // 1
    zero1_k<<<256, 256>>>();                              // 2
    zero2_k<<<4, 256>>>();                                // 3

    int grid = BB * (NN / P);   // 4096
    kA<<<grid, THREADS, SMEM_BYTES>>>(feat, clus, b_in, b1, b2, bc1, bc2, bc3);   // 4
    kB<<<BB, TE>>>(0);                                                            // 5
    kC<<<grid, THREADS, SMEM_BYTES>>>(clus, b3, b1 + 64, b2 + 128, bc1 + 128, bc2 + 256, bc3 + 32); // 6 <- ncu
    kB<<<BB, TE>>>(1);
    kD<<<grid, THREADS, SMEM_BYTES>>>(clus, b3 + 128, bo1, bo2);
    kE<<<1, TE>>>(dw1, db1, dw2, db2, dw3, db3, (float*)d_out);
}

// round 6
// speedup vs baseline: 4.3603x; 1.0860x over previous
#include <cuda_runtime.h>
#include <cuda_bf16.h>

#define BB 8
#define NN 32768
#define CC 32
#define KIN 22

constexpr int P  = 64;        // points per block
constexpr int SP = 72;        // channel-row pitch in halves (144B, conflict-free for ldmatrix)
constexpr int SPW = SP / 2;   // pitch in u32 words (36)
constexpr int THREADS = 512;  // 16 warps
constexpr int TE = 256;

// ---------------- device scratch ----------------
__device__ unsigned g_f2h[BB * 128 * NN / 2];    // f2 hi plane, channel-major u32 words (2 pts)
__device__ unsigned g_f2l[BB * 128 * NN / 2];    // f2 lo plane
__device__ int   g_cf[2 * BB * CC * 128];
__device__ int   g_cc[2 * BB * CC * 32];
__device__ float g_cf2[2 * BB * CC * 128];
__device__ int   g_net[BB * 128];

// weight fragments (u32 = 2 packed bf16), size = O * Ipad u32 per matrix
__device__ unsigned fr_in [256 * 32];
__device__ unsigned fr_w1 [2][64 * 256];
__device__ unsigned fr_w2 [2][128 * 64];
__device__ unsigned fr_w3 [2][128 * 128];
__device__ unsigned fr_c1 [2][128 * 128];
__device__ unsigned fr_c2 [2][256 * 128];
__device__ unsigned fr_c3 [2][32 * 256];
__device__ unsigned fr_o1 [128 * 256];
__device__ unsigned fr_o2 [128 * 128];

// ---------------- prep: pack all weights into MMA fragment layout ----------------
struct FJobs {
    const float* src[15];
    unsigned*    dst[15];
    int Ireal[15], Ipad[15], O[15], n[15];
};

__global__ void frag_all(FJobs jobs, int total) {
    int t = blockIdx.x * blockDim.x + threadIdx.x;
    if (t >= total) return;
    int j = 0, e = t;
    while (e >= jobs.n[j]) { e -= jobs.n[j]; j++; }
    int Ireal = jobs.Ireal[j], Ipad = jobs.Ipad[j];
    int KS = Ipad / 16;
    int f = e >> 7;                 // fragment index
    int idx = e & 127;              // u32 within fragment
    int lane = idx >> 2, r = idx & 3;
    int term = f & 1, q = f >> 1;
    int ks = q % KS, mt = q / KS;
    int g = lane >> 2, c = lane & 3;
    int row = mt * 16 + g + (r & 1) * 8;
    int k0  = ks * 16 + 2 * c + (r & 2) * 4;
    const float* W = jobs.src[j];
    float v0 = (k0     < Ireal) ? W[row * Ireal + k0]     : 0.0f;
    float v1 = (k0 + 1 < Ireal) ? W[row * Ireal + k0 + 1] : 0.0f;
    unsigned short h0, h1;
    if (term == 0) {
        h0 = __bfloat16_as_ushort(__float2bfloat16(v0));
        h1 = __bfloat16_as_ushort(__float2bfloat16(v1));
    } else {
        __nv_bfloat16 b0 = __float2bfloat16(v0);
        __nv_bfloat16 b1 = __float2bfloat16(v1);
        h0 = __bfloat16_as_ushort(__float2bfloat16(v0 - __bfloat162float(b0)));
        h1 = __bfloat16_as_ushort(__float2bfloat16(v1 - __bfloat162float(b1)));
    }
    jobs.dst[j][e] = (unsigned)h0 | ((unsigned)h1 << 16);
}

__global__ void zero1_k() {
    int t = blockIdx.x * blockDim.x + threadIdx.x;
    if (t < 2 * BB * CC * 128) g_cf[t] = 0;
    if (t < 2 * BB * CC * 32)  g_cc[t] = 0;
}
__global__ void zero2_k() {
    int t = blockIdx.x * blockDim.x + threadIdx.x;
    if (t < BB * 128) g_net[t] = 0;
}

// ---------------- asm helpers ----------------
__device__ __forceinline__ unsigned sptr(const void* p) {
    return (unsigned)__cvta_generic_to_shared(p);
}
__device__ __forceinline__ void mma16816(float* d, unsigned a0, unsigned a1,
                                         unsigned a2, unsigned a3,
                                         unsigned b0, unsigned b1) {
    asm volatile(
        "mma.sync.aligned.m16n8k16.row.col.f32.bf16.bf16.f32 "
        "{%0,%1,%2,%3}, {%4,%5,%6,%7}, {%8,%9}, {%0,%1,%2,%3};"
        : "+f"(d[0]), "+f"(d[1]), "+f"(d[2]), "+f"(d[3])
        : "r"(a0), "r"(a1), "r"(a2), "r"(a3), "r"(b0), "r"(b1));
}
__device__ __forceinline__ void ldsm_x4_t(unsigned addr, unsigned& r0, unsigned& r1,
                                          unsigned& r2, unsigned& r3) {
    asm volatile("ldmatrix.sync.aligned.m8n8.x4.trans.shared.b16 {%0,%1,%2,%3}, [%4];"
                 : "=r"(r0), "=r"(r1), "=r"(r2), "=r"(r3) : "r"(addr));
}
__device__ __forceinline__ void ldsm_x2_t(unsigned addr, unsigned& r0, unsigned& r1) {
    asm volatile("ldmatrix.sync.aligned.m8n8.x2.trans.shared.b16 {%0,%1}, [%2];"
                 : "=r"(r0), "=r"(r1) : "r"(addr));
}
__device__ __forceinline__ void stsm_x2(unsigned addr, unsigned r0, unsigned r1) {
    asm volatile("stmatrix.sync.aligned.m8n8.x2.shared.b16 [%0], {%1,%2};"
                 :: "r"(addr), "r"(r0), "r"(r1));
}
__device__ __forceinline__ unsigned pack_bf(__nv_bfloat16 a, __nv_bfloat16 b) {
    return (unsigned)__bfloat16_as_ushort(a) | ((unsigned)__bfloat16_as_ushort(b) << 16);
}
__device__ __forceinline__ float bflo(unsigned u) {
    return __bfloat162float(__ushort_as_bfloat16((unsigned short)(u & 0xFFFF)));
}
__device__ __forceinline__ float bfhi(unsigned u) {
    return __bfloat162float(__ushort_as_bfloat16((unsigned short)(u >> 16)));
}
// split two floats into packed hi-word and lo-word
__device__ __forceinline__ void split2(float v0, float v1, unsigned& hw, unsigned& lw) {
    __nv_bfloat16 h0 = __float2bfloat16(v0), h1 = __float2bfloat16(v1);
    float r0 = v0 - __bfloat162float(h0), r1 = v1 - __bfloat162float(h1);
    hw = pack_bf(h0, h1);
    lw = pack_bf(__float2bfloat16(r0), __float2bfloat16(r1));
}

// ---------------- tensor-core layer: D[O x 64] = W[O x I] * H[I x 64] -------
// channel-major smem (row = channel, SP halves pitch). ldmatrix.trans B, stmatrix D.
template <int I, int O, bool RELU>
__device__ __forceinline__ void layerMMA(const unsigned* __restrict__ WF,
                                         const float* __restrict__ bias,
                                         const __nv_bfloat16* __restrict__ Shi,
                                         const __nv_bfloat16* __restrict__ Slo,
                                         __nv_bfloat16* __restrict__ Dhi,
                                         __nv_bfloat16* __restrict__ Dlo,
                                         int w, int lane) {
    constexpr int KS  = I / 16;
    constexpr int MT  = O / 16;
    constexpr int NTW = MT / 2;       // n-tiles per warp (>=1)
    int mt  = w % MT;
    int ntb = (w / MT) * (NTW ? NTW : 1);
    int g = lane >> 2;
    float acc[(NTW ? NTW : 1)][4];
    float bv0 = __ldg(bias + mt * 16 + g);
    float bv1 = __ldg(bias + mt * 16 + 8 + g);
#pragma unroll
    for (int n = 0; n < (NTW ? NTW : 1); n++) {
        acc[n][0] = bv0; acc[n][1] = bv0;
        acc[n][2] = bv1; acc[n][3] = bv1;
    }
    // ldmatrix per-lane row addressing
    int krow  = ((lane >> 3) & 1) * 8 + (lane & 7);
    int ntoff = lane >> 4;            // used by x4 path
    unsigned baseH = sptr(Shi) + krow * (SP * 2);
    unsigned baseL = sptr(Slo) + krow * (SP * 2);
#pragma unroll 2
    for (int ks = 0; ks < KS; ks++) {
        const uint4* ab = reinterpret_cast<const uint4*>(WF) + (mt * KS + ks) * 64 + lane;
        uint4 ah = __ldg(ab);
        uint4 al = __ldg(ab + 32);
        unsigned koff = ks * (16 * SP * 2);
        if constexpr (NTW <= 1) {
            unsigned bh0, bh1, bl0, bl1;
            unsigned col = ntb * 16;
            ldsm_x2_t(baseH + koff + col, bh0, bh1);
            ldsm_x2_t(baseL + koff + col, bl0, bl1);
            mma16816(acc[0], ah.x, ah.y, ah.z, ah.w, bh0, bh1);
            mma16816(acc[0], ah.x, ah.y, ah.z, ah.w, bl0, bl1);
            mma16816(acc[0], al.x, al.y, al.z, al.w, bh0, bh1);
        } else {
#pragma unroll
            for (int np = 0; np < NTW / 2; np++) {
                unsigned col = (ntb + 2 * np + ntoff) * 16;
                unsigned bh0, bh1, bh2, bh3, bl0, bl1, bl2, bl3;
                ldsm_x4_t(baseH + koff + col, bh0, bh1, bh2, bh3);
                ldsm_x4_t(baseL + koff + col, bl0, bl1, bl2, bl3);
                mma16816(acc[2 * np],     ah.x, ah.y, ah.z, ah.w, bh0, bh1);
                mma16816(acc[2 * np],     ah.x, ah.y, ah.z, ah.w, bl0, bl1);
                mma16816(acc[2 * np],     al.x, al.y, al.z, al.w, bh0, bh1);
                mma16816(acc[2 * np + 1], ah.x, ah.y, ah.z, ah.w, bh2, bh3);
                mma16816(acc[2 * np + 1], ah.x, ah.y, ah.z, ah.w, bl2, bl3);
                mma16816(acc[2 * np + 1], al.x, al.y, al.z, al.w, bh2, bh3);
            }
        }
    }
    // stores via stmatrix: tiles rows = channels, cols = points
    int sl = lane & 15;
    int mrow = mt * 16 + (sl >> 3) * 8 + (sl & 7);
    unsigned stH = sptr(Dhi) + mrow * (SP * 2);
    unsigned stL = sptr(Dlo) + mrow * (SP * 2);
#pragma unroll
    for (int n = 0; n < (NTW ? NTW : 1); n++) {
        int nt = ntb + n;
        float d0 = acc[n][0], d1 = acc[n][1], d2 = acc[n][2], d3 = acc[n][3];
        if (RELU) {
            d0 = fmaxf(d0, 0.f); d1 = fmaxf(d1, 0.f);
            d2 = fmaxf(d2, 0.f); d3 = fmaxf(d3, 0.f);
        }
        unsigned h01, l01, h23, l23;
        split2(d0, d1, h01, l01);
        split2(d2, d3, h23, l23);
        stsm_x2(stH + nt * 16, h01, h23);
        stsm_x2(stL + nt * 16, l01, l23);
    }
}

// shared layout (bytes)
constexpr int AHI_OFF = 0;
constexpr int ALO_OFF = AHI_OFF + 256 * SP * 2;        // 36864
constexpr int BHI_OFF = ALO_OFF + 256 * SP * 2;        // 73728
constexpr int BLO_OFF = BHI_OFF + 128 * SP * 2;        // 92160
constexpr int CFL_OFF = BLO_OFF + 128 * SP * 2;        // 110592
constexpr int CCL_OFF = CFL_OFF + CC * 128 * 4;        // 126976
constexpr int CL_OFF  = CCL_OFF + CC * 32 * 4;         // 131072
constexpr int SMEM_BYTES = CL_OFF + 2 * 64 * 4;        // 131584

struct Smem {
    __nv_bfloat16 *Ahi, *Alo, *Bhi, *Blo;
    unsigned *AHw, *ALw, *BHw, *BLw;
    int *cfl, *ccl, *cl0, *cl1;
};
__device__ __forceinline__ Smem carve(char* sm) {
    Smem s;
    s.Ahi = (__nv_bfloat16*)(sm + AHI_OFF);
    s.Alo = (__nv_bfloat16*)(sm + ALO_OFF);
    s.Bhi = (__nv_bfloat16*)(sm + BHI_OFF);
    s.Blo = (__nv_bfloat16*)(sm + BLO_OFF);
    s.AHw = (unsigned*)s.Ahi; s.ALw = (unsigned*)s.Alo;
    s.BHw = (unsigned*)s.Bhi; s.BLw = (unsigned*)s.Blo;
    s.cfl = (int*)(sm + CFL_OFF);
    s.ccl = (int*)(sm + CCL_OFF);
    s.cl0 = (int*)(sm + CL_OFF);
    s.cl1 = s.cl0 + 64;
    return s;
}

// ---------------- kernel A ----------------
__global__ __launch_bounds__(THREADS, 1) void kA(const float* __restrict__ feat,
                                                 const int* __restrict__ clus,
                                                 const float* b_in, const float* b1,
                                                 const float* b2, const float* bc1,
                                                 const float* bc2, const float* bc3) {
    extern __shared__ char smraw[];
    Smem s = carve(smraw);
    int t = threadIdx.x, w = t >> 5, lane = t & 31;
    int b = blockIdx.x >> 9, n0 = (blockIdx.x & 511) * P;
    int n02 = (blockIdx.x & 511) * (P / 2);

    for (int r = t; r < CC * 128; r += THREADS) s.cfl[r] = 0;
    for (int r = t; r < CC * 32; r += THREADS)  s.ccl[r] = 0;
    if (t < P) s.cl0[t] = clus[b * NN + n0 + t];
    for (int r = t; r < 32 * 32; r += THREADS) {          // features (pad 22->32), pairs
        int pair = r & 31, k = r >> 5;
        float v0 = (k < KIN) ? feat[(b * NN + n0 + 2 * pair) * KIN + k] : 0.0f;
        float v1 = (k < KIN) ? feat[(b * NN + n0 + 2 * pair + 1) * KIN + k] : 0.0f;
        unsigned hw, lw; split2(v0, v1, hw, lw);
        s.BHw[k * SPW + pair] = hw; s.BLw[k * SPW + pair] = lw;
    }
    __syncthreads();
    layerMMA<32, 256, true>(fr_in, b_in, s.Bhi, s.Blo, s.Ahi, s.Alo, w, lane);
    __syncthreads();
    layerMMA<256, 64, true>(fr_w1[0], b1, s.Ahi, s.Alo, s.Bhi, s.Blo, w, lane);
    __syncthreads();
    layerMMA<64, 128, true>(fr_w2[0], b2, s.Bhi, s.Blo, s.Ahi, s.Alo, w, lane);
    __syncthreads();
    for (int r = t; r < 128 * 32; r += THREADS) {         // f2 store + segmax cf
        int pair = r & 31, c = r >> 5;
        unsigned h2 = s.AHw[c * SPW + pair], l2 = s.ALw[c * SPW + pair];
        int gi = (b * 128 + c) * (NN / 2) + n02 + pair;
        g_f2h[gi] = h2; g_f2l[gi] = l2;
        float v0 = bflo(h2) + bflo(l2);
        float v1 = bfhi(h2) + bfhi(l2);
        atomicMax(&s.cfl[s.cl0[2 * pair]     * 128 + c], __float_as_int(v0));
        atomicMax(&s.cfl[s.cl0[2 * pair + 1] * 128 + c], __float_as_int(v1));
    }
    layerMMA<128, 128, true>(fr_c1[0], bc1, s.Ahi, s.Alo, s.Bhi, s.Blo, w, lane);
    __syncthreads();
    layerMMA<128, 256, true>(fr_c2[0], bc2, s.Bhi, s.Blo, s.Ahi, s.Alo, w, lane);
    __syncthreads();
    layerMMA<256, 32, true>(fr_c3[0], bc3, s.Ahi, s.Alo, s.Bhi, s.Blo, w, lane);
    __syncthreads();
    for (int r = t; r < 32 * 32; r += THREADS) {          // segmax cc
        int pair = r & 31, c = r >> 5;
        unsigned h2 = s.BHw[c * SPW + pair], l2 = s.BLw[c * SPW + pair];
        float v0 = bflo(h2) + bflo(l2);
        float v1 = bfhi(h2) + bfhi(l2);
        atomicMax(&s.ccl[s.cl0[2 * pair]     * 32 + c], __float_as_int(v0));
        atomicMax(&s.ccl[s.cl0[2 * pair + 1] * 32 + c], __float_as_int(v1));
    }
    __syncthreads();
    for (int r = t; r < CC * 128; r += THREADS) { int v = s.cfl[r]; if (v) atomicMax(&g_cf[b * CC * 128 + r], v); }
    for (int r = t; r < CC * 32; r += THREADS)  { int v = s.ccl[r]; if (v) atomicMax(&g_cc[b * CC * 32 + r], v); }
}

// ---------------- kernel B: per-batch corr matrix + cf @ corr ----------------
__global__ void kB(int it) {
    __shared__ float cm[CC * 32], corr[CC * CC], invn[CC], cfs[CC * 128];
    int b = blockIdx.x, t = threadIdx.x;
    for (int r = t; r < CC * 32; r += TE)  cm[r]  = __int_as_float(g_cc[(it * BB + b) * CC * 32 + r]);
    for (int r = t; r < CC * 128; r += TE) cfs[r] = __int_as_float(g_cf[(it * BB + b) * CC * 128 + r]);
    __syncthreads();
    if (t < CC) {
        float ss = 0.f;
        for (int c = 0; c < 32; c++) { float v = cm[t * 32 + c]; ss += v * v; }
        invn[t] = 1.0f / fmaxf(sqrtf(ss), 1e-12f);
    }
    __syncthreads();
    for (int r = t; r < CC * 32; r += TE) cm[r] *= invn[r >> 5];
    __syncthreads();
    for (int r = t; r < CC * CC; r += TE) {
        int c1 = r >> 5, c2 = r & 31;
        float ss = 0.f;
        for (int c = 0; c < 32; c++) ss += cm[c1 * 32 + c] * cm[c2 * 32 + c];
        corr[r] = ss;
    }
    __syncthreads();
    for (int r = t; r < CC * 128; r += TE) {
        int c2 = r >> 7, ch = r & 127;
        float ss = 0.f;
        for (int c1 = 0; c1 < 32; c1++) ss += cfs[c1 * 128 + ch] * corr[c1 * 32 + c2];
        g_cf2[(it * BB + b) * CC * 128 + r] = ss;
    }
}

// ---------------- kernel C ----------------
__global__ __launch_bounds__(THREADS, 1) void kC(const int* __restrict__ clus,
                                                 const float* b3, const float* b1,
                                                 const float* b2, const float* bc1,
                                                 const float* bc2, const float* bc3) {
    extern __shared__ char smraw[];
    Smem s = carve(smraw);
    int t = threadIdx.x, w = t >> 5, lane = t & 31;
    int b = blockIdx.x >> 9, n0 = (blockIdx.x & 511) * P;
    int n02 = (blockIdx.x & 511) * (P / 2);

    for (int r = t; r < CC * 128; r += THREADS) s.cfl[r] = 0;
    for (int r = t; r < CC * 32; r += THREADS)  s.ccl[r] = 0;
    if (t < P) {
        s.cl0[t] = clus[b * NN + n0 + t];
        s.cl1[t] = clus[(BB + b) * NN + n0 + t];
    }
    for (int r = t; r < 128 * 32; r += THREADS) {         // load f2 -> B
        int pair = r & 31, c = r >> 5;
        int gi = (b * 128 + c) * (NN / 2) + n02 + pair;
        s.BHw[c * SPW + pair] = g_f2h[gi];
        s.BLw[c * SPW + pair] = g_f2l[gi];
    }
    __syncthreads();
    layerMMA<128, 128, true>(fr_w3[0], b3, s.Bhi, s.Blo, s.Ahi, s.Alo, w, lane);
    for (int r = t; r < 128 * 32; r += THREADS) {         // pool gather -> A ch 128..255
        int pair = r & 31, c = r >> 5;
        float v0 = g_cf2[(b * CC + s.cl0[2 * pair])     * 128 + c];
        float v1 = g_cf2[(b * CC + s.cl0[2 * pair + 1]) * 128 + c];
        unsigned hw, lw; split2(v0, v1, hw, lw);
        s.AHw[(128 + c) * SPW + pair] = hw;
        s.ALw[(128 + c) * SPW + pair] = lw;
    }
    __syncthreads();
    layerMMA<256, 64, true>(fr_w1[1], b1, s.Ahi, s.Alo, s.Bhi, s.Blo, w, lane);
    __syncthreads();
    layerMMA<64, 128, true>(fr_w2[1], b2, s.Bhi, s.Blo, s.Ahi, s.Alo, w, lane);
    __syncthreads();
    for (int r = t; r < 128 * 32; r += THREADS) {         // f2' store + segmax cf
        int pair = r & 31, c = r >> 5;
        unsigned h2 = s.AHw[c * SPW + pair], l2 = s.ALw[c * SPW + pair];
        int gi = (b * 128 + c) * (NN / 2) + n02 + pair;
        g_f2h[gi] = h2; g_f2l[gi] = l2;
        float v0 = bflo(h2) + bflo(l2);
        float v1 = bfhi(h2) + bfhi(l2);
        atomicMax(&s.cfl[s.cl1[2 * pair]     * 128 + c], __float_as_int(v0));
        atomicMax(&s.cfl[s.cl1[2 * pair + 1] * 128 + c], __float_as_int(v1));
    }
    layerMMA<128, 128, true>(fr_c1[1], bc1, s.Ahi, s.Alo, s.Bhi, s.Blo, w, lane);
    __syncthreads();
    layerMMA<128, 256, true>(fr_c2[1], bc2, s.Bhi, s.Blo, s.Ahi, s.Alo, w, lane);
    __syncthreads();
    layerMMA<256, 32, true>(fr_c3[1], bc3, s.Ahi, s.Alo, s.Bhi, s.Blo, w, lane);
    __syncthreads();
    for (int r = t; r < 32 * 32; r += THREADS) {
        int pair = r & 31, c = r >> 5;
        unsigned h2 = s.BHw[c * SPW + pair], l2 = s.BLw[c * SPW + pair];
        float v0 = bflo(h2) + bflo(l2);
        float v1 = bfhi(h2) + bfhi(l2);
        atomicMax(&s.ccl[s.cl1[2 * pair]     * 32 + c], __float_as_int(v0));
        atomicMax(&s.ccl[s.cl1[2 * pair + 1] * 32 + c], __float_as_int(v1));
    }
    __syncthreads();
    for (int r = t; r < CC * 128; r += THREADS) { int v = s.cfl[r]; if (v) atomicMax(&g_cf[(BB + b) * CC * 128 + r], v); }
    for (int r = t; r < CC * 32; r += THREADS)  { int v = s.ccl[r]; if (v) atomicMax(&g_cc[(BB + b) * CC * 32 + r], v); }
}

// ---------------- kernel D ----------------
__global__ __launch_bounds__(THREADS, 1) void kD(const int* __restrict__ clus,
                                                 const float* b3, const float* bo1,
                                                 const float* bo2) {
    extern __shared__ char smraw[];
    Smem s = carve(smraw);
    int t = threadIdx.x, w = t >> 5, lane = t & 31;
    int b = blockIdx.x >> 9, n0 = (blockIdx.x & 511) * P;
    int n02 = (blockIdx.x & 511) * (P / 2);

    if (t < P) s.cl1[t] = clus[(BB + b) * NN + n0 + t];
    for (int r = t; r < 128 * 32; r += THREADS) {         // load f2' -> B
        int pair = r & 31, c = r >> 5;
        int gi = (b * 128 + c) * (NN / 2) + n02 + pair;
        s.BHw[c * SPW + pair] = g_f2h[gi];
        s.BLw[c * SPW + pair] = g_f2l[gi];
    }
    __syncthreads();
    layerMMA<128, 128, true>(fr_w3[1], b3, s.Bhi, s.Blo, s.Ahi, s.Alo, w, lane);
    for (int r = t; r < 128 * 32; r += THREADS) {         // pool gather -> A ch 128..255
        int pair = r & 31, c = r >> 5;
        float v0 = g_cf2[((BB + b) * CC + s.cl1[2 * pair])     * 128 + c];
        float v1 = g_cf2[((BB + b) * CC + s.cl1[2 * pair + 1]) * 128 + c];
        unsigned hw, lw; split2(v0, v1, hw, lw);
        s.AHw[(128 + c) * SPW + pair] = hw;
        s.ALw[(128 + c) * SPW + pair] = lw;
    }
    __syncthreads();
    layerMMA<256, 128, true>(fr_o1, bo1, s.Ahi, s.Alo, s.Bhi, s.Blo, w, lane);
    __syncthreads();
    layerMMA<128, 128, true>(fr_o2, bo2, s.Bhi, s.Blo, s.Ahi, s.Alo, w, lane);
    __syncthreads();
    if (t < 128) {
        float m = 0.0f;
        for (int pair = 0; pair < 32; pair++) {
            unsigned h2 = s.AHw[t * SPW + pair], l2 = s.ALw[t * SPW + pair];
            m = fmaxf(m, fmaxf(bflo(h2) + bflo(l2), bfhi(h2) + bfhi(l2)));
        }
        atomicMax(&g_net[b * 128 + t], __float_as_int(m));
    }
}

// ---------------- kernel E: dense head ----------------
__global__ void kE(const float* __restrict__ dw1, const float* __restrict__ db1,
                   const float* __restrict__ dw2, const float* __restrict__ db2,
                   const float* __restrict__ dw3, const float* __restrict__ db3,
                   float* __restrict__ out) {
    __shared__ float net[BB * 128], l1[BB * 256], l2[BB * 256];
    int t = threadIdx.x;
    for (int r = t; r < BB * 128; r += TE) net[r] = __int_as_float(g_net[r]);
    __syncthreads();
    for (int r = t; r < BB * 256; r += TE) {
        int b = r >> 8, o = r & 255;
        float ss = db1[o];
        for (int i = 0; i < 128; i++) ss = fmaf(net[b * 128 + i], dw1[i * 256 + o], ss);
        l1[r] = ss >= 0.f ? ss : 0.2f * ss;
    }
    __syncthreads();
    for (int r = t; r < BB * 256; r += TE) {
        int b = r >> 8, o = r & 255;
        float ss = db2[o];
        for (int i = 0; i < 256; i++) ss = fmaf(l1[b * 256 + i], dw2[i * 256 + o], ss);
        l2[r] = ss >= 0.f ? ss : 0.2f * ss;
    }
    __syncthreads();
    for (int r = t; r < BB * 40; r += TE) {
        int b = r / 40, o = r % 40;
        float ss = db3[o];
        for (int i = 0; i < 256; i++) ss = fmaf(l2[b * 256 + i], dw3[i * 40 + o], ss);
        out[r] = ss;
    }
}

// ---------------- host launcher ----------------
extern "C" void kernel_launch(void* const* d_in, const int* in_sizes, int n_in,
                              void* d_out, int out_size) {
    const float* feat = (const float*)d_in[0];
    const int*   clus = (const int*)d_in[1];
    const float* w_in = (const float*)d_in[2];
    const float* b_in = (const float*)d_in[3];
    const float* w1   = (const float*)d_in[4];
    const float* b1   = (const float*)d_in[5];
    const float* w2   = (const float*)d_in[6];
    const float* b2   = (const float*)d_in[7];
    const float* w3   = (const float*)d_in[8];
    const float* b3   = (const float*)d_in[9];
    const float* wc1  = (const float*)d_in[10];
    const float* bc1  = (const float*)d_in[11];
    const float* wc2  = (const float*)d_in[12];
    const float* bc2  = (const float*)d_in[13];
    const float* wc3  = (const float*)d_in[14];
    const float* bc3  = (const float*)d_in[15];
    const float* wo1  = (const float*)d_in[16];
    const float* bo1  = (const float*)d_in[17];
    const float* wo2  = (const float*)d_in[18];
    const float* bo2  = (const float*)d_in[19];
    const float* dw1  = (const float*)d_in[20];
    const float* db1  = (const float*)d_in[21];
    const float* dw2  = (const float*)d_in[22];
    const float* db2  = (const float*)d_in[23];
    const float* dw3  = (const float*)d_in[24];
    const float* db3  = (const float*)d_in[25];

    cudaFuncSetAttribute(kA, cudaFuncAttributeMaxDynamicSharedMemorySize, SMEM_BYTES);
    cudaFuncSetAttribute(kC, cudaFuncAttributeMaxDynamicSharedMemorySize, SMEM_BYTES);
    cudaFuncSetAttribute(kD, cudaFuncAttributeMaxDynamicSharedMemorySize, SMEM_BYTES);

    unsigned *p_in, *p_w1, *p_w2, *p_w3, *p_c1, *p_c2, *p_c3, *p_o1, *p_o2;
    cudaGetSymbolAddress((void**)&p_in, fr_in);
    cudaGetSymbolAddress((void**)&p_w1, fr_w1);
    cudaGetSymbolAddress((void**)&p_w2, fr_w2);
    cudaGetSymbolAddress((void**)&p_w3, fr_w3);
    cudaGetSymbolAddress((void**)&p_c1, fr_c1);
    cudaGetSymbolAddress((void**)&p_c2, fr_c2);
    cudaGetSymbolAddress((void**)&p_c3, fr_c3);
    cudaGetSymbolAddress((void**)&p_o1, fr_o1);
    cudaGetSymbolAddress((void**)&p_o2, fr_o2);

    FJobs jobs;
    int idx = 0, total = 0;
    auto add = [&](const float* s, unsigned* d, int Ireal, int Ipad, int O) {
        jobs.src[idx] = s; jobs.dst[idx] = d;
        jobs.Ireal[idx] = Ireal; jobs.Ipad[idx] = Ipad; jobs.O[idx] = O;
        jobs.n[idx] = O * Ipad;
        total += O * Ipad; idx++;
    };
    add(w_in, p_in, KIN, 32, 256);
    for (int it = 0; it < 2; it++) {
        add(w1  + it * 64 * 256,  p_w1 + it * 64 * 256,  256, 256, 64);
        add(w2  + it * 128 * 64,  p_w2 + it * 128 * 64,  64, 64, 128);
        add(w3  + it * 128 * 128, p_w3 + it * 128 * 128, 128, 128, 128);
        add(wc1 + it * 128 * 128, p_c1 + it * 128 * 128, 128, 128, 128);
        add(wc2 + it * 256 * 128, p_c2 + it * 256 * 128, 128, 128, 256);
        add(wc3 + it * 32 * 256,  p_c3 + it * 32 * 256,  256, 256, 32);
    }
    add(wo1, p_o1, 256, 256, 128);
    add(wo2, p_o2, 128, 128, 128);

    // launch order chosen so ncu (-s 5 -c 1) captures kC (6th launch)
    frag_all<<<(total + 255) / 256, 256>>>(jobs, total);  // 1
    zero1_k<<<256, 256>>>();                              // 2
    zero2_k<<<4, 256>>>();                                // 3

    int grid = BB * (NN / P);   // 4096
    kA<<<grid, THREADS, SMEM_BYTES>>>(feat, clus, b_in, b1, b2, bc1, bc2, bc3);   // 4
    kB<<<BB, TE>>>(0);                                                            // 5
    kC<<<grid, THREADS, SMEM_BYTES>>>(clus, b3, b1 + 64, b2 + 128, bc1 + 128, bc2 + 256, bc3 + 32); // 6 <- ncu
    kB<<<BB, TE>>>(1);
    kD<<<grid, THREADS, SMEM_BYTES>>>(clus, b3 + 128, bo1, bo2);
    kE<<<1, TE>>>(dw1, db1, dw2, db2, dw3, db3, (float*)d_out);
}

// round 7
// speedup vs baseline: 4.3677x; 1.0017x over previous
#include <cuda_runtime.h>
#include <cuda_bf16.h>

#define BB 8
#define NN 32768
#define CC 32
#define KIN 22

constexpr int P  = 64;        // points per block
constexpr int SP = 72;        // channel-row pitch in halves (144B, conflict-free for ldmatrix)
constexpr int SPW = SP / 2;   // pitch in u32 words (36)
constexpr int THREADS = 512;  // 16 warps
constexpr int TE = 256;

// ---------------- device scratch ----------------
__device__ unsigned g_f2h[BB * 128 * NN / 2];    // f2 hi plane, channel-major u32 words (2 pts)
__device__ unsigned g_f2l[BB * 128 * NN / 2];    // f2 lo plane
__device__ int   g_cf[2 * BB * CC * 128];
__device__ int   g_cc[2 * BB * CC * 32];
__device__ float g_cf2[2 * BB * CC * 128];
__device__ int   g_net[BB * 128];

// weight fragments (u32 = 2 packed bf16), size = O * Ipad u32 per matrix
__device__ unsigned fr_in [256 * 32];
__device__ unsigned fr_w1 [2][64 * 256];
__device__ unsigned fr_w2 [2][128 * 64];
__device__ unsigned fr_w3 [2][128 * 128];
__device__ unsigned fr_c1 [2][128 * 128];
__device__ unsigned fr_c2 [2][256 * 128];
__device__ unsigned fr_c3 [2][32 * 256];
__device__ unsigned fr_o1 [128 * 256];
__device__ unsigned fr_o2 [128 * 128];

// ---------------- prep: pack all weights into MMA fragment layout ----------------
struct FJobs {
    const float* src[15];
    unsigned*    dst[15];
    int Ireal[15], Ipad[15], O[15], n[15];
};

__global__ void frag_all(FJobs jobs, int total) {
    int t = blockIdx.x * blockDim.x + threadIdx.x;
    if (t >= total) return;
    int j = 0, e = t;
    while (e >= jobs.n[j]) { e -= jobs.n[j]; j++; }
    int Ireal = jobs.Ireal[j], Ipad = jobs.Ipad[j];
    int KS = Ipad / 16;
    int f = e >> 7;                 // fragment index
    int idx = e & 127;              // u32 within fragment
    int lane = idx >> 2, r = idx & 3;
    int term = f & 1, q = f >> 1;
    int ks = q % KS, mt = q / KS;
    int g = lane >> 2, c = lane & 3;
    int row = mt * 16 + g + (r & 1) * 8;
    int k0  = ks * 16 + 2 * c + (r & 2) * 4;
    const float* W = jobs.src[j];
    float v0 = (k0     < Ireal) ? W[row * Ireal + k0]     : 0.0f;
    float v1 = (k0 + 1 < Ireal) ? W[row * Ireal + k0 + 1] : 0.0f;
    unsigned short h0, h1;
    if (term == 0) {
        h0 = __bfloat16_as_ushort(__float2bfloat16(v0));
        h1 = __bfloat16_as_ushort(__float2bfloat16(v1));
    } else {
        __nv_bfloat16 b0 = __float2bfloat16(v0);
        __nv_bfloat16 b1 = __float2bfloat16(v1);
        h0 = __bfloat16_as_ushort(__float2bfloat16(v0 - __bfloat162float(b0)));
        h1 = __bfloat16_as_ushort(__float2bfloat16(v1 - __bfloat162float(b1)));
    }
    jobs.dst[j][e] = (unsigned)h0 | ((unsigned)h1 << 16);
}

__global__ void zero1_k() {
    int t = blockIdx.x * blockDim.x + threadIdx.x;
    if (t < 2 * BB * CC * 128) g_cf[t] = 0;
    if (t < 2 * BB * CC * 32)  g_cc[t] = 0;
}
__global__ void zero2_k() {
    int t = blockIdx.x * blockDim.x + threadIdx.x;
    if (t < BB * 128) g_net[t] = 0;
}

// ---------------- asm helpers ----------------
__device__ __forceinline__ unsigned sptr(const void* p) {
    return (unsigned)__cvta_generic_to_shared(p);
}
__device__ __forceinline__ void mma16816(float* d, unsigned a0, unsigned a1,
                                         unsigned a2, unsigned a3,
                                         unsigned b0, unsigned b1) {
    asm volatile(
        "mma.sync.aligned.m16n8k16.row.col.f32.bf16.bf16.f32 "
        "{%0,%1,%2,%3}, {%4,%5,%6,%7}, {%8,%9}, {%0,%1,%2,%3};"
        : "+f"(d[0]), "+f"(d[1]), "+f"(d[2]), "+f"(d[3])
        : "r"(a0), "r"(a1), "r"(a2), "r"(a3), "r"(b0), "r"(b1));
}
__device__ __forceinline__ void ldsm_x4_t(unsigned addr, unsigned& r0, unsigned& r1,
                                          unsigned& r2, unsigned& r3) {
    asm volatile("ldmatrix.sync.aligned.m8n8.x4.trans.shared.b16 {%0,%1,%2,%3}, [%4];"
                 : "=r"(r0), "=r"(r1), "=r"(r2), "=r"(r3) : "r"(addr));
}
__device__ __forceinline__ void ldsm_x2_t(unsigned addr, unsigned& r0, unsigned& r1) {
    asm volatile("ldmatrix.sync.aligned.m8n8.x2.trans.shared.b16 {%0,%1}, [%2];"
                 : "=r"(r0), "=r"(r1) : "r"(addr));
}
__device__ __forceinline__ void stsm_x2(unsigned addr, unsigned r0, unsigned r1) {
    asm volatile("stmatrix.sync.aligned.m8n8.x2.shared.b16 [%0], {%1,%2};"
                 :: "r"(addr), "r"(r0), "r"(r1));
}
__device__ __forceinline__ unsigned pack_bf(__nv_bfloat16 a, __nv_bfloat16 b) {
    return (unsigned)__bfloat16_as_ushort(a) | ((unsigned)__bfloat16_as_ushort(b) << 16);
}
__device__ __forceinline__ float bflo(unsigned u) {
    return __bfloat162float(__ushort_as_bfloat16((unsigned short)(u & 0xFFFF)));
}
__device__ __forceinline__ float bfhi(unsigned u) {
    return __bfloat162float(__ushort_as_bfloat16((unsigned short)(u >> 16)));
}
// split two floats into packed hi-word and lo-word
__device__ __forceinline__ void split2(float v0, float v1, unsigned& hw, unsigned& lw) {
    __nv_bfloat16 h0 = __float2bfloat16(v0), h1 = __float2bfloat16(v1);
    float r0 = v0 - __bfloat162float(h0), r1 = v1 - __bfloat162float(h1);
    hw = pack_bf(h0, h1);
    lw = pack_bf(__float2bfloat16(r0), __float2bfloat16(r1));
}

// ---------------- tensor-core layer: D[O x 64] = W[O x I] * H[I x 64] -------
// channel-major smem (row = channel, SP halves pitch). ldmatrix.trans B, stmatrix D.
template <int I, int O, bool RELU>
__device__ __forceinline__ void layerMMA(const unsigned* __restrict__ WF,
                                         const float* __restrict__ bias,
                                         const __nv_bfloat16* __restrict__ Shi,
                                         const __nv_bfloat16* __restrict__ Slo,
                                         __nv_bfloat16* __restrict__ Dhi,
                                         __nv_bfloat16* __restrict__ Dlo,
                                         int w, int lane) {
    constexpr int KS  = I / 16;
    constexpr int MT  = O / 16;
    constexpr int NTW = MT / 2;       // n-tiles per warp (>=1)
    int mt  = w % MT;
    int ntb = (w / MT) * (NTW ? NTW : 1);
    int g = lane >> 2;
    float acc[(NTW ? NTW : 1)][4];
    float bv0 = __ldg(bias + mt * 16 + g);
    float bv1 = __ldg(bias + mt * 16 + 8 + g);
#pragma unroll
    for (int n = 0; n < (NTW ? NTW : 1); n++) {
        acc[n][0] = bv0; acc[n][1] = bv0;
        acc[n][2] = bv1; acc[n][3] = bv1;
    }
    // ldmatrix per-lane row addressing
    int krow  = ((lane >> 3) & 1) * 8 + (lane & 7);
    int ntoff = lane >> 4;            // used by x4 path
    unsigned baseH = sptr(Shi) + krow * (SP * 2);
    unsigned baseL = sptr(Slo) + krow * (SP * 2);
#pragma unroll 2
    for (int ks = 0; ks < KS; ks++) {
        const uint4* ab = reinterpret_cast<const uint4*>(WF) + (mt * KS + ks) * 64 + lane;
        uint4 ah = __ldg(ab);
        uint4 al = __ldg(ab + 32);
        unsigned koff = ks * (16 * SP * 2);
        if constexpr (NTW <= 1) {
            unsigned bh0, bh1, bl0, bl1;
            unsigned col = ntb * 16;
            ldsm_x2_t(baseH + koff + col, bh0, bh1);
            ldsm_x2_t(baseL + koff + col, bl0, bl1);
            mma16816(acc[0], ah.x, ah.y, ah.z, ah.w, bh0, bh1);
            mma16816(acc[0], ah.x, ah.y, ah.z, ah.w, bl0, bl1);
            mma16816(acc[0], al.x, al.y, al.z, al.w, bh0, bh1);
        } else {
#pragma unroll
            for (int np = 0; np < NTW / 2; np++) {
                unsigned col = (ntb + 2 * np + ntoff) * 16;
                unsigned bh0, bh1, bh2, bh3, bl0, bl1, bl2, bl3;
                ldsm_x4_t(baseH + koff + col, bh0, bh1, bh2, bh3);
                ldsm_x4_t(baseL + koff + col, bl0, bl1, bl2, bl3);
                mma16816(acc[2 * np],     ah.x, ah.y, ah.z, ah.w, bh0, bh1);
                mma16816(acc[2 * np],     ah.x, ah.y, ah.z, ah.w, bl0, bl1);
                mma16816(acc[2 * np],     al.x, al.y, al.z, al.w, bh0, bh1);
                mma16816(acc[2 * np + 1], ah.x, ah.y, ah.z, ah.w, bh2, bh3);
                mma16816(acc[2 * np + 1], ah.x, ah.y, ah.z, ah.w, bl2, bl3);
                mma16816(acc[2 * np + 1], al.x, al.y, al.z, al.w, bh2, bh3);
            }
        }
    }
    // stores via stmatrix: tiles rows = channels, cols = points
    int sl = lane & 15;
    int mrow = mt * 16 + (sl >> 3) * 8 + (sl & 7);
    unsigned stH = sptr(Dhi) + mrow * (SP * 2);
    unsigned stL = sptr(Dlo) + mrow * (SP * 2);
#pragma unroll
    for (int n = 0; n < (NTW ? NTW : 1); n++) {
        int nt = ntb + n;
        float d0 = acc[n][0], d1 = acc[n][1], d2 = acc[n][2], d3 = acc[n][3];
        if (RELU) {
            d0 = fmaxf(d0, 0.f); d1 = fmaxf(d1, 0.f);
            d2 = fmaxf(d2, 0.f); d3 = fmaxf(d3, 0.f);
        }
        unsigned h01, l01, h23, l23;
        split2(d0, d1, h01, l01);
        split2(d2, d3, h23, l23);
        stsm_x2(stH + nt * 16, h01, h23);
        stsm_x2(stL + nt * 16, l01, l23);
    }
}

// shared layout (bytes)
constexpr int AHI_OFF = 0;
constexpr int ALO_OFF = AHI_OFF + 256 * SP * 2;        // 36864
constexpr int BHI_OFF = ALO_OFF + 256 * SP * 2;        // 73728
constexpr int BLO_OFF = BHI_OFF + 128 * SP * 2;        // 92160
constexpr int CFL_OFF = BLO_OFF + 128 * SP * 2;        // 110592
constexpr int CCL_OFF = CFL_OFF + CC * 128 * 4;        // 126976
constexpr int CL_OFF  = CCL_OFF + CC * 32 * 4;         // 131072
constexpr int SMEM_BYTES = CL_OFF + 2 * 64 * 4;        // 131584

struct Smem {
    __nv_bfloat16 *Ahi, *Alo, *Bhi, *Blo;
    unsigned *AHw, *ALw, *BHw, *BLw;
    int *cfl, *ccl, *cl0, *cl1;
};
__device__ __forceinline__ Smem carve(char* sm) {
    Smem s;
    s.Ahi = (__nv_bfloat16*)(sm + AHI_OFF);
    s.Alo = (__nv_bfloat16*)(sm + ALO_OFF);
    s.Bhi = (__nv_bfloat16*)(sm + BHI_OFF);
    s.Blo = (__nv_bfloat16*)(sm + BLO_OFF);
    s.AHw = (unsigned*)s.Ahi; s.ALw = (unsigned*)s.Alo;
    s.BHw = (unsigned*)s.Bhi; s.BLw = (unsigned*)s.Blo;
    s.cfl = (int*)(sm + CFL_OFF);
    s.ccl = (int*)(sm + CCL_OFF);
    s.cl0 = (int*)(sm + CL_OFF);
    s.cl1 = s.cl0 + 64;
    return s;
}

// ---------------- kernel A ----------------
__global__ __launch_bounds__(THREADS, 1) void kA(const float* __restrict__ feat,
                                                 const int* __restrict__ clus,
                                                 const float* b_in, const float* b1,
                                                 const float* b2, const float* bc1,
                                                 const float* bc2, const float* bc3) {
    extern __shared__ char smraw[];
    Smem s = carve(smraw);
    int t = threadIdx.x, w = t >> 5, lane = t & 31;
    int b = blockIdx.x >> 9, n0 = (blockIdx.x & 511) * P;
    int n02 = (blockIdx.x & 511) * (P / 2);

    for (int r = t; r < CC * 128; r += THREADS) s.cfl[r] = 0;
    for (int r = t; r < CC * 32; r += THREADS)  s.ccl[r] = 0;
    if (t < P) s.cl0[t] = clus[b * NN + n0 + t];
    for (int r = t; r < 32 * 32; r += THREADS) {          // features (pad 22->32), pairs
        int pair = r & 31, k = r >> 5;
        float v0 = (k < KIN) ? feat[(b * NN + n0 + 2 * pair) * KIN + k] : 0.0f;
        float v1 = (k < KIN) ? feat[(b * NN + n0 + 2 * pair + 1) * KIN + k] : 0.0f;
        unsigned hw, lw; split2(v0, v1, hw, lw);
        s.BHw[k * SPW + pair] = hw; s.BLw[k * SPW + pair] = lw;
    }
    __syncthreads();
    layerMMA<32, 256, true>(fr_in, b_in, s.Bhi, s.Blo, s.Ahi, s.Alo, w, lane);
    __syncthreads();
    layerMMA<256, 64, true>(fr_w1[0], b1, s.Ahi, s.Alo, s.Bhi, s.Blo, w, lane);
    __syncthreads();
    layerMMA<64, 128, true>(fr_w2[0], b2, s.Bhi, s.Blo, s.Ahi, s.Alo, w, lane);
    __syncthreads();
    for (int r = t; r < 128 * 32; r += THREADS) {         // f2 store + segmax cf
        int pair = r & 31, c = r >> 5;
        unsigned h2 = s.AHw[c * SPW + pair], l2 = s.ALw[c * SPW + pair];
        int gi = (b * 128 + c) * (NN / 2) + n02 + pair;
        g_f2h[gi] = h2; g_f2l[gi] = l2;
        float v0 = bflo(h2) + bflo(l2);
        float v1 = bfhi(h2) + bfhi(l2);
        atomicMax(&s.cfl[s.cl0[2 * pair]     * 128 + c], __float_as_int(v0));
        atomicMax(&s.cfl[s.cl0[2 * pair + 1] * 128 + c], __float_as_int(v1));
    }
    layerMMA<128, 128, true>(fr_c1[0], bc1, s.Ahi, s.Alo, s.Bhi, s.Blo, w, lane);
    __syncthreads();
    layerMMA<128, 256, true>(fr_c2[0], bc2, s.Bhi, s.Blo, s.Ahi, s.Alo, w, lane);
    __syncthreads();
    layerMMA<256, 32, true>(fr_c3[0], bc3, s.Ahi, s.Alo, s.Bhi, s.Blo, w, lane);
    __syncthreads();
    for (int r = t; r < 32 * 32; r += THREADS) {          // segmax cc
        int pair = r & 31, c = r >> 5;
        unsigned h2 = s.BHw[c * SPW + pair], l2 = s.BLw[c * SPW + pair];
        float v0 = bflo(h2) + bflo(l2);
        float v1 = bfhi(h2) + bfhi(l2);
        atomicMax(&s.ccl[s.cl0[2 * pair]     * 32 + c], __float_as_int(v0));
        atomicMax(&s.ccl[s.cl0[2 * pair + 1] * 32 + c], __float_as_int(v1));
    }
    __syncthreads();
    for (int r = t; r < CC * 128; r += THREADS) { int v = s.cfl[r]; if (v) atomicMax(&g_cf[b * CC * 128 + r], v); }
    for (int r = t; r < CC * 32; r += THREADS)  { int v = s.ccl[r]; if (v) atomicMax(&g_cc[b * CC * 32 + r], v); }
}

// ---------------- kernel B: per-batch corr matrix + cf @ corr ----------------
__global__ void kB(int it) {
    __shared__ float cm[CC * 32], corr[CC * CC], invn[CC], cfs[CC * 128];
    int b = blockIdx.x, t = threadIdx.x;
    for (int r = t; r < CC * 32; r += TE)  cm[r]  = __int_as_float(g_cc[(it * BB + b) * CC * 32 + r]);
    for (int r = t; r < CC * 128; r += TE) cfs[r] = __int_as_float(g_cf[(it * BB + b) * CC * 128 + r]);
    __syncthreads();
    if (t < CC) {
        float ss = 0.f;
        for (int c = 0; c < 32; c++) { float v = cm[t * 32 + c]; ss += v * v; }
        invn[t] = 1.0f / fmaxf(sqrtf(ss), 1e-12f);
    }
    __syncthreads();
    for (int r = t; r < CC * 32; r += TE) cm[r] *= invn[r >> 5];
    __syncthreads();
    for (int r = t; r < CC * CC; r += TE) {
        int c1 = r >> 5, c2 = r & 31;
        float ss = 0.f;
        for (int c = 0; c < 32; c++) ss += cm[c1 * 32 + c] * cm[c2 * 32 + c];
        corr[r] = ss;
    }
    __syncthreads();
    for (int r = t; r < CC * 128; r += TE) {
        int c2 = r >> 7, ch = r & 127;
        float ss = 0.f;
        for (int c1 = 0; c1 < 32; c1++) ss += cfs[c1 * 128 + ch] * corr[c1 * 32 + c2];
        g_cf2[(it * BB + b) * CC * 128 + r] = ss;
    }
}

// ---------------- kernel C ----------------
__global__ __launch_bounds__(THREADS, 1) void kC(const int* __restrict__ clus,
                                                 const float* b3, const float* b1,
                                                 const float* b2, const float* bc1,
                                                 const float* bc2, const float* bc3) {
    extern __shared__ char smraw[];
    Smem s = carve(smraw);
    int t = threadIdx.x, w = t >> 5, lane = t & 31;
    int b = blockIdx.x >> 9, n0 = (blockIdx.x & 511) * P;
    int n02 = (blockIdx.x & 511) * (P / 2);

    for (int r = t; r < CC * 128; r += THREADS) s.cfl[r] = 0;
    for (int r = t; r < CC * 32; r += THREADS)  s.ccl[r] = 0;
    if (t < P) {
        s.cl0[t] = clus[b * NN + n0 + t];
        s.cl1[t] = clus[(BB + b) * NN + n0 + t];
    }
    for (int r = t; r < 128 * 32; r += THREADS) {         // load f2 -> B
        int pair = r & 31, c = r >> 5;
        int gi = (b * 128 + c) * (NN / 2) + n02 + pair;
        s.BHw[c * SPW + pair] = g_f2h[gi];
        s.BLw[c * SPW + pair] = g_f2l[gi];
    }
    __syncthreads();
    layerMMA<128, 128, true>(fr_w3[0], b3, s.Bhi, s.Blo, s.Ahi, s.Alo, w, lane);
    for (int r = t; r < 128 * 32; r += THREADS) {         // pool gather -> A ch 128..255
        int pair = r & 31, c = r >> 5;
        float v0 = g_cf2[(b * CC + s.cl0[2 * pair])     * 128 + c];
        float v1 = g_cf2[(b * CC + s.cl0[2 * pair + 1]) * 128 + c];
        unsigned hw, lw; split2(v0, v1, hw, lw);
        s.AHw[(128 + c) * SPW + pair] = hw;
        s.ALw[(128 + c) * SPW + pair] = lw;
    }
    __syncthreads();
    layerMMA<256, 64, true>(fr_w1[1], b1, s.Ahi, s.Alo, s.Bhi, s.Blo, w, lane);
    __syncthreads();
    layerMMA<64, 128, true>(fr_w2[1], b2, s.Bhi, s.Blo, s.Ahi, s.Alo, w, lane);
    __syncthreads();
    for (int r = t; r < 128 * 32; r += THREADS) {         // f2' store + segmax cf
        int pair = r & 31, c = r >> 5;
        unsigned h2 = s.AHw[c * SPW + pair], l2 = s.ALw[c * SPW + pair];
        int gi = (b * 128 + c) * (NN / 2) + n02 + pair;
        g_f2h[gi] = h2; g_f2l[gi] = l2;
        float v0 = bflo(h2) + bflo(l2);
        float v1 = bfhi(h2) + bfhi(l2);
        atomicMax(&s.cfl[s.cl1[2 * pair]     * 128 + c], __float_as_int(v0));
        atomicMax(&s.cfl[s.cl1[2 * pair + 1] * 128 + c], __float_as_int(v1));
    }
    layerMMA<128, 128, true>(fr_c1[1], bc1, s.Ahi, s.Alo, s.Bhi, s.Blo, w, lane);
    __syncthreads();
    layerMMA<128, 256, true>(fr_c2[1], bc2, s.Bhi, s.Blo, s.Ahi, s.Alo, w, lane);
    __syncthreads();
    layerMMA<256, 32, true>(fr_c3[1], bc3, s.Ahi, s.Alo, s.Bhi, s.Blo, w, lane);
    __syncthreads();
    for (int r = t; r < 32 * 32; r += THREADS) {
        int pair = r & 31, c = r >> 5;
        unsigned h2 = s.BHw[c * SPW + pair], l2 = s.BLw[c * SPW + pair];
        float v0 = bflo(h2) + bflo(l2);
        float v1 = bfhi(h2) + bfhi(l2);
        atomicMax(&s.ccl[s.cl1[2 * pair]     * 32 + c], __float_as_int(v0));
        atomicMax(&s.ccl[s.cl1[2 * pair + 1] * 32 + c], __float_as_int(v1));
    }
    __syncthreads();
    for (int r = t; r < CC * 128; r += THREADS) { int v = s.cfl[r]; if (v) atomicMax(&g_cf[(BB + b) * CC * 128 + r], v); }
    for (int r = t; r < CC * 32; r += THREADS)  { int v = s.ccl[r]; if (v) atomicMax(&g_cc[(BB + b) * CC * 32 + r], v); }
}

// ---------------- kernel D ----------------
__global__ __launch_bounds__(THREADS, 1) void kD(const int* __restrict__ clus,
                                                 const float* b3, const float* bo1,
                                                 const float* bo2) {
    extern __shared__ char smraw[];
    Smem s = carve(smraw);
    int t = threadIdx.x, w = t >> 5, lane = t & 31;
    int b = blockIdx.x >> 9, n0 = (blockIdx.x & 511) * P;
    int n02 = (blockIdx.x & 511) * (P / 2);

    if (t < P) s.cl1[t] = clus[(BB + b) * NN + n0 + t];
    for (int r = t; r < 128 * 32; r += THREADS) {         // load f2' -> B
        int pair = r & 31, c = r >> 5;
        int gi = (b * 128 + c) * (NN / 2) + n02 + pair;
        s.BHw[c * SPW + pair] = g_f2h[gi];
        s.BLw[c * SPW + pair] = g_f2l[gi];
    }
    __syncthreads();
    layerMMA<128, 128, true>(fr_w3[1], b3, s.Bhi, s.Blo, s.Ahi, s.Alo, w, lane);
    for (int r = t; r < 128 * 32; r += THREADS) {         // pool gather -> A ch 128..255
        int pair = r & 31, c = r >> 5;
        float v0 = g_cf2[((BB + b) * CC + s.cl1[2 * pair])     * 128 + c];
        float v1 = g_cf2[((BB + b) * CC + s.cl1[2 * pair + 1]) * 128 + c];
        unsigned hw, lw; split2(v0, v1, hw, lw);
        s.AHw[(128 + c) * SPW + pair] = hw;
        s.ALw[(128 + c) * SPW + pair] = lw;
    }
    __syncthreads();
    layerMMA<256, 128, true>(fr_o1, bo1, s.Ahi, s.Alo, s.Bhi, s.Blo, w, lane);
    __syncthreads();
    layerMMA<128, 128, true>(fr_o2, bo2, s.Bhi, s.Blo, s.Ahi, s.Alo, w, lane);
    __syncthreads();
    if (t < 128) {
        float m = 0.0f;
        for (int pair = 0; pair < 32; pair++) {
            unsigned h2 = s.AHw[t * SPW + pair], l2 = s.ALw[t * SPW + pair];
            m = fmaxf(m, fmaxf(bflo(h2) + bflo(l2), bfhi(h2) + bfhi(l2)));
        }
        atomicMax(&g_net[b * 128 + t], __float_as_int(m));
    }
}

// ---------------- kernel E: dense head ----------------
__global__ void kE(const float* __restrict__ dw1, const float* __restrict__ db1,
                   const float* __restrict__ dw2, const float* __restrict__ db2,
                   const float* __restrict__ dw3, const float* __restrict__ db3,
                   float* __restrict__ out) {
    __shared__ float net[BB * 128], l1[BB * 256], l2[BB * 256];
    int t = threadIdx.x;
    for (int r = t; r < BB * 128; r += TE) net[r] = __int_as_float(g_net[r]);
    __syncthreads();
    for (int r = t; r < BB * 256; r += TE) {
        int b = r >> 8, o = r & 255;
        float ss = db1[o];
        for (int i = 0; i < 128; i++) ss = fmaf(net[b * 128 + i], dw1[i * 256 + o], ss);
        l1[r] = ss >= 0.f ? ss : 0.2f * ss;
    }
    __syncthreads();
    for (int r = t; r < BB * 256; r += TE) {
        int b = r >> 8, o = r & 255;
        float ss = db2[o];
        for (int i = 0; i < 256; i++) ss = fmaf(l1[b * 256 + i], dw2[i * 256 + o], ss);
        l2[r] = ss >= 0.f ? ss : 0.2f * ss;
    }
    __syncthreads();
    for (int r = t; r < BB * 40; r += TE) {
        int b = r / 40, o = r % 40;
        float ss = db3[o];
        for (int i = 0; i < 256; i++) ss = fmaf(l2[b * 256 + i], dw3[i * 40 + o], ss);
        out[r] = ss;
    }
}

// ---------------- host launcher ----------------
extern "C" void kernel_launch(void* const* d_in, const int* in_sizes, int n_in,
                              void* d_out, int out_size) {
    const float* feat = (const float*)d_in[0];
    const int*   clus = (const int*)d_in[1];
    const float* w_in = (const float*)d_in[2];
    const float* b_in = (const float*)d_in[3];
    const float* w1   = (const float*)d_in[4];
    const float* b1   = (const float*)d_in[5];
    const float* w2   = (const float*)d_in[6];
    const float* b2   = (const float*)d_in[7];
    const float* w3   = (const float*)d_in[8];
    const float* b3   = (const float*)d_in[9];
    const float* wc1  = (const float*)d_in[10];
    const float* bc1  = (const float*)d_in[11];
    const float* wc2  = (const float*)d_in[12];
    const float* bc2  = (const float*)d_in[13];
    const float* wc3  = (const float*)d_in[14];
    const float* bc3  = (const float*)d_in[15];
    const float* wo1  = (const float*)d_in[16];
    const float* bo1  = (const float*)d_in[17];
    const float* wo2  = (const float*)d_in[18];
    const float* bo2  = (const float*)d_in[19];
    const float* dw1  = (const float*)d_in[20];
    const float* db1  = (const float*)d_in[21];
    const float* dw2  = (const float*)d_in[22];
    const float* db2  = (const float*)d_in[23];
    const float* dw3  = (const float*)d_in[24];
    const float* db3  = (const float*)d_in[25];

    cudaFuncSetAttribute(kA, cudaFuncAttributeMaxDynamicSharedMemorySize, SMEM_BYTES);
    cudaFuncSetAttribute(kC, cudaFuncAttributeMaxDynamicSharedMemorySize, SMEM_BYTES);
    cudaFuncSetAttribute(kD, cudaFuncAttributeMaxDynamicSharedMemorySize, SMEM_BYTES);

    unsigned *p_in, *p_w1, *p_w2, *p_w3, *p_c1, *p_c2, *p_c3, *p_o1, *p_o2;
    cudaGetSymbolAddress((void**)&p_in, fr_in);
    cudaGetSymbolAddress((void**)&p_w1, fr_w1);
    cudaGetSymbolAddress((void**)&p_w2, fr_w2);
    cudaGetSymbolAddress((void**)&p_w3, fr_w3);
    cudaGetSymbolAddress((void**)&p_c1, fr_c1);
    cudaGetSymbolAddress((void**)&p_c2, fr_c2);
    cudaGetSymbolAddress((void**)&p_c3, fr_c3);
    cudaGetSymbolAddress((void**)&p_o1, fr_o1);
    cudaGetSymbolAddress((void**)&p_o2, fr_o2);

    FJobs jobs;
    int idx = 0, total = 0;
    auto add = [&](const float* s, unsigned* d, int Ireal, int Ipad, int O) {
        jobs.src[idx] = s; jobs.dst[idx] = d;
        jobs.Ireal[idx] = Ireal; jobs.Ipad[idx] = Ipad; jobs.O[idx] = O;
        jobs.n[idx] = O * Ipad;
        total += O * Ipad; idx++;
    };
    add(w_in, p_in, KIN, 32, 256);
    for (int it = 0; it < 2; it++) {
        add(w1  + it * 64 * 256,  p_w1 + it * 64 * 256,  256, 256, 64);
        add(w2  + it * 128 * 64,  p_w2 + it * 128 * 64,  64, 64, 128);
        add(w3  + it * 128 * 128, p_w3 + it * 128 * 128, 128, 128, 128);
        add(wc1 + it * 128 * 128, p_c1 + it * 128 * 128, 128, 128, 128);
        add(wc2 + it * 256 * 128, p_c2 + it * 256 * 128, 128, 128, 256);
        add(wc3 + it * 32 * 256,  p_c3 + it * 32 * 256,  256, 256, 32);
    }
    add(wo1, p_o1, 256, 256, 128);
    add(wo2, p_o2, 128, 128, 128);

    // launch order chosen so ncu (-s 5 -c 1) captures kC (6th launch)
    frag_all<<<(total + 255) / 256, 256>>>(jobs, total);  // 1
    zero1_k<<<256, 256>>>();                              // 2
    zero2_k<<<4, 256>>>();                                // 3

    int grid = BB * (NN / P);   // 4096
    kA<<<grid, THREADS, SMEM_BYTES>>>(feat, clus, b_in, b1, b2, bc1, bc2, bc3);   // 4
    kB<<<BB, TE>>>(0);                                                            // 5
    kC<<<grid, THREADS, SMEM_BYTES>>>(clus, b3, b1 + 64, b2 + 128, bc1 + 128, bc2 + 256, bc3 + 32); // 6 <- ncu
    kB<<<BB, TE>>>(1);
    kD<<<grid, THREADS, SMEM_BYTES>>>(clus, b3 + 128, bo1, bo2);
    kE<<<1, TE>>>(dw1, db1, dw2, db2, dw3, db3, (float*)d_out);
}

// round 9
// speedup vs baseline: 4.8361x; 1.1073x over previous
#include <cuda_runtime.h>
#include <cuda_bf16.h>

#define BB 8
#define NN 32768
#define CC 32
#define KIN 22

constexpr int THREADS = 512;  // 16 warps
constexpr int TE = 256;
constexpr int P = 128;        // points per CTA

// ---------------- device scratch ----------------
__device__ unsigned g_f2h[(size_t)BB * 128 * (NN / 2)];  // [(b*128+c)*(NN/2)+q] : points (2q,2q+1) hi
__device__ unsigned g_f2l[(size_t)BB * 128 * (NN / 2)];
__device__ int   g_cf[2 * BB * CC * 128];
__device__ int   g_cc[2 * BB * CC * 32];
__device__ float g_cf2[2 * BB * CC * 128];
__device__ int   g_net[BB * 128];

// weight fragments (u32 = 2 packed bf16): per (mt,ks): 64 uint4 = hi(32)+lo(32)
__device__ unsigned fr_in [256 * 32];
__device__ unsigned fr_w1 [2][64 * 256];
__device__ unsigned fr_w2 [2][128 * 64];
__device__ unsigned fr_w3 [2][128 * 128];
__device__ unsigned fr_c1 [2][128 * 128];
__device__ unsigned fr_c2 [2][256 * 128];
__device__ unsigned fr_c3 [2][32 * 256];
__device__ unsigned fr_o1 [128 * 256];
__device__ unsigned fr_o2 [128 * 128];

// ---------------- prep: pack all weights into MMA fragment layout ------------
struct FJobs {
    const float* src[15];
    unsigned*    dst[15];
    int Ireal[15], Ipad[15], O[15], n[15];
};

__global__ void frag_all(FJobs jobs, int total) {
    int t = blockIdx.x * blockDim.x + threadIdx.x;
    if (t >= total) return;
    int j = 0, e = t;
    while (e >= jobs.n[j]) { e -= jobs.n[j]; j++; }
    int Ireal = jobs.Ireal[j], Ipad = jobs.Ipad[j];
    int KS = Ipad / 16;
    int f = e >> 7;
    int idx = e & 127;
    int lane = idx >> 2, r = idx & 3;
    int term = f & 1, q = f >> 1;
    int ks = q % KS, mt = q / KS;
    int g = lane >> 2, c = lane & 3;
    int row = mt * 16 + g + (r & 1) * 8;
    int k0  = ks * 16 + 2 * c + (r & 2) * 4;
    const float* W = jobs.src[j];
    float v0 = (k0     < Ireal) ? W[row * Ireal + k0]     : 0.0f;
    float v1 = (k0 + 1 < Ireal) ? W[row * Ireal + k0 + 1] : 0.0f;
    unsigned short h0, h1;
    if (term == 0) {
        h0 = __bfloat16_as_ushort(__float2bfloat16(v0));
        h1 = __bfloat16_as_ushort(__float2bfloat16(v1));
    } else {
        __nv_bfloat16 b0 = __float2bfloat16(v0);
        __nv_bfloat16 b1 = __float2bfloat16(v1);
        h0 = __bfloat16_as_ushort(__float2bfloat16(v0 - __bfloat162float(b0)));
        h1 = __bfloat16_as_ushort(__float2bfloat16(v1 - __bfloat162float(b1)));
    }
    jobs.dst[j][e] = (unsigned)h0 | ((unsigned)h1 << 16);
}

__global__ void zero1_k() {
    int t = blockIdx.x * blockDim.x + threadIdx.x;
    if (t < 2 * BB * CC * 128) g_cf[t] = 0;
    if (t < 2 * BB * CC * 32)  g_cc[t] = 0;
}
__global__ void zero2_k() {
    int t = blockIdx.x * blockDim.x + threadIdx.x;
    if (t < BB * 128) g_net[t] = 0;
}

// ---------------- asm helpers ----------------
__device__ __forceinline__ unsigned sptr(const void* p) {
    return (unsigned)__cvta_generic_to_shared(p);
}
__device__ __forceinline__ void mma16816(float* d, unsigned a0, unsigned a1,
                                         unsigned a2, unsigned a3,
                                         unsigned b0, unsigned b1) {
    asm volatile(
        "mma.sync.aligned.m16n8k16.row.col.f32.bf16.bf16.f32 "
        "{%0,%1,%2,%3}, {%4,%5,%6,%7}, {%8,%9}, {%0,%1,%2,%3};"
        : "+f"(d[0]), "+f"(d[1]), "+f"(d[2]), "+f"(d[3])
        : "r"(a0), "r"(a1), "r"(a2), "r"(a3), "r"(b0), "r"(b1));
}
__device__ __forceinline__ void ldsm_x4_t(unsigned addr, unsigned& r0, unsigned& r1,
                                          unsigned& r2, unsigned& r3) {
    asm volatile("ldmatrix.sync.aligned.m8n8.x4.trans.shared.b16 {%0,%1,%2,%3}, [%4];"
                 : "=r"(r0), "=r"(r1), "=r"(r2), "=r"(r3) : "r"(addr));
}
__device__ __forceinline__ void ldsm_x2_t(unsigned addr, unsigned& r0, unsigned& r1) {
    asm volatile("ldmatrix.sync.aligned.m8n8.x2.trans.shared.b16 {%0,%1}, [%2];"
                 : "=r"(r0), "=r"(r1) : "r"(addr));
}
__device__ __forceinline__ void stsm_x2(unsigned addr, unsigned r0, unsigned r1) {
    asm volatile("stmatrix.sync.aligned.m8n8.x2.shared.b16 [%0], {%1,%2};"
                 :: "r"(addr), "r"(r0), "r"(r1));
}
__device__ __forceinline__ unsigned pack_bf(__nv_bfloat16 a, __nv_bfloat16 b) {
    return (unsigned)__bfloat16_as_ushort(a) | ((unsigned)__bfloat16_as_ushort(b) << 16);
}
__device__ __forceinline__ float bflo(unsigned u) {
    return __bfloat162float(__ushort_as_bfloat16((unsigned short)(u & 0xFFFF)));
}
__device__ __forceinline__ float bfhi(unsigned u) {
    return __bfloat162float(__ushort_as_bfloat16((unsigned short)(u >> 16)));
}
__device__ __forceinline__ void split2(float v0, float v1, unsigned& hw, unsigned& lw) {
    __nv_bfloat16 h0 = __float2bfloat16(v0), h1 = __float2bfloat16(v1);
    hw = pack_bf(h0, h1);
    lw = pack_bf(__float2bfloat16(v0 - __bfloat162float(h0)),
                 __float2bfloat16(v1 - __bfloat162float(h1)));
}
// swizzled element offset: row = channel, 256B row, XOR-16B swizzle
__device__ __forceinline__ int soff(int c, int q) {   // q = point pair index (u32)
    return c * 256 + ((q * 4) ^ ((c & 7) << 4));
}

// ---------------- tensor-core layer: D[O x 128] = W[O x K] * H[K x 128] ------
// warp tile = WM m-tiles x WN n-tiles; (MT/WM)*(16/WN) must equal 16
template <int K, int O, int WM, int WN, bool RELU>
__device__ __forceinline__ void layerMMA(const unsigned* __restrict__ WF,
                                         const float* __restrict__ bias,
                                         const __nv_bfloat16* Shi, const __nv_bfloat16* Slo,
                                         __nv_bfloat16* Dhi, __nv_bfloat16* Dlo,
                                         int w, int lane) {
    constexpr int KS = K / 16;
    constexpr int MT = O / 16;
    constexpr int GN = 16 / WN;
    static_assert((MT / WM) * GN == 16, "warp grid");
    int gm = w / GN, gn = w % GN;
    int g = lane >> 2;
    float acc[WM][WN][4];
#pragma unroll
    for (int i = 0; i < WM; i++) {
        int mr = (gm * WM + i) * 16 + g;
        float b0 = __ldg(bias + mr), b1 = __ldg(bias + mr + 8);
#pragma unroll
        for (int j = 0; j < WN; j++) {
            acc[i][j][0] = b0; acc[i][j][1] = b0;
            acc[i][j][2] = b1; acc[i][j][3] = b1;
        }
    }
    int krow = ((lane >> 3) & 1) * 8 + (lane & 7);
    unsigned swz = ((unsigned)(krow & 7)) << 4;
    int ntoff = lane >> 4;
    unsigned baseH = sptr(Shi) + krow * 256;
    unsigned baseL = sptr(Slo) + krow * 256;
#pragma unroll
    for (int ks = 0; ks < KS; ks++) {
        uint4 ah[WM], al[WM];
#pragma unroll
        for (int i = 0; i < WM; i++) {
            const uint4* bp = reinterpret_cast<const uint4*>(WF) + ((gm * WM + i) * KS + ks) * 64 + lane;
            ah[i] = __ldg(bp); al[i] = __ldg(bp + 32);
        }
        unsigned koff = (unsigned)ks * 4096;
        if constexpr (WN == 1) {
            unsigned col = ((unsigned)(gn * 16)) ^ swz;
            unsigned bh0, bh1, bl0, bl1;
            ldsm_x2_t(baseH + koff + col, bh0, bh1);
            ldsm_x2_t(baseL + koff + col, bl0, bl1);
#pragma unroll
            for (int i = 0; i < WM; i++) {
                mma16816(acc[i][0], ah[i].x, ah[i].y, ah[i].z, ah[i].w, bh0, bh1);
                mma16816(acc[i][0], ah[i].x, ah[i].y, ah[i].z, ah[i].w, bl0, bl1);
                mma16816(acc[i][0], al[i].x, al[i].y, al[i].z, al[i].w, bh0, bh1);
            }
        } else {
#pragma unroll
            for (int jp = 0; jp < WN / 2; jp++) {
                unsigned col = ((unsigned)((gn * WN + 2 * jp + ntoff) * 16)) ^ swz;
                unsigned bh0, bh1, bh2, bh3, bl0, bl1, bl2, bl3;
                ldsm_x4_t(baseH + koff + col, bh0, bh1, bh2, bh3);
                ldsm_x4_t(baseL + koff + col, bl0, bl1, bl2, bl3);
#pragma unroll
                for (int i = 0; i < WM; i++) {
                    mma16816(acc[i][2 * jp], ah[i].x, ah[i].y, ah[i].z, ah[i].w, bh0, bh1);
                    mma16816(acc[i][2 * jp], ah[i].x, ah[i].y, ah[i].z, ah[i].w, bl0, bl1);
                    mma16816(acc[i][2 * jp], al[i].x, al[i].y, al[i].z, al[i].w, bh0, bh1);
                    mma16816(acc[i][2 * jp + 1], ah[i].x, ah[i].y, ah[i].z, ah[i].w, bh2, bh3);
                    mma16816(acc[i][2 * jp + 1], ah[i].x, ah[i].y, ah[i].z, ah[i].w, bl2, bl3);
                    mma16816(acc[i][2 * jp + 1], al[i].x, al[i].y, al[i].z, al[i].w, bh2, bh3);
                }
            }
        }
    }
    int sl = lane & 15;
#pragma unroll
    for (int i = 0; i < WM; i++) {
        int mrow = (gm * WM + i) * 16 + (sl >> 3) * 8 + (sl & 7);
        unsigned sswz = ((unsigned)(mrow & 7)) << 4;
        unsigned stH = sptr(Dhi) + mrow * 256;
        unsigned stL = sptr(Dlo) + mrow * 256;
#pragma unroll
        for (int j = 0; j < WN; j++) {
            unsigned col = ((unsigned)((gn * WN + j) * 16)) ^ sswz;
            float d0 = acc[i][j][0], d1 = acc[i][j][1], d2 = acc[i][j][2], d3 = acc[i][j][3];
            if (RELU) {
                d0 = fmaxf(d0, 0.f); d1 = fmaxf(d1, 0.f);
                d2 = fmaxf(d2, 0.f); d3 = fmaxf(d3, 0.f);
            }
            unsigned h01, l01, h23, l23;
            split2(d0, d1, h01, l01);
            split2(d2, d3, h23, l23);
            stsm_x2(stH + col, h01, h23);
            stsm_x2(stL + col, l01, l23);
        }
    }
}

// shared layout (bytes): A 256ch, B 128ch, rows = 256B swizzled
constexpr int AHI_OFF = 0;
constexpr int ALO_OFF = 65536;
constexpr int BHI_OFF = 131072;
constexpr int BLO_OFF = 163840;
constexpr int CFL_OFF = 196608;
constexpr int CCL_OFF = 212992;
constexpr int CL_OFF  = 217088;
constexpr int SMEM_BYTES = 218112;

// ---------------- kernel A ----------------
__global__ __launch_bounds__(THREADS, 1) void kA(const float* __restrict__ feat,
                                                 const int* __restrict__ clus,
                                                 const float* b_in, const float* b1,
                                                 const float* b2, const float* bc1,
                                                 const float* bc2, const float* bc3) {
    extern __shared__ char sm[];
    __nv_bfloat16* Ahi = (__nv_bfloat16*)(sm + AHI_OFF);
    __nv_bfloat16* Alo = (__nv_bfloat16*)(sm + ALO_OFF);
    __nv_bfloat16* Bhi = (__nv_bfloat16*)(sm + BHI_OFF);
    __nv_bfloat16* Blo = (__nv_bfloat16*)(sm + BLO_OFF);
    int* cfl = (int*)(sm + CFL_OFF);
    int* ccl = (int*)(sm + CCL_OFF);
    int* cl  = (int*)(sm + CL_OFF);
    int t = threadIdx.x, w = t >> 5, lane = t & 31;
    int b = blockIdx.x >> 8, nblk = blockIdx.x & 255;
    int n0 = nblk * P, q0 = nblk * (P / 2);

    for (int r = t; r < CC * 128; r += THREADS) cfl[r] = 0;
    for (int r = t; r < CC * 32; r += THREADS)  ccl[r] = 0;
    if (t < P) cl[t] = clus[(size_t)b * NN + n0 + t];
    for (int r = t; r < 32 * 64; r += THREADS) {            // features pad 22->32
        int c = r >> 6, q = r & 63;
        float v0 = (c < KIN) ? feat[((size_t)b * NN + n0 + 2 * q) * KIN + c] : 0.0f;
        float v1 = (c < KIN) ? feat[((size_t)b * NN + n0 + 2 * q + 1) * KIN + c] : 0.0f;
        unsigned hw, lw; split2(v0, v1, hw, lw);
        *(unsigned*)((char*)Bhi + soff(c, q)) = hw;
        *(unsigned*)((char*)Blo + soff(c, q)) = lw;
    }
    __syncthreads();
    layerMMA<32, 256, 4, 4, true>(fr_in, b_in, Bhi, Blo, Ahi, Alo, w, lane);
    __syncthreads();
    layerMMA<256, 64, 2, 2, true>(fr_w1[0], b1, Ahi, Alo, Bhi, Blo, w, lane);
    __syncthreads();
    layerMMA<64, 128, 2, 4, true>(fr_w2[0], b2, Bhi, Blo, Ahi, Alo, w, lane);
    __syncthreads();
    for (int r = t; r < 128 * 64; r += THREADS) {           // f2 store + segmax cf
        int c = r >> 6, q = r & 63;
        unsigned h2 = *(unsigned*)((char*)Ahi + soff(c, q));
        unsigned l2 = *(unsigned*)((char*)Alo + soff(c, q));
        size_t gi = ((size_t)(b * 128 + c)) * (NN / 2) + q0 + q;
        g_f2h[gi] = h2; g_f2l[gi] = l2;
        atomicMax(&cfl[cl[2 * q] * 128 + c], __float_as_int(bflo(h2) + bflo(l2)));
        atomicMax(&cfl[cl[2 * q + 1] * 128 + c], __float_as_int(bfhi(h2) + bfhi(l2)));
    }
    layerMMA<128, 128, 2, 4, true>(fr_c1[0], bc1, Ahi, Alo, Bhi, Blo, w, lane);
    __syncthreads();
    layerMMA<128, 256, 4, 4, true>(fr_c2[0], bc2, Bhi, Blo, Ahi, Alo, w, lane);
    __syncthreads();
    layerMMA<256, 32, 2, 1, true>(fr_c3[0], bc3, Ahi, Alo, Bhi, Blo, w, lane);
    __syncthreads();
    for (int r = t; r < 32 * 64; r += THREADS) {            // segmax cc
        int c = r >> 6, q = r & 63;
        unsigned h2 = *(unsigned*)((char*)Bhi + soff(c, q));
        unsigned l2 = *(unsigned*)((char*)Blo + soff(c, q));
        atomicMax(&ccl[cl[2 * q] * 32 + c], __float_as_int(bflo(h2) + bflo(l2)));
        atomicMax(&ccl[cl[2 * q + 1] * 32 + c], __float_as_int(bfhi(h2) + bfhi(l2)));
    }
    __syncthreads();
    for (int r = t; r < CC * 128; r += THREADS) { int v = cfl[r]; if (v) atomicMax(&g_cf[b * CC * 128 + r], v); }
    for (int r = t; r < CC * 32; r += THREADS)  { int v = ccl[r]; if (v) atomicMax(&g_cc[b * CC * 32 + r], v); }
}

// ---------------- kernel B: per-batch corr matrix + cf @ corr ----------------
__global__ void kB(int it) {
    __shared__ float cm[CC * 32], corr[CC * CC], invn[CC], cfs[CC * 128];
    int b = blockIdx.x, t = threadIdx.x;
    for (int r = t; r < CC * 32; r += TE)  cm[r]  = __int_as_float(g_cc[(it * BB + b) * CC * 32 + r]);
    for (int r = t; r < CC * 128; r += TE) cfs[r] = __int_as_float(g_cf[(it * BB + b) * CC * 128 + r]);
    __syncthreads();
    if (t < CC) {
        float ss = 0.f;
        for (int c = 0; c < 32; c++) { float v = cm[t * 32 + c]; ss += v * v; }
        invn[t] = 1.0f / fmaxf(sqrtf(ss), 1e-12f);
    }
    __syncthreads();
    for (int r = t; r < CC * 32; r += TE) cm[r] *= invn[r >> 5];
    __syncthreads();
    for (int r = t; r < CC * CC; r += TE) {
        int c1 = r >> 5, c2 = r & 31;
        float ss = 0.f;
        for (int c = 0; c < 32; c++) ss += cm[c1 * 32 + c] * cm[c2 * 32 + c];
        corr[r] = ss;
    }
    __syncthreads();
    for (int r = t; r < CC * 128; r += TE) {
        int c2 = r >> 7, ch = r & 127;
        float ss = 0.f;
        for (int c1 = 0; c1 < 32; c1++) ss += cfs[c1 * 128 + ch] * corr[c1 * 32 + c2];
        g_cf2[(it * BB + b) * CC * 128 + r] = ss;
    }
}

// ---------------- kernel C ----------------
__global__ __launch_bounds__(THREADS, 1) void kC(const int* __restrict__ clus,
                                                 const float* b3, const float* b1,
                                                 const float* b2, const float* bc1,
                                                 const float* bc2, const float* bc3) {
    extern __shared__ char sm[];
    __nv_bfloat16* Ahi = (__nv_bfloat16*)(sm + AHI_OFF);
    __nv_bfloat16* Alo = (__nv_bfloat16*)(sm + ALO_OFF);
    __nv_bfloat16* Bhi = (__nv_bfloat16*)(sm + BHI_OFF);
    __nv_bfloat16* Blo = (__nv_bfloat16*)(sm + BLO_OFF);
    int* cfl = (int*)(sm + CFL_OFF);
    int* ccl = (int*)(sm + CCL_OFF);
    int* cl0 = (int*)(sm + CL_OFF);
    int* cl1 = cl0 + 128;
    int t = threadIdx.x, w = t >> 5, lane = t & 31;
    int b = blockIdx.x >> 8, nblk = blockIdx.x & 255;
    int n0 = nblk * P, q0 = nblk * (P / 2);

    for (int r = t; r < CC * 128; r += THREADS) cfl[r] = 0;
    for (int r = t; r < CC * 32; r += THREADS)  ccl[r] = 0;
    if (t < P) {
        cl0[t] = clus[(size_t)b * NN + n0 + t];
        cl1[t] = clus[(size_t)(BB + b) * NN + n0 + t];
    }
    for (int r = t; r < 128 * 64; r += THREADS) {           // load f2 -> B
        int c = r >> 6, q = r & 63;
        size_t gi = ((size_t)(b * 128 + c)) * (NN / 2) + q0 + q;
        *(unsigned*)((char*)Bhi + soff(c, q)) = g_f2h[gi];
        *(unsigned*)((char*)Blo + soff(c, q)) = g_f2l[gi];
    }
    __syncthreads();
    layerMMA<128, 128, 2, 4, true>(fr_w3[0], b3, Bhi, Blo, Ahi, Alo, w, lane);  // A rows 0..127
    __syncthreads();
    for (int r = t; r < 128 * 64; r += THREADS) {           // pool gather -> A rows 128..255
        int c = r >> 6, q = r & 63;
        float v0 = g_cf2[((size_t)b * CC + cl0[2 * q]) * 128 + c];
        float v1 = g_cf2[((size_t)b * CC + cl0[2 * q + 1]) * 128 + c];
        unsigned hw, lw; split2(v0, v1, hw, lw);
        *(unsigned*)((char*)Ahi + soff(128 + c, q)) = hw;
        *(unsigned*)((char*)Alo + soff(128 + c, q)) = lw;
    }
    __syncthreads();
    layerMMA<256, 64, 2, 2, true>(fr_w1[1], b1, Ahi, Alo, Bhi, Blo, w, lane);
    __syncthreads();
    layerMMA<64, 128, 2, 4, true>(fr_w2[1], b2, Bhi, Blo, Ahi, Alo, w, lane);
    __syncthreads();
    for (int r = t; r < 128 * 64; r += THREADS) {           // f2' store + segmax cf
        int c = r >> 6, q = r & 63;
        unsigned h2 = *(unsigned*)((char*)Ahi + soff(c, q));
        unsigned l2 = *(unsigned*)((char*)Alo + soff(c, q));
        size_t gi = ((size_t)(b * 128 + c)) * (NN / 2) + q0 + q;
        g_f2h[gi] = h2; g_f2l[gi] = l2;
        atomicMax(&cfl[cl1[2 * q] * 128 + c], __float_as_int(bflo(h2) + bflo(l2)));
        atomicMax(&cfl[cl1[2 * q + 1] * 128 + c], __float_as_int(bfhi(h2) + bfhi(l2)));
    }
    layerMMA<128, 128, 2, 4, true>(fr_c1[1], bc1, Ahi, Alo, Bhi, Blo, w, lane);
    __syncthreads();
    layerMMA<128, 256, 4, 4, true>(fr_c2[1], bc2, Bhi, Blo, Ahi, Alo, w, lane);
    __syncthreads();
    layerMMA<256, 32, 2, 1, true>(fr_c3[1], bc3, Ahi, Alo, Bhi, Blo, w, lane);
    __syncthreads();
    for (int r = t; r < 32 * 64; r += THREADS) {
        int c = r >> 6, q = r & 63;
        unsigned h2 = *(unsigned*)((char*)Bhi + soff(c, q));
        unsigned l2 = *(unsigned*)((char*)Blo + soff(c, q));
        atomicMax(&ccl[cl1[2 * q] * 32 + c], __float_as_int(bflo(h2) + bflo(l2)));
        atomicMax(&ccl[cl1[2 * q + 1] * 32 + c], __float_as_int(bfhi(h2) + bfhi(l2)));
    }
    __syncthreads();
    for (int r = t; r < CC * 128; r += THREADS) { int v = cfl[r]; if (v) atomicMax(&g_cf[(BB + b) * CC * 128 + r], v); }
    for (int r = t; r < CC * 32; r += THREADS)  { int v = ccl[r]; if (v) atomicMax(&g_cc[(BB + b) * CC * 32 + r], v); }
}

// ---------------- kernel D ----------------
__global__ __launch_bounds__(THREADS, 1) void kD(const int* __restrict__ clus,
                                                 const float* b3, const float* bo1,
                                                 const float* bo2) {
    extern __shared__ char sm[];
    __nv_bfloat16* Ahi = (__nv_bfloat16*)(sm + AHI_OFF);
    __nv_bfloat16* Alo = (__nv_bfloat16*)(sm + ALO_OFF);
    __nv_bfloat16* Bhi = (__nv_bfloat16*)(sm + BHI_OFF);
    __nv_bfloat16* Blo = (__nv_bfloat16*)(sm + BLO_OFF);
    int* cl1 = (int*)(sm + CL_OFF);
    int t = threadIdx.x, w = t >> 5, lane = t & 31;
    int b = blockIdx.x >> 8, nblk = blockIdx.x & 255;
    int n0 = nblk * P, q0 = nblk * (P / 2);

    if (t < P) cl1[t] = clus[(size_t)(BB + b) * NN + n0 + t];
    for (int r = t; r < 128 * 64; r += THREADS) {           // load f2' -> B
        int c = r >> 6, q = r & 63;
        size_t gi = ((size_t)(b * 128 + c)) * (NN / 2) + q0 + q;
        *(unsigned*)((char*)Bhi + soff(c, q)) = g_f2h[gi];
        *(unsigned*)((char*)Blo + soff(c, q)) = g_f2l[gi];
    }
    __syncthreads();
    layerMMA<128, 128, 2, 4, true>(fr_w3[1], b3, Bhi, Blo, Ahi, Alo, w, lane);
    __syncthreads();
    for (int r = t; r < 128 * 64; r += THREADS) {           // pool gather -> A rows 128..255
        int c = r >> 6, q = r & 63;
        float v0 = g_cf2[((size_t)(BB + b) * CC + cl1[2 * q]) * 128 + c];
        float v1 = g_cf2[((size_t)(BB + b) * CC + cl1[2 * q + 1]) * 128 + c];
        unsigned hw, lw; split2(v0, v1, hw, lw);
        *(unsigned*)((char*)Ahi + soff(128 + c, q)) = hw;
        *(unsigned*)((char*)Alo + soff(128 + c, q)) = lw;
    }
    __syncthreads();
    layerMMA<256, 128, 2, 4, true>(fr_o1, bo1, Ahi, Alo, Bhi, Blo, w, lane);
    __syncthreads();
    layerMMA<128, 128, 2, 4, true>(fr_o2, bo2, Bhi, Blo, Ahi, Alo, w, lane);
    __syncthreads();
    if (t < 128) {
        float m = 0.0f;
        for (int q = 0; q < 64; q++) {
            unsigned h2 = *(unsigned*)((char*)Ahi + soff(t, q));
            unsigned l2 = *(unsigned*)((char*)Alo + soff(t, q));
            m = fmaxf(m, fmaxf(bflo(h2) + bflo(l2), bfhi(h2) + bfhi(l2)));
        }
        atomicMax(&g_net[b * 128 + t], __float_as_int(m));
    }
}

// ---------------- kernel E: dense head ----------------
__global__ void kE(const float* __restrict__ dw1, const float* __restrict__ db1,
                   const float* __restrict__ dw2, const float* __restrict__ db2,
                   const float* __restrict__ dw3, const float* __restrict__ db3,
                   float* __restrict__ out) {
    __shared__ float net[BB * 128], l1[BB * 256], l2[BB * 256];
    int t = threadIdx.x;
    for (int r = t; r < BB * 128; r += TE) net[r] = __int_as_float(g_net[r]);
    __syncthreads();
    for (int r = t; r < BB * 256; r += TE) {
        int b = r >> 8, o = r & 255;
        float ss = db1[o];
        for (int i = 0; i < 128; i++) ss = fmaf(net[b * 128 + i], dw1[i * 256 + o], ss);
        l1[r] = ss >= 0.f ? ss : 0.2f * ss;
    }
    __syncthreads();
    for (int r = t; r < BB * 256; r += TE) {
        int b = r >> 8, o = r & 255;
        float ss = db2[o];
        for (int i = 0; i < 256; i++) ss = fmaf(l1[b * 256 + i], dw2[i * 256 + o], ss);
        l2[r] = ss >= 0.f ? ss : 0.2f * ss;
    }
    __syncthreads();
    for (int r = t; r < BB * 40; r += TE) {
        int b = r / 40, o = r % 40;
        float ss = db3[o];
        for (int i = 0; i < 256; i++) ss = fmaf(l2[b * 256 + i], dw3[i * 40 + o], ss);
        out[r] = ss;
    }
}

// ---------------- host launcher ----------------
extern "C" void kernel_launch(void* const* d_in, const int* in_sizes, int n_in,
                              void* d_out, int out_size) {
    const float* feat = (const float*)d_in[0];
    const int*   clus = (const int*)d_in[1];
    const float* w_in = (const float*)d_in[2];
    const float* b_in = (const float*)d_in[3];
    const float* w1   = (const float*)d_in[4];
    const float* b1   = (const float*)d_in[5];
    const float* w2   = (const float*)d_in[6];
    const float* b2   = (const float*)d_in[7];
    const float* w3   = (const float*)d_in[8];
    const float* b3   = (const float*)d_in[9];
    const float* wc1  = (const float*)d_in[10];
    const float* bc1  = (const float*)d_in[11];
    const float* wc2  = (const float*)d_in[12];
    const float* bc2  = (const float*)d_in[13];
    const float* wc3  = (const float*)d_in[14];
    const float* bc3  = (const float*)d_in[15];
    const float* wo1  = (const float*)d_in[16];
    const float* bo1  = (const float*)d_in[17];
    const float* wo2  = (const float*)d_in[18];
    const float* bo2  = (const float*)d_in[19];
    const float* dw1  = (const float*)d_in[20];
    const float* db1  = (const float*)d_in[21];
    const float* dw2  = (const float*)d_in[22];
    const float* db2  = (const float*)d_in[23];
    const float* dw3  = (const float*)d_in[24];
    const float* db3  = (const float*)d_in[25];

    cudaFuncSetAttribute(kA, cudaFuncAttributeMaxDynamicSharedMemorySize, SMEM_BYTES);
    cudaFuncSetAttribute(kC, cudaFuncAttributeMaxDynamicSharedMemorySize, SMEM_BYTES);
    cudaFuncSetAttribute(kD, cudaFuncAttributeMaxDynamicSharedMemorySize, SMEM_BYTES);

    unsigned *p_in, *p_w1, *p_w2, *p_w3, *p_c1, *p_c2, *p_c3, *p_o1, *p_o2;
    cudaGetSymbolAddress((void**)&p_in, fr_in);
    cudaGetSymbolAddress((void**)&p_w1, fr_w1);
    cudaGetSymbolAddress((void**)&p_w2, fr_w2);
    cudaGetSymbolAddress((void**)&p_w3, fr_w3);
    cudaGetSymbolAddress((void**)&p_c1, fr_c1);
    cudaGetSymbolAddress((void**)&p_c2, fr_c2);
    cudaGetSymbolAddress((void**)&p_c3, fr_c3);
    cudaGetSymbolAddress((void**)&p_o1, fr_o1);
    cudaGetSymbolAddress((void**)&p_o2, fr_o2);

    FJobs jobs;
    int idx = 0, total = 0;
    auto add = [&](const float* s, unsigned* d, int Ireal, int Ipad, int O) {
        jobs.src[idx] = s; jobs.dst[idx] = d;
        jobs.Ireal[idx] = Ireal; jobs.Ipad[idx] = Ipad; jobs.O[idx] = O;
        jobs.n[idx] = O * Ipad;
        total += O * Ipad; idx++;
    };
    add(w_in, p_in, KIN, 32, 256);
    for (int it = 0; it < 2; it++) {
        add(w1  + it * 64 * 256,  p_w1 + it * 64 * 256,  256, 256, 64);
        add(w2  + it * 128 * 64,  p_w2 + it * 128 * 64,  64, 64, 128);
        add(w3  + it * 128 * 128, p_w3 + it * 128 * 128, 128, 128, 128);
        add(wc1 + it * 128 * 128, p_c1 + it * 128 * 128, 128, 128, 128);
        add(wc2 + it * 256 * 128, p_c2 + it * 256 * 128, 128, 128, 256);
        add(wc3 + it * 32 * 256,  p_c3 + it * 32 * 256,  256, 256, 32);
    }
    add(wo1, p_o1, 256, 256, 128);
    add(wo2, p_o2, 128, 128, 128);

    // launch order chosen so ncu (-s 5 -c 1) captures kC (6th launch)
    frag_all<<<(total + 255) / 256, 256>>>(jobs, total);  // 1
    zero1_k<<<256, 256>>>();                              // 2
    zero2_k<<<4, 256>>>();                                // 3

    int grid = BB * (NN / P);   // 2048
    kA<<<grid, THREADS, SMEM_BYTES>>>(feat, clus, b_in, b1, b2, bc1, bc2, bc3);   // 4
    kB<<<BB, TE>>>(0);                                                            // 5
    kC<<<grid, THREADS, SMEM_BYTES>>>(clus, b3, b1 + 64, b2 + 128, bc1 + 128, bc2 + 256, bc3 + 32); // 6 <- ncu
    kB<<<BB, TE>>>(1);
    kD<<<grid, THREADS, SMEM_BYTES>>>(clus, b3 + 128, bo1, bo2);
    kE<<<1, TE>>>(dw1, db1, dw2, db2, dw3, db3, (float*)d_out);
}